// round 2
// baseline (speedup 1.0000x reference)
#include <cuda_runtime.h>
#include <math.h>

#define EPSBN 1e-5f

// Problem dims (fixed)
#define B_    64
#define CIN   1024
#define P_    512
#define COUT  2048
#define NSP   256      // W*H = 16*16
#define HEADS 4
#define DH    128      // P_/HEADS

// ---------------- scratch (static __device__, no allocs) ----------------
__device__ __align__(16) float d_w1s [P_  * CIN ];
__device__ __align__(16) float d_w3s [COUT* P_  ];
__device__ __align__(16) float d_wscs[COUT* CIN ];
__device__ __align__(16) float d_t1    [P_ ];
__device__ __align__(16) float d_vscale[P_ ];
__device__ __align__(16) float d_vshift[P_ ];
__device__ __align__(16) float d_tfin  [COUT];
__device__ __align__(16) float d_pos [HEADS * DH * NSP];
__device__ __align__(16) float d_out1[B_ * P_ * NSP];
__device__ __align__(16) float d_qb  [B_ * P_ * NSP];
__device__ __align__(16) float d_kb  [B_ * P_ * NSP];
__device__ __align__(16) float d_vb  [B_ * P_ * NSP];
__device__ __align__(16) float d_attn[B_ * HEADS * NSP * NSP];
__device__ __align__(16) float d_attout[B_ * P_ * NSP];

// ---------------- generic tiled GEMM (fp32) ----------------
#define BK 16
#define BM 128
#define BN 128
#define LDSP 132   // padded smem row stride

// KMAJ=true : G is [K][dim] (k slow), load float4 along dim, store direct
// KMAJ=false: G is [dim][K] (k fast), load float4 along k, transpose on store
template<bool KMAJ>
__device__ __forceinline__ void load_tile(float* __restrict__ S,
                                          const float* __restrict__ G,
                                          int ldg, int base, int k0, int tid) {
    if (KMAJ) {
#pragma unroll
        for (int it = 0; it < 2; ++it) {
            int idx = tid + it * 256;       // 0..511 for 16x128 tile
            int r = idx >> 5;               // k row 0..15
            int c = (idx & 31) << 2;        // dim col 0..124
            float4 v = *reinterpret_cast<const float4*>(G + (long)(k0 + r) * ldg + base + c);
            *reinterpret_cast<float4*>(S + r * LDSP + c) = v;
        }
    } else {
#pragma unroll
        for (int it = 0; it < 2; ++it) {
            int idx = tid + it * 256;
            int r = idx >> 2;               // dim row 0..127
            int c = (idx & 3) << 2;         // k col 0..12
            float4 v = *reinterpret_cast<const float4*>(G + (long)(base + r) * ldg + k0 + c);
            S[(c + 0) * LDSP + r] = v.x;
            S[(c + 1) * LDSP + r] = v.y;
            S[(c + 2) * LDSP + r] = v.z;
            S[(c + 3) * LDSP + r] = v.w;
        }
    }
}

__device__ __forceinline__ void mma_step(const float* __restrict__ As,
                                         const float* __restrict__ Bs,
                                         float (&acc)[8][8], int tr, int tc) {
#pragma unroll
    for (int kk = 0; kk < BK; ++kk) {
        float a[8], b[8];
        *reinterpret_cast<float4*>(a)     = *reinterpret_cast<const float4*>(As + kk * LDSP + tr * 8);
        *reinterpret_cast<float4*>(a + 4) = *reinterpret_cast<const float4*>(As + kk * LDSP + tr * 8 + 4);
        *reinterpret_cast<float4*>(b)     = *reinterpret_cast<const float4*>(Bs + kk * LDSP + tc * 8);
        *reinterpret_cast<float4*>(b + 4) = *reinterpret_cast<const float4*>(Bs + kk * LDSP + tc * 8 + 4);
#pragma unroll
        for (int i = 0; i < 8; ++i)
#pragma unroll
            for (int j = 0; j < 8; ++j)
                acc[i][j] = fmaf(a[i], b[j], acc[i][j]);
    }
}

// C[z][m][n] = act( (phase1 + phase2 dot products) * scale[m] + shift[m] )
// C row stride is always 256 (=NSP or attn row).
template<bool AKM1, bool BKM1, bool AKM2, bool BKM2, bool RELU, bool HAS2>
__global__ void __launch_bounds__(256, 2)
gemm_kernel(const float* __restrict__ A1, int lda1, long sA1,
            const float* __restrict__ B1, int ldb1, long sB1, int K1,
            const float* __restrict__ A2, int lda2, long sA2, int aMod2,
            const float* __restrict__ B2, int ldb2, long sB2, int K2,
            float* __restrict__ C, long sC,
            const float* __restrict__ scale, const float* __restrict__ shift) {
    __shared__ __align__(16) float As[BK * LDSP];
    __shared__ __align__(16) float Bs[BK * LDSP];
    const int z  = blockIdx.z;
    const int m0 = blockIdx.y * BM;
    const int n0 = blockIdx.x * BN;
    const int tid = threadIdx.x;
    const int tr = tid >> 4;
    const int tc = tid & 15;

    float acc[8][8];
#pragma unroll
    for (int i = 0; i < 8; ++i)
#pragma unroll
        for (int j = 0; j < 8; ++j) acc[i][j] = 0.0f;

    {
        const float* Az = A1 + (long)z * sA1;
        const float* Bz = B1 + (long)z * sB1;
        for (int k0 = 0; k0 < K1; k0 += BK) {
            __syncthreads();
            load_tile<AKM1>(As, Az, lda1, m0, k0, tid);
            load_tile<BKM1>(Bs, Bz, ldb1, n0, k0, tid);
            __syncthreads();
            mma_step(As, Bs, acc, tr, tc);
        }
    }
    if (HAS2) {
        const float* Az = A2 + (long)(aMod2 ? (z % aMod2) : z) * sA2;
        const float* Bz = B2 + (long)z * sB2;
        for (int k0 = 0; k0 < K2; k0 += BK) {
            __syncthreads();
            load_tile<AKM2>(As, Az, lda2, m0, k0, tid);
            load_tile<BKM2>(Bs, Bz, ldb2, n0, k0, tid);
            __syncthreads();
            mma_step(As, Bs, acc, tr, tc);
        }
    }

#pragma unroll
    for (int i = 0; i < 8; ++i) {
        int row = m0 + tr * 8 + i;
        float s = scale ? __ldg(scale + row) : 1.0f;
        float t = shift ? __ldg(shift + row) : 0.0f;
        float outv[8];
#pragma unroll
        for (int j = 0; j < 8; ++j) {
            float vv = fmaf(acc[i][j], s, t);
            if (RELU) vv = fmaxf(vv, 0.0f);
            outv[j] = vv;
        }
        float* cp = C + (long)z * sC + (long)row * 256 + n0 + tc * 8;
        *reinterpret_cast<float4*>(cp)     = *reinterpret_cast<float4*>(outv);
        *reinterpret_cast<float4*>(cp + 4) = *reinterpret_cast<float4*>(outv + 4);
    }
}

// ---------------- small kernels ----------------
__global__ void scale_w_kernel(const float* __restrict__ w, const float* __restrict__ g,
                               const float* __restrict__ var, float* __restrict__ out,
                               int total, int C) {
    int idx = blockIdx.x * blockDim.x + threadIdx.x;
    if (idx >= total) return;
    int o = idx / C;
    out[idx] = w[idx] * (g[o] / sqrtf(var[o] + EPSBN));
}

__global__ void prep_vec_kernel(const float* bn1_g, const float* bn1_b, const float* bn1_m, const float* bn1_v,
                                const float* bn2_g, const float* bn2_b, const float* bn2_m, const float* bn2_v,
                                const float* v_b,
                                const float* bn3_g, const float* bn3_b, const float* bn3_m, const float* bn3_v,
                                const float* sc_b,
                                const float* scbn_g, const float* scbn_b, const float* scbn_m, const float* scbn_v) {
    int i = blockIdx.x * blockDim.x + threadIdx.x;
    if (i < P_) {
        float s1 = bn1_g[i] / sqrtf(bn1_v[i] + EPSBN);
        d_t1[i] = bn1_b[i] - bn1_m[i] * s1;
        float s2 = bn2_g[i] / sqrtf(bn2_v[i] + EPSBN);
        float t2 = bn2_b[i] - bn2_m[i] * s2;
        d_vscale[i] = s2;
        d_vshift[i] = fmaf(v_b[i], s2, t2);   // BN2 folded into V (softmax rows sum to 1)
    }
    if (i < COUT) {
        float s3 = bn3_g[i] / sqrtf(bn3_v[i] + EPSBN);
        float t3 = bn3_b[i] - bn3_m[i] * s3;
        float ss = scbn_g[i] / sqrtf(scbn_v[i] + EPSBN);
        float tsc = fmaf(sc_b[i] - scbn_m[i], ss, scbn_b[i]);
        d_tfin[i] = t3 + tsc;
    }
}

__global__ void pos_kernel(const float* __restrict__ rel_h, const float* __restrict__ rel_w) {
    int idx = blockIdx.x * blockDim.x + threadIdx.x;
    if (idx >= HEADS * DH * NSP) return;
    int n  = idx & 255;        // n = w*16 + h'
    int hd = idx >> 8;         // h*DH + d
    int w  = n >> 4;
    int hh = n & 15;
    d_pos[idx] = rel_h[hd * 16 + hh] + rel_w[hd * 16 + w];
}

// 256-wide row softmax, one warp per row
__global__ void softmax256_kernel(float* __restrict__ a) {
    int warp = (blockIdx.x * blockDim.x + threadIdx.x) >> 5;
    int lane = threadIdx.x & 31;
    float* row = a + (long)warp * 256;
    float v[8];
    float mx = -INFINITY;
#pragma unroll
    for (int j = 0; j < 8; ++j) { v[j] = row[lane + j * 32]; mx = fmaxf(mx, v[j]); }
#pragma unroll
    for (int o = 16; o; o >>= 1) mx = fmaxf(mx, __shfl_xor_sync(0xffffffffu, mx, o));
    float s = 0.0f;
#pragma unroll
    for (int j = 0; j < 8; ++j) { v[j] = __expf(v[j] - mx); s += v[j]; }
#pragma unroll
    for (int o = 16; o; o >>= 1) s += __shfl_xor_sync(0xffffffffu, s, o);
    float inv = 1.0f / s;
#pragma unroll
    for (int j = 0; j < 8; ++j) row[lane + j * 32] = v[j] * inv;
}

// ---------------- launch ----------------
extern "C" void kernel_launch(void* const* d_in, const int* in_sizes, int n_in,
                              void* d_out, int out_size) {
    const float* x       = (const float*)d_in[0];
    const float* conv1_w = (const float*)d_in[1];
    const float* bn1_g = (const float*)d_in[2];
    const float* bn1_b = (const float*)d_in[3];
    const float* bn1_m = (const float*)d_in[4];
    const float* bn1_v = (const float*)d_in[5];
    const float* q_w = (const float*)d_in[6];
    const float* q_b = (const float*)d_in[7];
    const float* k_w = (const float*)d_in[8];
    const float* k_b = (const float*)d_in[9];
    const float* v_w = (const float*)d_in[10];
    const float* v_b = (const float*)d_in[11];
    const float* rel_h = (const float*)d_in[12];
    const float* rel_w = (const float*)d_in[13];
    const float* bn2_g = (const float*)d_in[14];
    const float* bn2_b = (const float*)d_in[15];
    const float* bn2_m = (const float*)d_in[16];
    const float* bn2_v = (const float*)d_in[17];
    const float* conv3_w = (const float*)d_in[18];
    const float* bn3_g = (const float*)d_in[19];
    const float* bn3_b = (const float*)d_in[20];
    const float* bn3_m = (const float*)d_in[21];
    const float* bn3_v = (const float*)d_in[22];
    const float* sc_w  = (const float*)d_in[23];
    const float* sc_b  = (const float*)d_in[24];
    const float* scbn_g = (const float*)d_in[25];
    const float* scbn_b = (const float*)d_in[26];
    const float* scbn_m = (const float*)d_in[27];
    const float* scbn_v = (const float*)d_in[28];
    float* out = (float*)d_out;

    float *w1s, *w3s, *wscs, *t1, *vscale, *vshift, *tfin, *pos;
    float *out1, *qb, *kb, *vb, *attn, *attout;
    cudaGetSymbolAddress((void**)&w1s,   d_w1s);
    cudaGetSymbolAddress((void**)&w3s,   d_w3s);
    cudaGetSymbolAddress((void**)&wscs,  d_wscs);
    cudaGetSymbolAddress((void**)&t1,    d_t1);
    cudaGetSymbolAddress((void**)&vscale,d_vscale);
    cudaGetSymbolAddress((void**)&vshift,d_vshift);
    cudaGetSymbolAddress((void**)&tfin,  d_tfin);
    cudaGetSymbolAddress((void**)&pos,   d_pos);
    cudaGetSymbolAddress((void**)&out1,  d_out1);
    cudaGetSymbolAddress((void**)&qb,    d_qb);
    cudaGetSymbolAddress((void**)&kb,    d_kb);
    cudaGetSymbolAddress((void**)&vb,    d_vb);
    cudaGetSymbolAddress((void**)&attn,  d_attn);
    cudaGetSymbolAddress((void**)&attout,d_attout);

    // ---- prep: fold BN into weights / vectors ----
    scale_w_kernel<<<(P_ * CIN + 255) / 256, 256>>>(conv1_w, bn1_g, bn1_v, w1s, P_ * CIN, CIN);
    scale_w_kernel<<<(COUT * P_ + 255) / 256, 256>>>(conv3_w, bn3_g, bn3_v, w3s, COUT * P_, P_);
    scale_w_kernel<<<(COUT * CIN + 255) / 256, 256>>>(sc_w, scbn_g, scbn_v, wscs, COUT * CIN, CIN);
    prep_vec_kernel<<<(COUT + 255) / 256, 256>>>(bn1_g, bn1_b, bn1_m, bn1_v,
                                                 bn2_g, bn2_b, bn2_m, bn2_v, v_b,
                                                 bn3_g, bn3_b, bn3_m, bn3_v, sc_b,
                                                 scbn_g, scbn_b, scbn_m, scbn_v);
    pos_kernel<<<(HEADS * DH * NSP + 255) / 256, 256>>>(rel_h, rel_w);

    // ---- conv1 + BN1 + ReLU : out1[b][p][n] ----
    gemm_kernel<false, true, false, true, true, false><<<dim3(2, 4, B_), 256>>>(
        w1s, CIN, 0, x, NSP, (long)CIN * NSP, CIN,
        nullptr, 0, 0, 0, nullptr, 0, 0, 0,
        out1, (long)P_ * NSP, nullptr, t1);

    // ---- q, k, v (v has BN2 folded in) ----
    gemm_kernel<false, true, false, true, false, false><<<dim3(2, 4, B_), 256>>>(
        q_w, P_, 0, out1, NSP, (long)P_ * NSP, P_,
        nullptr, 0, 0, 0, nullptr, 0, 0, 0,
        qb, (long)P_ * NSP, nullptr, q_b);
    gemm_kernel<false, true, false, true, false, false><<<dim3(2, 4, B_), 256>>>(
        k_w, P_, 0, out1, NSP, (long)P_ * NSP, P_,
        nullptr, 0, 0, 0, nullptr, 0, 0, 0,
        kb, (long)P_ * NSP, nullptr, k_b);
    gemm_kernel<false, true, false, true, false, false><<<dim3(2, 4, B_), 256>>>(
        v_w, P_, 0, out1, NSP, (long)P_ * NSP, P_,
        nullptr, 0, 0, 0, nullptr, 0, 0, 0,
        vb, (long)P_ * NSP, vscale, vshift);

    // ---- logits L[n][m] = Q^T K + pos^T Q per (b,h) ----
    gemm_kernel<true, true, true, true, false, true><<<dim3(2, 2, B_ * HEADS), 256>>>(
        qb, NSP, (long)DH * NSP, kb, NSP, (long)DH * NSP, DH,
        pos, NSP, (long)DH * NSP, HEADS,
        qb, NSP, (long)DH * NSP, DH,
        attn, (long)NSP * NSP, nullptr, nullptr);

    // ---- softmax over m (rows of 256) ----
    softmax256_kernel<<<(B_ * HEADS * NSP) / 8, 256>>>(attn);

    // ---- out[d][n] = V' · A^T, epilogue = ReLU (BN2 already in V') ----
    gemm_kernel<false, false, false, false, true, false><<<dim3(2, 1, B_ * HEADS), 256>>>(
        vb, NSP, (long)DH * NSP, attn, NSP, (long)NSP * NSP, NSP,
        nullptr, 0, 0, 0, nullptr, 0, 0, 0,
        attout, (long)DH * NSP, nullptr, nullptr);

    // ---- conv3+BN3 + shortcut+scBN + add + ReLU, fused two-phase GEMM ----
    gemm_kernel<false, true, false, true, true, true><<<dim3(2, 16, B_), 256>>>(
        w3s, P_, 0, attout, NSP, (long)P_ * NSP, P_,
        wscs, CIN, 0, 0, x, NSP, (long)CIN * NSP, CIN,
        out, (long)COUT * NSP, nullptr, tfin);
}

// round 3
// speedup vs baseline: 1.0008x; 1.0008x over previous
#include <cuda_runtime.h>
#include <math.h>

#define EPSBN 1e-5f

// Problem dims (fixed)
#define B_    64
#define CIN   1024
#define P_    512
#define COUT  2048
#define NSP   256      // W*H = 16*16
#define HEADS 4
#define DH    128      // P_/HEADS

// ---------------- scratch (static __device__, no allocs) ----------------
__device__ __align__(16) float d_w1s [P_  * CIN ];
__device__ __align__(16) float d_w3s [COUT* P_  ];
__device__ __align__(16) float d_wscs[COUT* CIN ];
__device__ __align__(16) float d_t1    [P_ ];
__device__ __align__(16) float d_vscale[P_ ];
__device__ __align__(16) float d_vshift[P_ ];
__device__ __align__(16) float d_tfin  [COUT];
__device__ __align__(16) float d_pos [HEADS * DH * NSP];
__device__ __align__(16) float d_out1[B_ * P_ * NSP];
__device__ __align__(16) float d_qb  [B_ * P_ * NSP];
__device__ __align__(16) float d_kb  [B_ * P_ * NSP];
__device__ __align__(16) float d_vb  [B_ * P_ * NSP];
__device__ __align__(16) float d_attn[B_ * HEADS * NSP * NSP];
__device__ __align__(16) float d_attout[B_ * P_ * NSP];

// ---------------- generic tiled GEMM (fp32) ----------------
#define BK 16
#define BM 128
#define BN 128
#define LDSP 132   // padded smem row stride

// KMAJ=true : G is [K][dim] (k slow), load float4 along dim, store direct
// KMAJ=false: G is [dim][K] (k fast), load float4 along k, transpose on store
template<bool KMAJ>
__device__ __forceinline__ void load_tile(float* __restrict__ S,
                                          const float* __restrict__ G,
                                          int ldg, int base, int k0, int tid) {
    if (KMAJ) {
#pragma unroll
        for (int it = 0; it < 2; ++it) {
            int idx = tid + it * 256;       // 0..511 for 16x128 tile
            int r = idx >> 5;               // k row 0..15
            int c = (idx & 31) << 2;        // dim col 0..124
            float4 v = *reinterpret_cast<const float4*>(G + (long)(k0 + r) * ldg + base + c);
            *reinterpret_cast<float4*>(S + r * LDSP + c) = v;
        }
    } else {
#pragma unroll
        for (int it = 0; it < 2; ++it) {
            int idx = tid + it * 256;
            int r = idx >> 2;               // dim row 0..127
            int c = (idx & 3) << 2;         // k col 0..12
            float4 v = *reinterpret_cast<const float4*>(G + (long)(base + r) * ldg + k0 + c);
            S[(c + 0) * LDSP + r] = v.x;
            S[(c + 1) * LDSP + r] = v.y;
            S[(c + 2) * LDSP + r] = v.z;
            S[(c + 3) * LDSP + r] = v.w;
        }
    }
}

__device__ __forceinline__ void mma_step(const float* __restrict__ As,
                                         const float* __restrict__ Bs,
                                         float (&acc)[8][8], int tr, int tc) {
#pragma unroll
    for (int kk = 0; kk < BK; ++kk) {
        float a[8], b[8];
        *reinterpret_cast<float4*>(a)     = *reinterpret_cast<const float4*>(As + kk * LDSP + tr * 8);
        *reinterpret_cast<float4*>(a + 4) = *reinterpret_cast<const float4*>(As + kk * LDSP + tr * 8 + 4);
        *reinterpret_cast<float4*>(b)     = *reinterpret_cast<const float4*>(Bs + kk * LDSP + tc * 8);
        *reinterpret_cast<float4*>(b + 4) = *reinterpret_cast<const float4*>(Bs + kk * LDSP + tc * 8 + 4);
#pragma unroll
        for (int i = 0; i < 8; ++i)
#pragma unroll
            for (int j = 0; j < 8; ++j)
                acc[i][j] = fmaf(a[i], b[j], acc[i][j]);
    }
}

// C[z][m][n] = act( (phase1 + phase2 dot products) * scale[m] + shift[m] )
// C row stride is always 256 (=NSP or attn row).
template<bool AKM1, bool BKM1, bool AKM2, bool BKM2, bool RELU, bool HAS2>
__global__ void __launch_bounds__(256, 2)
gemm_kernel(const float* __restrict__ A1, int lda1, long sA1,
            const float* __restrict__ B1, int ldb1, long sB1, int K1,
            const float* __restrict__ A2, int lda2, long sA2, int aMod2,
            const float* __restrict__ B2, int ldb2, long sB2, int K2,
            float* __restrict__ C, long sC,
            const float* __restrict__ scale, const float* __restrict__ shift) {
    __shared__ __align__(16) float As[BK * LDSP];
    __shared__ __align__(16) float Bs[BK * LDSP];
    const int z  = blockIdx.z;
    const int m0 = blockIdx.y * BM;
    const int n0 = blockIdx.x * BN;
    const int tid = threadIdx.x;
    const int tr = tid >> 4;
    const int tc = tid & 15;

    float acc[8][8];
#pragma unroll
    for (int i = 0; i < 8; ++i)
#pragma unroll
        for (int j = 0; j < 8; ++j) acc[i][j] = 0.0f;

    {
        const float* Az = A1 + (long)z * sA1;
        const float* Bz = B1 + (long)z * sB1;
        for (int k0 = 0; k0 < K1; k0 += BK) {
            __syncthreads();
            load_tile<AKM1>(As, Az, lda1, m0, k0, tid);
            load_tile<BKM1>(Bs, Bz, ldb1, n0, k0, tid);
            __syncthreads();
            mma_step(As, Bs, acc, tr, tc);
        }
    }
    if (HAS2) {
        const float* Az = A2 + (long)(aMod2 ? (z % aMod2) : z) * sA2;
        const float* Bz = B2 + (long)z * sB2;
        for (int k0 = 0; k0 < K2; k0 += BK) {
            __syncthreads();
            load_tile<AKM2>(As, Az, lda2, m0, k0, tid);
            load_tile<BKM2>(Bs, Bz, ldb2, n0, k0, tid);
            __syncthreads();
            mma_step(As, Bs, acc, tr, tc);
        }
    }

#pragma unroll
    for (int i = 0; i < 8; ++i) {
        int row = m0 + tr * 8 + i;
        float s = scale ? __ldg(scale + row) : 1.0f;
        float t = shift ? __ldg(shift + row) : 0.0f;
        float outv[8];
#pragma unroll
        for (int j = 0; j < 8; ++j) {
            float vv = fmaf(acc[i][j], s, t);
            if (RELU) vv = fmaxf(vv, 0.0f);
            outv[j] = vv;
        }
        float* cp = C + (long)z * sC + (long)row * 256 + n0 + tc * 8;
        *reinterpret_cast<float4*>(cp)     = *reinterpret_cast<float4*>(outv);
        *reinterpret_cast<float4*>(cp + 4) = *reinterpret_cast<float4*>(outv + 4);
    }
}

// ---------------- small kernels ----------------
__global__ void scale_w_kernel(const float* __restrict__ w, const float* __restrict__ g,
                               const float* __restrict__ var, float* __restrict__ out,
                               int total, int C) {
    int idx = blockIdx.x * blockDim.x + threadIdx.x;
    if (idx >= total) return;
    int o = idx / C;
    out[idx] = w[idx] * (g[o] / sqrtf(var[o] + EPSBN));
}

__global__ void prep_vec_kernel(const float* bn1_g, const float* bn1_b, const float* bn1_m, const float* bn1_v,
                                const float* bn2_g, const float* bn2_b, const float* bn2_m, const float* bn2_v,
                                const float* v_b,
                                const float* bn3_g, const float* bn3_b, const float* bn3_m, const float* bn3_v,
                                const float* sc_b,
                                const float* scbn_g, const float* scbn_b, const float* scbn_m, const float* scbn_v) {
    int i = blockIdx.x * blockDim.x + threadIdx.x;
    if (i < P_) {
        float s1 = bn1_g[i] / sqrtf(bn1_v[i] + EPSBN);
        d_t1[i] = bn1_b[i] - bn1_m[i] * s1;
        float s2 = bn2_g[i] / sqrtf(bn2_v[i] + EPSBN);
        float t2 = bn2_b[i] - bn2_m[i] * s2;
        d_vscale[i] = s2;
        d_vshift[i] = fmaf(v_b[i], s2, t2);   // BN2 folded into V (softmax rows sum to 1)
    }
    if (i < COUT) {
        float s3 = bn3_g[i] / sqrtf(bn3_v[i] + EPSBN);
        float t3 = bn3_b[i] - bn3_m[i] * s3;
        float ss = scbn_g[i] / sqrtf(scbn_v[i] + EPSBN);
        float tsc = fmaf(sc_b[i] - scbn_m[i], ss, scbn_b[i]);
        d_tfin[i] = t3 + tsc;
    }
}

__global__ void pos_kernel(const float* __restrict__ rel_h, const float* __restrict__ rel_w) {
    int idx = blockIdx.x * blockDim.x + threadIdx.x;
    if (idx >= HEADS * DH * NSP) return;
    int n  = idx & 255;        // n = w*16 + h'
    int hd = idx >> 8;         // h*DH + d
    int w  = n >> 4;
    int hh = n & 15;
    d_pos[idx] = rel_h[hd * 16 + hh] + rel_w[hd * 16 + w];
}

// 256-wide row softmax, one warp per row
__global__ void softmax256_kernel(float* __restrict__ a) {
    int warp = (blockIdx.x * blockDim.x + threadIdx.x) >> 5;
    int lane = threadIdx.x & 31;
    float* row = a + (long)warp * 256;
    float v[8];
    float mx = -INFINITY;
#pragma unroll
    for (int j = 0; j < 8; ++j) { v[j] = row[lane + j * 32]; mx = fmaxf(mx, v[j]); }
#pragma unroll
    for (int o = 16; o; o >>= 1) mx = fmaxf(mx, __shfl_xor_sync(0xffffffffu, mx, o));
    float s = 0.0f;
#pragma unroll
    for (int j = 0; j < 8; ++j) { v[j] = __expf(v[j] - mx); s += v[j]; }
#pragma unroll
    for (int o = 16; o; o >>= 1) s += __shfl_xor_sync(0xffffffffu, s, o);
    float inv = 1.0f / s;
#pragma unroll
    for (int j = 0; j < 8; ++j) row[lane + j * 32] = v[j] * inv;
}

// ---------------- launch ----------------
extern "C" void kernel_launch(void* const* d_in, const int* in_sizes, int n_in,
                              void* d_out, int out_size) {
    const float* x       = (const float*)d_in[0];
    const float* conv1_w = (const float*)d_in[1];
    const float* bn1_g = (const float*)d_in[2];
    const float* bn1_b = (const float*)d_in[3];
    const float* bn1_m = (const float*)d_in[4];
    const float* bn1_v = (const float*)d_in[5];
    const float* q_w = (const float*)d_in[6];
    const float* q_b = (const float*)d_in[7];
    const float* k_w = (const float*)d_in[8];
    const float* k_b = (const float*)d_in[9];
    const float* v_w = (const float*)d_in[10];
    const float* v_b = (const float*)d_in[11];
    const float* rel_h = (const float*)d_in[12];
    const float* rel_w = (const float*)d_in[13];
    const float* bn2_g = (const float*)d_in[14];
    const float* bn2_b = (const float*)d_in[15];
    const float* bn2_m = (const float*)d_in[16];
    const float* bn2_v = (const float*)d_in[17];
    const float* conv3_w = (const float*)d_in[18];
    const float* bn3_g = (const float*)d_in[19];
    const float* bn3_b = (const float*)d_in[20];
    const float* bn3_m = (const float*)d_in[21];
    const float* bn3_v = (const float*)d_in[22];
    const float* sc_w  = (const float*)d_in[23];
    const float* sc_b  = (const float*)d_in[24];
    const float* scbn_g = (const float*)d_in[25];
    const float* scbn_b = (const float*)d_in[26];
    const float* scbn_m = (const float*)d_in[27];
    const float* scbn_v = (const float*)d_in[28];
    float* out = (float*)d_out;

    float *w1s, *w3s, *wscs, *t1, *vscale, *vshift, *tfin, *pos;
    float *out1, *qb, *kb, *vb, *attn, *attout;
    cudaGetSymbolAddress((void**)&w1s,   d_w1s);
    cudaGetSymbolAddress((void**)&w3s,   d_w3s);
    cudaGetSymbolAddress((void**)&wscs,  d_wscs);
    cudaGetSymbolAddress((void**)&t1,    d_t1);
    cudaGetSymbolAddress((void**)&vscale,d_vscale);
    cudaGetSymbolAddress((void**)&vshift,d_vshift);
    cudaGetSymbolAddress((void**)&tfin,  d_tfin);
    cudaGetSymbolAddress((void**)&pos,   d_pos);
    cudaGetSymbolAddress((void**)&out1,  d_out1);
    cudaGetSymbolAddress((void**)&qb,    d_qb);
    cudaGetSymbolAddress((void**)&kb,    d_kb);
    cudaGetSymbolAddress((void**)&vb,    d_vb);
    cudaGetSymbolAddress((void**)&attn,  d_attn);
    cudaGetSymbolAddress((void**)&attout,d_attout);

    // ---- prep: fold BN into weights / vectors ----
    scale_w_kernel<<<(P_ * CIN + 255) / 256, 256>>>(conv1_w, bn1_g, bn1_v, w1s, P_ * CIN, CIN);
    scale_w_kernel<<<(COUT * P_ + 255) / 256, 256>>>(conv3_w, bn3_g, bn3_v, w3s, COUT * P_, P_);
    scale_w_kernel<<<(COUT * CIN + 255) / 256, 256>>>(sc_w, scbn_g, scbn_v, wscs, COUT * CIN, CIN);
    prep_vec_kernel<<<(COUT + 255) / 256, 256>>>(bn1_g, bn1_b, bn1_m, bn1_v,
                                                 bn2_g, bn2_b, bn2_m, bn2_v, v_b,
                                                 bn3_g, bn3_b, bn3_m, bn3_v, sc_b,
                                                 scbn_g, scbn_b, scbn_m, scbn_v);
    pos_kernel<<<(HEADS * DH * NSP + 255) / 256, 256>>>(rel_h, rel_w);

    // ---- conv1 + BN1 + ReLU : out1[b][p][n] ----
    gemm_kernel<false, true, false, true, true, false><<<dim3(2, 4, B_), 256>>>(
        w1s, CIN, 0, x, NSP, (long)CIN * NSP, CIN,
        nullptr, 0, 0, 0, nullptr, 0, 0, 0,
        out1, (long)P_ * NSP, nullptr, t1);

    // ---- q, k, v (v has BN2 folded in) ----
    gemm_kernel<false, true, false, true, false, false><<<dim3(2, 4, B_), 256>>>(
        q_w, P_, 0, out1, NSP, (long)P_ * NSP, P_,
        nullptr, 0, 0, 0, nullptr, 0, 0, 0,
        qb, (long)P_ * NSP, nullptr, q_b);
    gemm_kernel<false, true, false, true, false, false><<<dim3(2, 4, B_), 256>>>(
        k_w, P_, 0, out1, NSP, (long)P_ * NSP, P_,
        nullptr, 0, 0, 0, nullptr, 0, 0, 0,
        kb, (long)P_ * NSP, nullptr, k_b);
    gemm_kernel<false, true, false, true, false, false><<<dim3(2, 4, B_), 256>>>(
        v_w, P_, 0, out1, NSP, (long)P_ * NSP, P_,
        nullptr, 0, 0, 0, nullptr, 0, 0, 0,
        vb, (long)P_ * NSP, vscale, vshift);

    // ---- logits L[n][m] = Q^T K + pos^T Q per (b,h) ----
    gemm_kernel<true, true, true, true, false, true><<<dim3(2, 2, B_ * HEADS), 256>>>(
        qb, NSP, (long)DH * NSP, kb, NSP, (long)DH * NSP, DH,
        pos, NSP, (long)DH * NSP, HEADS,
        qb, NSP, (long)DH * NSP, DH,
        attn, (long)NSP * NSP, nullptr, nullptr);

    // ---- softmax over m (rows of 256) ----
    softmax256_kernel<<<(B_ * HEADS * NSP) / 8, 256>>>(attn);

    // ---- out[d][n] = V' · A^T, epilogue = ReLU (BN2 already in V') ----
    gemm_kernel<false, false, false, false, true, false><<<dim3(2, 1, B_ * HEADS), 256>>>(
        vb, NSP, (long)DH * NSP, attn, NSP, (long)NSP * NSP, NSP,
        nullptr, 0, 0, 0, nullptr, 0, 0, 0,
        attout, (long)DH * NSP, nullptr, nullptr);

    // ---- conv3+BN3 + shortcut+scBN + add + ReLU, fused two-phase GEMM ----
    gemm_kernel<false, true, false, true, true, true><<<dim3(2, 16, B_), 256>>>(
        w3s, P_, 0, attout, NSP, (long)P_ * NSP, P_,
        wscs, CIN, 0, 0, x, NSP, (long)CIN * NSP, CIN,
        out, (long)COUT * NSP, nullptr, tfin);
}

// round 5
// speedup vs baseline: 1.5733x; 1.5719x over previous
#include <cuda_runtime.h>
#include <cuda_bf16.h>
#include <math.h>
#include <stdint.h>
typedef __nv_bfloat16 bf16;

#define EPSBN 1e-5f
#define B_    64
#define CIN   1024
#define P_    512
#define COUT  2048
#define NSP   256
#define HEADS 4
#define DH    128

// ---------------- scratch ----------------
__device__ __align__(16) float d_w1s [P_  * CIN ];
__device__ __align__(16) float d_w3s [COUT* P_  ];
__device__ __align__(16) float d_wscs[COUT* CIN ];
__device__ __align__(16) float d_t1    [P_ ];
__device__ __align__(16) float d_vscale[P_ ];
__device__ __align__(16) float d_vshift[P_ ];
__device__ __align__(16) float d_tfin  [COUT];
__device__ __align__(16) float d_pos [HEADS * DH * NSP];
__device__ __align__(16) float d_out1[B_ * P_ * NSP];
__device__ __align__(16) float d_qb  [B_ * P_ * NSP];
__device__ __align__(16) float d_kb  [B_ * P_ * NSP];
__device__ __align__(16) float d_vb  [B_ * P_ * NSP];
__device__ __align__(16) float d_attn[B_ * HEADS * NSP * NSP];
__device__ __align__(16) float d_attout[B_ * P_ * NSP];

// ---------------- helpers ----------------
__device__ __forceinline__ void spl(float v, bf16& h, bf16& l) {
    h = __float2bfloat16(v);
    l = __float2bfloat16(v - __bfloat162float(h));
}
__device__ __forceinline__ uint32_t pk(bf16 a, bf16 b) {
    return (uint32_t)__bfloat16_as_ushort(a) | ((uint32_t)__bfloat16_as_ushort(b) << 16);
}
__device__ __forceinline__ void mma16816(float* c, const uint32_t* a, const uint32_t* b) {
    asm volatile(
        "mma.sync.aligned.m16n8k16.row.col.f32.bf16.bf16.f32 "
        "{%0,%1,%2,%3},{%4,%5,%6,%7},{%8,%9},{%0,%1,%2,%3};"
        : "+f"(c[0]), "+f"(c[1]), "+f"(c[2]), "+f"(c[3])
        : "r"(a[0]), "r"(a[1]), "r"(a[2]), "r"(a[3]), "r"(b[0]), "r"(b[1]));
}

// ---------------- tensor-core tiled GEMM ----------------
// BM=BN=128, BK=32. smem planes: [k2=16][dim=128] packed bf16x2-along-k, stride 136.
#define LDP 136

// KMAJ=true : G is [K][dim] (k slow). KMAJ=false: G is [dim][K] (k fast).
template<bool KMAJ>
__device__ __forceinline__ void load_tile(uint32_t (*SH)[LDP], uint32_t (*SL)[LDP],
                                          const float* __restrict__ G,
                                          int ldg, int base, int k0, int tid) {
    if (!KMAJ) {
#pragma unroll
        for (int it = 0; it < 4; ++it) {
            int idx = tid + it * 256;
            int r = idx >> 3;          // dim 0..127
            int c = idx & 7;           // k4 chunk 0..7
            float4 v = *(const float4*)(G + (long)(base + r) * ldg + k0 + c * 4);
            bf16 hx,lx,hy,ly,hz,lz,hw,lw;
            spl(v.x,hx,lx); spl(v.y,hy,ly); spl(v.z,hz,lz); spl(v.w,hw,lw);
            SH[c*2][r]   = pk(hx,hy);  SH[c*2+1][r] = pk(hz,hw);
            SL[c*2][r]   = pk(lx,ly);  SL[c*2+1][r] = pk(lz,lw);
        }
    } else {
#pragma unroll
        for (int it = 0; it < 2; ++it) {
            int idx = tid + it * 256;
            int r2 = idx >> 5;         // k2 0..15
            int c  = idx & 31;         // m4 chunk 0..31
            const float* g0 = G + (long)(k0 + 2 * r2) * ldg + base + c * 4;
            float4 va = *(const float4*)g0;
            float4 vb = *(const float4*)(g0 + ldg);
            bf16 h0,l0,h1,l1,h2,l2,h3,l3, g0h,g0l,g1h,g1l,g2h,g2l,g3h,g3l;
            spl(va.x,h0,l0); spl(vb.x,g0h,g0l);
            spl(va.y,h1,l1); spl(vb.y,g1h,g1l);
            spl(va.z,h2,l2); spl(vb.z,g2h,g2l);
            spl(va.w,h3,l3); spl(vb.w,g3h,g3l);
            uint32_t* ph = &SH[r2][c*4];
            uint32_t* pl = &SL[r2][c*4];
            ph[0]=pk(h0,g0h); ph[1]=pk(h1,g1h); ph[2]=pk(h2,g2h); ph[3]=pk(h3,g3h);
            pl[0]=pk(l0,g0l); pl[1]=pk(l1,g1l); pl[2]=pk(l2,g2l); pl[3]=pk(l3,g3l);
        }
    }
}

template<bool AKM1, bool BKM1, bool AKM2, bool BKM2, bool RELU, bool HAS2>
__global__ void __launch_bounds__(256)
gemm_kernel(const float* __restrict__ A1, int lda1, long sA1,
            const float* __restrict__ B1, int ldb1, long sB1, int K1,
            const float* __restrict__ A2, int lda2, long sA2, int aMod2,
            const float* __restrict__ B2, int ldb2, long sB2, int K2,
            float* __restrict__ C, long sC,
            const float* __restrict__ scale, const float* __restrict__ shift) {
    __shared__ uint32_t AsH[16][LDP], AsL[16][LDP], BsH[16][LDP], BsL[16][LDP];
    const int z  = blockIdx.z;
    const int m0 = blockIdx.y * 128;
    const int n0 = blockIdx.x * 128;
    const int tid = threadIdx.x;
    const int lane = tid & 31, w = tid >> 5;
    const int wm = w >> 1, wn = w & 1;        // warp tile: 32x64
    const int qr = lane >> 2, qk = lane & 3;

    float acc[2][8][4];
#pragma unroll
    for (int i = 0; i < 2; ++i)
#pragma unroll
        for (int j = 0; j < 8; ++j)
#pragma unroll
            for (int q = 0; q < 4; ++q) acc[i][j][q] = 0.0f;

    auto compute = [&]() {
#pragma unroll
        for (int s = 0; s < 2; ++s) {
            const int r0 = s * 8 + qk, r1 = r0 + 4;
            uint32_t ah[2][4], al[2][4];
#pragma unroll
            for (int mi = 0; mi < 2; ++mi) {
                int mc = wm * 32 + mi * 16 + qr;
                ah[mi][0]=AsH[r0][mc]; ah[mi][1]=AsH[r0][mc+8];
                ah[mi][2]=AsH[r1][mc]; ah[mi][3]=AsH[r1][mc+8];
                al[mi][0]=AsL[r0][mc]; al[mi][1]=AsL[r0][mc+8];
                al[mi][2]=AsL[r1][mc]; al[mi][3]=AsL[r1][mc+8];
            }
#pragma unroll
            for (int ni = 0; ni < 8; ++ni) {
                int nc = wn * 64 + ni * 8 + qr;
                uint32_t bh[2], bl[2];
                bh[0]=BsH[r0][nc]; bh[1]=BsH[r1][nc];
                bl[0]=BsL[r0][nc]; bl[1]=BsL[r1][nc];
#pragma unroll
                for (int mi = 0; mi < 2; ++mi) {
                    mma16816(acc[mi][ni], ah[mi], bh);
                    mma16816(acc[mi][ni], ah[mi], bl);
                    mma16816(acc[mi][ni], al[mi], bh);
                }
            }
        }
    };

    {
        const float* Az = A1 + (long)z * sA1;
        const float* Bz = B1 + (long)z * sB1;
        for (int k0 = 0; k0 < K1; k0 += 32) {
            __syncthreads();
            load_tile<AKM1>(AsH, AsL, Az, lda1, m0, k0, tid);
            load_tile<BKM1>(BsH, BsL, Bz, ldb1, n0, k0, tid);
            __syncthreads();
            compute();
        }
    }
    if (HAS2) {
        const float* Az = A2 + (long)(aMod2 ? (z % aMod2) : z) * sA2;
        const float* Bz = B2 + (long)z * sB2;
        for (int k0 = 0; k0 < K2; k0 += 32) {
            __syncthreads();
            load_tile<AKM2>(AsH, AsL, Az, lda2, m0, k0, tid);
            load_tile<BKM2>(BsH, BsL, Bz, ldb2, n0, k0, tid);
            __syncthreads();
            compute();
        }
    }

    // epilogue
#pragma unroll
    for (int mi = 0; mi < 2; ++mi) {
#pragma unroll
        for (int half = 0; half < 2; ++half) {
            int row = m0 + wm * 32 + mi * 16 + qr + half * 8;
            float s = scale ? __ldg(scale + row) : 1.0f;
            float t = shift ? __ldg(shift + row) : 0.0f;
            float* cp = C + (long)z * sC + (long)row * 256 + n0 + wn * 64 + qk * 2;
#pragma unroll
            for (int ni = 0; ni < 8; ++ni) {
                float v0 = fmaf(acc[mi][ni][half * 2],     s, t);
                float v1 = fmaf(acc[mi][ni][half * 2 + 1], s, t);
                if (RELU) { v0 = fmaxf(v0, 0.0f); v1 = fmaxf(v1, 0.0f); }
                float2 f = {v0, v1};
                *(float2*)(cp + ni * 8) = f;
            }
        }
    }
}

// ---------------- small kernels ----------------
__global__ void scale_w_kernel(const float* __restrict__ w, const float* __restrict__ g,
                               const float* __restrict__ var, float* __restrict__ out,
                               int total, int C) {
    int idx = blockIdx.x * blockDim.x + threadIdx.x;
    if (idx >= total) return;
    int o = idx / C;
    out[idx] = w[idx] * (g[o] * rsqrtf(var[o] + EPSBN));
}

__global__ void prep_vec_kernel(const float* bn1_g, const float* bn1_b, const float* bn1_m, const float* bn1_v,
                                const float* bn2_g, const float* bn2_b, const float* bn2_m, const float* bn2_v,
                                const float* v_b,
                                const float* bn3_g, const float* bn3_b, const float* bn3_m, const float* bn3_v,
                                const float* sc_b,
                                const float* scbn_g, const float* scbn_b, const float* scbn_m, const float* scbn_v) {
    int i = blockIdx.x * blockDim.x + threadIdx.x;
    if (i < P_) {
        float s1 = bn1_g[i] * rsqrtf(bn1_v[i] + EPSBN);
        d_t1[i] = bn1_b[i] - bn1_m[i] * s1;
        float s2 = bn2_g[i] * rsqrtf(bn2_v[i] + EPSBN);
        float t2 = bn2_b[i] - bn2_m[i] * s2;
        d_vscale[i] = s2;
        d_vshift[i] = fmaf(v_b[i], s2, t2);   // BN2 folded into V (softmax rows sum to 1)
    }
    if (i < COUT) {
        float s3 = bn3_g[i] * rsqrtf(bn3_v[i] + EPSBN);
        float t3 = bn3_b[i] - bn3_m[i] * s3;
        float ss = scbn_g[i] * rsqrtf(scbn_v[i] + EPSBN);
        float tsc = fmaf(sc_b[i] - scbn_m[i], ss, scbn_b[i]);
        d_tfin[i] = t3 + tsc;
    }
}

__global__ void pos_kernel(const float* __restrict__ rel_h, const float* __restrict__ rel_w) {
    int idx = blockIdx.x * blockDim.x + threadIdx.x;
    if (idx >= HEADS * DH * NSP) return;
    int n  = idx & 255;
    int hd = idx >> 8;
    d_pos[idx] = rel_h[hd * 16 + (n & 15)] + rel_w[hd * 16 + (n >> 4)];
}

__global__ void softmax256_kernel(float* __restrict__ a) {
    int warp = (blockIdx.x * blockDim.x + threadIdx.x) >> 5;
    int lane = threadIdx.x & 31;
    float* row = a + (long)warp * 256;
    float v[8];
    float mx = -INFINITY;
#pragma unroll
    for (int j = 0; j < 8; ++j) { v[j] = row[lane + j * 32]; mx = fmaxf(mx, v[j]); }
#pragma unroll
    for (int o = 16; o; o >>= 1) mx = fmaxf(mx, __shfl_xor_sync(0xffffffffu, mx, o));
    float s = 0.0f;
#pragma unroll
    for (int j = 0; j < 8; ++j) { v[j] = __expf(v[j] - mx); s += v[j]; }
#pragma unroll
    for (int o = 16; o; o >>= 1) s += __shfl_xor_sync(0xffffffffu, s, o);
    float inv = 1.0f / s;
#pragma unroll
    for (int j = 0; j < 8; ++j) row[lane + j * 32] = v[j] * inv;
}

// ---------------- launch ----------------
extern "C" void kernel_launch(void* const* d_in, const int* in_sizes, int n_in,
                              void* d_out, int out_size) {
    const float* x       = (const float*)d_in[0];
    const float* conv1_w = (const float*)d_in[1];
    const float* bn1_g = (const float*)d_in[2];
    const float* bn1_b = (const float*)d_in[3];
    const float* bn1_m = (const float*)d_in[4];
    const float* bn1_v = (const float*)d_in[5];
    const float* q_w = (const float*)d_in[6];
    const float* q_b = (const float*)d_in[7];
    const float* k_w = (const float*)d_in[8];
    const float* k_b = (const float*)d_in[9];
    const float* v_w = (const float*)d_in[10];
    const float* v_b = (const float*)d_in[11];
    const float* rel_h = (const float*)d_in[12];
    const float* rel_w = (const float*)d_in[13];
    const float* bn2_g = (const float*)d_in[14];
    const float* bn2_b = (const float*)d_in[15];
    const float* bn2_m = (const float*)d_in[16];
    const float* bn2_v = (const float*)d_in[17];
    const float* conv3_w = (const float*)d_in[18];
    const float* bn3_g = (const float*)d_in[19];
    const float* bn3_b = (const float*)d_in[20];
    const float* bn3_m = (const float*)d_in[21];
    const float* bn3_v = (const float*)d_in[22];
    const float* sc_w  = (const float*)d_in[23];
    const float* sc_b  = (const float*)d_in[24];
    const float* scbn_g = (const float*)d_in[25];
    const float* scbn_b = (const float*)d_in[26];
    const float* scbn_m = (const float*)d_in[27];
    const float* scbn_v = (const float*)d_in[28];
    float* out = (float*)d_out;

    float *w1s, *w3s, *wscs, *t1, *vscale, *vshift, *tfin, *pos;
    float *out1, *qb, *kb, *vb, *attn, *attout;
    cudaGetSymbolAddress((void**)&w1s,   d_w1s);
    cudaGetSymbolAddress((void**)&w3s,   d_w3s);
    cudaGetSymbolAddress((void**)&wscs,  d_wscs);
    cudaGetSymbolAddress((void**)&t1,    d_t1);
    cudaGetSymbolAddress((void**)&vscale,d_vscale);
    cudaGetSymbolAddress((void**)&vshift,d_vshift);
    cudaGetSymbolAddress((void**)&tfin,  d_tfin);
    cudaGetSymbolAddress((void**)&pos,   d_pos);
    cudaGetSymbolAddress((void**)&out1,  d_out1);
    cudaGetSymbolAddress((void**)&qb,    d_qb);
    cudaGetSymbolAddress((void**)&kb,    d_kb);
    cudaGetSymbolAddress((void**)&vb,    d_vb);
    cudaGetSymbolAddress((void**)&attn,  d_attn);
    cudaGetSymbolAddress((void**)&attout,d_attout);

    scale_w_kernel<<<(P_ * CIN + 255) / 256, 256>>>(conv1_w, bn1_g, bn1_v, w1s, P_ * CIN, CIN);
    scale_w_kernel<<<(COUT * P_ + 255) / 256, 256>>>(conv3_w, bn3_g, bn3_v, w3s, COUT * P_, P_);
    scale_w_kernel<<<(COUT * CIN + 255) / 256, 256>>>(sc_w, scbn_g, scbn_v, wscs, COUT * CIN, CIN);
    prep_vec_kernel<<<(COUT + 255) / 256, 256>>>(bn1_g, bn1_b, bn1_m, bn1_v,
                                                 bn2_g, bn2_b, bn2_m, bn2_v, v_b,
                                                 bn3_g, bn3_b, bn3_m, bn3_v, sc_b,
                                                 scbn_g, scbn_b, scbn_m, scbn_v);
    pos_kernel<<<(HEADS * DH * NSP + 255) / 256, 256>>>(rel_h, rel_w);

    // conv1 + BN1 + ReLU : out1[b][p][n]
    gemm_kernel<false, true, false, true, true, false><<<dim3(2, 4, B_), 256>>>(
        w1s, CIN, 0, x, NSP, (long)CIN * NSP, CIN,
        nullptr, 0, 0, 0, nullptr, 0, 0, 0,
        out1, (long)P_ * NSP, nullptr, t1);

    // q, k, v (v has BN2 folded in)
    gemm_kernel<false, true, false, true, false, false><<<dim3(2, 4, B_), 256>>>(
        q_w, P_, 0, out1, NSP, (long)P_ * NSP, P_,
        nullptr, 0, 0, 0, nullptr, 0, 0, 0,
        qb, (long)P_ * NSP, nullptr, q_b);
    gemm_kernel<false, true, false, true, false, false><<<dim3(2, 4, B_), 256>>>(
        k_w, P_, 0, out1, NSP, (long)P_ * NSP, P_,
        nullptr, 0, 0, 0, nullptr, 0, 0, 0,
        kb, (long)P_ * NSP, nullptr, k_b);
    gemm_kernel<false, true, false, true, false, false><<<dim3(2, 4, B_), 256>>>(
        v_w, P_, 0, out1, NSP, (long)P_ * NSP, P_,
        nullptr, 0, 0, 0, nullptr, 0, 0, 0,
        vb, (long)P_ * NSP, vscale, vshift);

    // logits L[n][m] = Q^T K + pos^T Q per (b,h)
    gemm_kernel<true, true, true, true, false, true><<<dim3(2, 2, B_ * HEADS), 256>>>(
        qb, NSP, (long)DH * NSP, kb, NSP, (long)DH * NSP, DH,
        pos, NSP, (long)DH * NSP, HEADS,
        qb, NSP, (long)DH * NSP, DH,
        attn, (long)NSP * NSP, nullptr, nullptr);

    softmax256_kernel<<<(B_ * HEADS * NSP) / 8, 256>>>(attn);

    // out[d][n] = V' · A^T, ReLU
    gemm_kernel<false, false, false, false, true, false><<<dim3(2, 1, B_ * HEADS), 256>>>(
        vb, NSP, (long)DH * NSP, attn, NSP, (long)NSP * NSP, NSP,
        nullptr, 0, 0, 0, nullptr, 0, 0, 0,
        attout, (long)DH * NSP, nullptr, nullptr);

    // conv3+BN3 + shortcut+scBN + add + ReLU
    gemm_kernel<false, true, false, true, true, true><<<dim3(2, 16, B_), 256>>>(
        w3s, P_, 0, attout, NSP, (long)P_ * NSP, P_,
        wscs, CIN, 0, 0, x, NSP, (long)CIN * NSP, CIN,
        out, (long)COUT * NSP, nullptr, tfin);
}

// round 6
// speedup vs baseline: 2.1394x; 1.3598x over previous
#include <cuda_runtime.h>
#include <cuda_bf16.h>
#include <math.h>
#include <stdint.h>
typedef __nv_bfloat16 bf16;

#define EPSBN 1e-5f
#define B_    64
#define CIN   1024
#define P_    512
#define COUT  2048
#define NSP   256
#define HEADS 4
#define DH    128

// ---------------- scratch: bf16 hi plane + lo plane (lo at +count) ----------------
__device__ __align__(16) bf16 g_xt [2*16777216];  // xT[b][n][cin]
__device__ __align__(16) bf16 g_w1 [2*524288];    // [512][1024]
__device__ __align__(16) bf16 g_wq [2*262144];
__device__ __align__(16) bf16 g_wk [2*262144];
__device__ __align__(16) bf16 g_wv [2*262144];    // pre-scaled by BN2
__device__ __align__(16) bf16 g_w3 [2*1048576];
__device__ __align__(16) bf16 g_wsc[2*2097152];
__device__ __align__(16) bf16 g_o1 [2*8388608];   // out1[b][n][p]
__device__ __align__(16) bf16 g_q  [2*8388608];   // q[b][n][p]
__device__ __align__(16) bf16 g_k  [2*8388608];
__device__ __align__(16) bf16 g_v  [2*8388608];   // v'[b][p][m]
__device__ __align__(16) bf16 g_ao [2*8388608];   // attout[b][n][p]
__device__ __align__(16) bf16 g_at [2*16777216];  // attn bf16 [bh][n][m]
__device__ __align__(16) bf16 g_pos[2*131072];    // posT[h][n][d]
__device__ __align__(16) float g_attnf[16777216];
__device__ __align__(16) float d_t1[P_], d_vshift[P_], d_tfin[COUT];

// ---------------- helpers ----------------
__device__ __forceinline__ uint32_t su32(const void* p){uint32_t a;asm("{ .reg .u64 t; cvta.to.shared.u64 t, %1; cvt.u32.u64 %0, t; }":"=r"(a):"l"(p));return a;}
__device__ __forceinline__ void cp16(uint32_t d, const void* s){asm volatile("cp.async.cg.shared.global [%0], [%1], 16;"::"r"(d),"l"(s));}
__device__ __forceinline__ void spl(float v, bf16& h, bf16& l){h=__float2bfloat16(v); l=__float2bfloat16(v-__bfloat162float(h));}
__device__ __forceinline__ uint32_t pk(bf16 a, bf16 b){return (uint32_t)__bfloat16_as_ushort(a)|((uint32_t)__bfloat16_as_ushort(b)<<16);}
__device__ __forceinline__ void mma16816(float* c, const uint32_t* a, const uint32_t* b){
    asm volatile("mma.sync.aligned.m16n8k16.row.col.f32.bf16.bf16.f32 "
        "{%0,%1,%2,%3},{%4,%5,%6,%7},{%8,%9},{%0,%1,%2,%3};"
        : "+f"(c[0]), "+f"(c[1]), "+f"(c[2]), "+f"(c[3])
        : "r"(a[0]), "r"(a[1]), "r"(a[2]), "r"(a[3]), "r"(b[0]), "r"(b[1]));
}

// ---------------- tensor-core GEMM: BM=BN=128, BK=32, all operands bf16 k-fast ----------------
// plane = 128 rows x 80B (32 bf16 + pad). planes: Ah,Al,Bh,Bl; 2 buffers.
#define PLANE 10240
#define BUFSZ 40960
#define SMEMSZ 81920

template<bool BIASROW, bool RELU, bool HAS2, bool OUTBF>
__global__ void __launch_bounds__(256) tc(
  const bf16* __restrict__ A1, long aso1, long asi1, int adiv1, int lda1, long alod1, int K1,
  const bf16* __restrict__ B1, long bso1, long bsi1, int bdiv1, int ldb1, long blod1,
  const bf16* __restrict__ A2, long aso2, long asi2, int adiv2, int lda2, long alod2, int K2,
  const bf16* __restrict__ B2, long bso2, long bsi2, int bdiv2, int ldb2, long blod2,
  void* __restrict__ C, long cso, long csi, int cdiv, int ldc, long clod,
  const float* __restrict__ bias)
{
    extern __shared__ char sm[];
    const uint32_t sbase = su32(sm);
    const int tid = threadIdx.x;
    const int z = blockIdx.z, m0 = blockIdx.y*128, n0 = blockIdx.x*128;
    const int lane = tid&31, w = tid>>5;
    const int wm = w>>1, wn = w&1;
    const int qr = lane>>2, qk = lane&3;

    const bf16* pA1 = A1 + (long)(z/adiv1)*aso1 + (long)(z%adiv1)*asi1;
    const bf16* pB1 = B1 + (long)(z/bdiv1)*bso1 + (long)(z%bdiv1)*bsi1;
    const bf16* pA2 = HAS2 ? A2 + (long)(z/adiv2)*aso2 + (long)(z%adiv2)*asi2 : nullptr;
    const bf16* pB2 = HAS2 ? B2 + (long)(z/bdiv2)*bso2 + (long)(z%bdiv2)*bsi2 : nullptr;
    const int nst1 = K1/32, nst = nst1 + (HAS2 ? K2/32 : 0);

    float acc[2][8][4];
#pragma unroll
    for(int i=0;i<2;++i)
#pragma unroll
        for(int j=0;j<8;++j)
#pragma unroll
            for(int q=0;q<4;++q) acc[i][j][q]=0.0f;

    auto ld=[&](int c){
        const bf16 *pa,*pb; int la,lb,k0; long al,bl;
        if(!HAS2 || c<nst1){ pa=pA1; pb=pB1; la=lda1; lb=ldb1; al=alod1; bl=blod1; k0=c*32; }
        else               { pa=pA2; pb=pB2; la=lda2; lb=ldb2; al=alod2; bl=blod2; k0=(c-nst1)*32; }
        uint32_t sb = sbase + (uint32_t)(c&1)*BUFSZ;
#pragma unroll
        for(int it=0;it<2;++it){
            int ch=tid+it*256, r=ch>>2, q=ch&3;
            const bf16* sa = pa + (long)(m0+r)*la + k0 + q*8;
            uint32_t da = sb + (uint32_t)r*80 + q*16;
            cp16(da, sa);            cp16(da+PLANE, sa+al);
            const bf16* sbp = pb + (long)(n0+r)*lb + k0 + q*8;
            cp16(da+2*PLANE, sbp);   cp16(da+3*PLANE, sbp+bl);
        }
        asm volatile("cp.async.commit_group;":::"memory");
    };

    auto compute=[&](int buf){
        const uint32_t* P  = (const uint32_t*)(sm + buf*BUFSZ);
        const uint32_t* Ah = P;
        const uint32_t* Al = P + PLANE/4;
        const uint32_t* Bh = P + 2*(PLANE/4);
        const uint32_t* Bl = P + 3*(PLANE/4);
#pragma unroll
        for(int s=0;s<2;++s){
            const int r0 = s*8+qk, r1 = r0+4;
            uint32_t ah[2][4], al[2][4];
#pragma unroll
            for(int mi=0;mi<2;++mi){
                int mc = wm*32 + mi*16 + qr;
                ah[mi][0]=Ah[mc*20+r0];     ah[mi][1]=Ah[(mc+8)*20+r0];
                ah[mi][2]=Ah[mc*20+r1];     ah[mi][3]=Ah[(mc+8)*20+r1];
                al[mi][0]=Al[mc*20+r0];     al[mi][1]=Al[(mc+8)*20+r0];
                al[mi][2]=Al[mc*20+r1];     al[mi][3]=Al[(mc+8)*20+r1];
            }
#pragma unroll
            for(int ni=0;ni<8;++ni){
                int nc = wn*64 + ni*8 + qr;
                uint32_t bh[2], bl[2];
                bh[0]=Bh[nc*20+r0]; bh[1]=Bh[nc*20+r1];
                bl[0]=Bl[nc*20+r0]; bl[1]=Bl[nc*20+r1];
#pragma unroll
                for(int mi=0;mi<2;++mi){
                    mma16816(acc[mi][ni], ah[mi], bh);
                    mma16816(acc[mi][ni], ah[mi], bl);
                    mma16816(acc[mi][ni], al[mi], bh);
                }
            }
        }
    };

    ld(0);
    if(nst>1) ld(1);
    for(int c=0;c<nst;++c){
        if(c+1<nst) asm volatile("cp.async.wait_group 1;":::"memory");
        else        asm volatile("cp.async.wait_group 0;":::"memory");
        __syncthreads();
        compute(c&1);
        __syncthreads();
        if(c+2<nst) ld(c+2);
    }

    // ---------------- epilogue ----------------
    long cz = (long)(z/cdiv)*cso + (long)(z%cdiv)*csi;
#pragma unroll
    for(int mi=0;mi<2;++mi){
#pragma unroll
        for(int half=0;half<2;++half){
            int row = m0 + wm*32 + mi*16 + qr + half*8;
            float tr = (BIASROW && bias) ? __ldg(bias+row) : 0.0f;
#pragma unroll
            for(int ni=0;ni<8;++ni){
                int col = n0 + wn*64 + ni*8 + qk*2;
                float v0 = acc[mi][ni][half*2], v1 = acc[mi][ni][half*2+1];
                if(BIASROW){ v0 += tr; v1 += tr; }
                else if(bias){ v0 += __ldg(bias+col); v1 += __ldg(bias+col+1); }
                if(RELU){ v0 = fmaxf(v0,0.0f); v1 = fmaxf(v1,0.0f); }
                if(OUTBF){
                    bf16 h0,l0,h1,l1; spl(v0,h0,l0); spl(v1,h1,l1);
                    bf16* Cb = (bf16*)C + cz + (long)row*ldc + col;
                    *(uint32_t*)Cb = pk(h0,h1);
                    *(uint32_t*)(Cb+clod) = pk(l0,l1);
                } else {
                    float2 f = {v0, v1};
                    *(float2*)((float*)C + cz + (long)row*ldc + col) = f;
                }
            }
        }
    }
}

// ---------------- prep kernels ----------------
__global__ void k_convw(const float* __restrict__ w, const float* __restrict__ g,
                        const float* __restrict__ vr, bf16* __restrict__ o, long lod, int K, int total){
    int i = blockIdx.x*256 + threadIdx.x; if(i>=total) return;
    float s = g ? g[i/K]*rsqrtf(vr[i/K]+EPSBN) : 1.0f;
    bf16 h,l; spl(w[i]*s,h,l);
    o[i]=h; o[i+lod]=l;
}
__global__ void k_xt(const float* __restrict__ x, bf16* __restrict__ o){
    __shared__ float t[32][33];
    int c0=blockIdx.x*32, nn0=blockIdx.y*32, b=blockIdx.z, tx=threadIdx.x, ty=threadIdx.y;
#pragma unroll
    for(int i=0;i<4;++i) t[ty+i*8][tx] = x[((long)b*1024 + c0+ty+i*8)*256 + nn0+tx];
    __syncthreads();
    bf16* ob = o + (long)b*262144;
#pragma unroll
    for(int i=0;i<4;++i){
        bf16 h,l; spl(t[tx][ty+i*8],h,l);
        long idx = (long)(nn0+ty+i*8)*1024 + c0+tx;
        ob[idx]=h; ob[idx+16777216]=l;
    }
}
__global__ void k_posT(const float* __restrict__ rh, const float* __restrict__ rw, bf16* __restrict__ o){
    int i = blockIdx.x*256 + threadIdx.x; if(i>=131072) return;
    int d = i&127, n = (i>>7)&255, h = i>>15;
    int hd = h*128+d;
    float v = rh[hd*16+(n&15)] + rw[hd*16+(n>>4)];
    bf16 hh,ll; spl(v,hh,ll);
    o[i]=hh; o[i+131072]=ll;
}
__global__ void k_prepvec(const float* g1,const float* b1,const float* m1,const float* v1,
                          const float* g2,const float* b2,const float* m2,const float* v2,const float* vbv,
                          const float* g3,const float* b3,const float* m3,const float* v3,const float* scb,
                          const float* gs,const float* bs,const float* ms,const float* vs){
    int i = blockIdx.x*256 + threadIdx.x;
    if(i<P_){
        float s1=g1[i]*rsqrtf(v1[i]+EPSBN); d_t1[i]=b1[i]-m1[i]*s1;
        float s2=g2[i]*rsqrtf(v2[i]+EPSBN);
        d_vshift[i]=fmaf(vbv[i],s2,b2[i]-m2[i]*s2);     // BN2 folded into V
    }
    if(i<COUT){
        float s3=g3[i]*rsqrtf(v3[i]+EPSBN);
        float ss=gs[i]*rsqrtf(vs[i]+EPSBN);
        d_tfin[i]=(b3[i]-m3[i]*s3) + fmaf(scb[i]-ms[i],ss,bs[i]);
    }
}
__global__ void k_softmax(const float* __restrict__ a, bf16* __restrict__ o){
    int row = blockIdx.x*8 + (threadIdx.x>>5), lane = threadIdx.x&31;
    const float* rp = a + (long)row*256;
    float4 f0 = ((const float4*)rp)[lane*2], f1 = ((const float4*)rp)[lane*2+1];
    float v[8] = {f0.x,f0.y,f0.z,f0.w,f1.x,f1.y,f1.z,f1.w};
    float mx = -1e30f;
#pragma unroll
    for(int j=0;j<8;++j) mx = fmaxf(mx,v[j]);
#pragma unroll
    for(int s=16;s;s>>=1) mx = fmaxf(mx,__shfl_xor_sync(~0u,mx,s));
    float sum = 0;
#pragma unroll
    for(int j=0;j<8;++j){ v[j]=__expf(v[j]-mx); sum+=v[j]; }
#pragma unroll
    for(int s=16;s;s>>=1) sum += __shfl_xor_sync(~0u,sum,s);
    float inv = 1.0f/sum;
    uint32_t hw[4], lw[4];
#pragma unroll
    for(int p=0;p<4;++p){
        bf16 h0,l0,h1,l1;
        spl(v[2*p]*inv,h0,l0); spl(v[2*p+1]*inv,h1,l1);
        hw[p]=pk(h0,h1); lw[p]=pk(l0,l1);
    }
    bf16* ob = o + (long)row*256 + lane*8;
    uint4 hq={hw[0],hw[1],hw[2],hw[3]}, lq={lw[0],lw[1],lw[2],lw[3]};
    *(uint4*)ob = hq;
    *(uint4*)(ob+16777216) = lq;
}

// ---------------- launch ----------------
extern "C" void kernel_launch(void* const* d_in, const int* in_sizes, int n_in,
                              void* d_out, int out_size) {
    const float *x=(const float*)d_in[0], *c1w=(const float*)d_in[1];
    const float *b1g=(const float*)d_in[2],*b1b=(const float*)d_in[3],*b1m=(const float*)d_in[4],*b1v=(const float*)d_in[5];
    const float *qw=(const float*)d_in[6],*qbv=(const float*)d_in[7],*kw=(const float*)d_in[8],*kbv=(const float*)d_in[9];
    const float *vw=(const float*)d_in[10],*vbv=(const float*)d_in[11],*rh=(const float*)d_in[12],*rwv=(const float*)d_in[13];
    const float *b2g=(const float*)d_in[14],*b2b=(const float*)d_in[15],*b2m=(const float*)d_in[16],*b2v=(const float*)d_in[17];
    const float *c3w=(const float*)d_in[18];
    const float *b3g=(const float*)d_in[19],*b3b=(const float*)d_in[20],*b3m=(const float*)d_in[21],*b3v=(const float*)d_in[22];
    const float *scw=(const float*)d_in[23],*scb=(const float*)d_in[24];
    const float *sg=(const float*)d_in[25],*sb=(const float*)d_in[26],*smn=(const float*)d_in[27],*sv=(const float*)d_in[28];

    bf16 *xt,*w1,*wq,*wk,*wv,*w3,*wsc,*o1,*q,*k,*v,*ao,*at,*pos;
    float *attnf,*t1,*vsh,*tf;
    cudaGetSymbolAddress((void**)&xt, g_xt);   cudaGetSymbolAddress((void**)&w1, g_w1);
    cudaGetSymbolAddress((void**)&wq, g_wq);   cudaGetSymbolAddress((void**)&wk, g_wk);
    cudaGetSymbolAddress((void**)&wv, g_wv);   cudaGetSymbolAddress((void**)&w3, g_w3);
    cudaGetSymbolAddress((void**)&wsc,g_wsc);  cudaGetSymbolAddress((void**)&o1, g_o1);
    cudaGetSymbolAddress((void**)&q,  g_q);    cudaGetSymbolAddress((void**)&k,  g_k);
    cudaGetSymbolAddress((void**)&v,  g_v);    cudaGetSymbolAddress((void**)&ao, g_ao);
    cudaGetSymbolAddress((void**)&at, g_at);   cudaGetSymbolAddress((void**)&pos,g_pos);
    cudaGetSymbolAddress((void**)&attnf, g_attnf);
    cudaGetSymbolAddress((void**)&t1, d_t1);   cudaGetSymbolAddress((void**)&vsh, d_vshift);
    cudaGetSymbolAddress((void**)&tf, d_tfin);

    cudaFuncSetAttribute(tc<false,true ,false,true >, cudaFuncAttributeMaxDynamicSharedMemorySize, SMEMSZ);
    cudaFuncSetAttribute(tc<false,false,false,true >, cudaFuncAttributeMaxDynamicSharedMemorySize, SMEMSZ);
    cudaFuncSetAttribute(tc<true ,false,false,true >, cudaFuncAttributeMaxDynamicSharedMemorySize, SMEMSZ);
    cudaFuncSetAttribute(tc<false,false,true ,false>, cudaFuncAttributeMaxDynamicSharedMemorySize, SMEMSZ);
    cudaFuncSetAttribute(tc<true ,true ,true ,false>, cudaFuncAttributeMaxDynamicSharedMemorySize, SMEMSZ);

    // prep: convert weights/x once (bf16 hi/lo), fold BN
    k_convw<<<2048,256>>>(c1w, b1g, b1v, w1, 524288, 1024, 524288);
    k_convw<<<1024,256>>>(qw, nullptr, nullptr, wq, 262144, 512, 262144);
    k_convw<<<1024,256>>>(kw, nullptr, nullptr, wk, 262144, 512, 262144);
    k_convw<<<1024,256>>>(vw, b2g, b2v, wv, 262144, 512, 262144);     // BN2 scale folded
    k_convw<<<4096,256>>>(c3w, b3g, b3v, w3, 1048576, 512, 1048576);
    k_convw<<<8192,256>>>(scw, sg, sv, wsc, 2097152, 1024, 2097152);
    k_xt<<<dim3(32,8,64),dim3(32,8)>>>(x, xt);
    k_posT<<<512,256>>>(rh, rwv, pos);
    k_prepvec<<<8,256>>>(b1g,b1b,b1m,b1v, b2g,b2b,b2m,b2v,vbv, b3g,b3b,b3m,b3v,scb, sg,sb,smn,sv);

    // 1) out1[b][n][p] = xT·w1 + t1[col], ReLU
    tc<false,true,false,true><<<dim3(4,2,64),256,SMEMSZ>>>(
        xt,262144,0,1,1024,16777216,1024,  w1,0,0,1,1024,524288,
        nullptr,0,0,1,0,0,0, nullptr,0,0,1,0,0,
        o1,131072,0,1,512,8388608, t1);
    // 2) q[b][n][p]
    tc<false,false,false,true><<<dim3(4,2,64),256,SMEMSZ>>>(
        o1,131072,0,1,512,8388608,512,  wq,0,0,1,512,262144,
        nullptr,0,0,1,0,0,0, nullptr,0,0,1,0,0,
        q,131072,0,1,512,8388608, qbv);
    // 3) k[b][n][p]
    tc<false,false,false,true><<<dim3(4,2,64),256,SMEMSZ>>>(
        o1,131072,0,1,512,8388608,512,  wk,0,0,1,512,262144,
        nullptr,0,0,1,0,0,0, nullptr,0,0,1,0,0,
        k,131072,0,1,512,8388608, kbv);
    // 4) v'[b][p][m] = (s2·wv)·out1 + vshift[row]
    tc<true,false,false,true><<<dim3(2,4,64),256,SMEMSZ>>>(
        wv,0,0,1,512,262144,512,  o1,131072,0,1,512,8388608,
        nullptr,0,0,1,0,0,0, nullptr,0,0,1,0,0,
        v,131072,0,1,256,8388608, vsh);
    // 5) logits[bh][n][m] = q·k + posT·q (two-phase)
    tc<false,false,true,false><<<dim3(2,2,256),256,SMEMSZ>>>(
        q,131072,128,4,512,8388608,128,  k,131072,128,4,512,8388608,
        pos,0,32768,4,128,131072,128,    q,131072,128,4,512,8388608,
        attnf,65536,0,1,256,0, nullptr);
    // 6) softmax -> attn bf16
    k_softmax<<<8192,256>>>(attnf, at);
    // 7) attout[b][n][h*128+d] = attn·v', ReLU
    tc<false,true,false,true><<<dim3(1,2,256),256,SMEMSZ>>>(
        at,65536,0,1,256,16777216,256,  v,131072,32768,4,256,8388608,
        nullptr,0,0,1,0,0,0, nullptr,0,0,1,0,0,
        ao,131072,128,4,512,8388608, nullptr);
    // 8) out[b][cout][n] = w3·attout + wsc·xT + tfin[row], ReLU
    tc<true,true,true,false><<<dim3(2,16,64),256,SMEMSZ>>>(
        w3,0,0,1,512,1048576,512,  ao,131072,0,1,512,8388608,
        wsc,0,0,1,1024,2097152,1024,  xt,262144,0,1,1024,16777216,
        d_out,524288,0,1,256,0, tf);
}

// round 7
// speedup vs baseline: 2.3361x; 1.0919x over previous
#include <cuda_runtime.h>
#include <cuda_bf16.h>
#include <math.h>
#include <stdint.h>
typedef __nv_bfloat16 bf16;

#define EPSBN 1e-5f
#define B_    64
#define CIN   1024
#define P_    512
#define COUT  2048
#define NSP   256
#define HEADS 4
#define DH    128

// ---------------- scratch: bf16 hi plane + lo plane (lo at +count) ----------------
__device__ __align__(16) bf16 g_xt [2*16777216];  // xT[b][n][cin]
__device__ __align__(16) bf16 g_w1 [2*524288];
__device__ __align__(16) bf16 g_wq [2*262144];
__device__ __align__(16) bf16 g_wk [2*262144];
__device__ __align__(16) bf16 g_wv [2*262144];    // pre-scaled by BN2
__device__ __align__(16) bf16 g_w3 [2*1048576];
__device__ __align__(16) bf16 g_wsc[2*2097152];
__device__ __align__(16) bf16 g_o1 [2*8388608];   // out1[b][n][p]
__device__ __align__(16) bf16 g_q  [2*8388608];
__device__ __align__(16) bf16 g_k  [2*8388608];
__device__ __align__(16) bf16 g_v  [2*8388608];   // v'[b][p][m]
__device__ __align__(16) bf16 g_ao [2*8388608];   // attout[b][n][p]
__device__ __align__(16) bf16 g_at [2*16777216];  // attn bf16 [bh][n][m]
__device__ __align__(16) bf16 g_pos[2*131072];    // posT[h][n][d]
__device__ __align__(16) float g_attnf[16777216];
__device__ __align__(16) float d_t1[P_], d_vshift[P_], d_tfin[COUT];

// ---------------- helpers ----------------
__device__ __forceinline__ uint32_t su32(const void* p){uint32_t a;asm("{ .reg .u64 t; cvta.to.shared.u64 t, %1; cvt.u32.u64 %0, t; }":"=r"(a):"l"(p));return a;}
__device__ __forceinline__ void cp16(uint32_t d, const void* s){asm volatile("cp.async.cg.shared.global [%0], [%1], 16;"::"r"(d),"l"(s));}
__device__ __forceinline__ void spl(float v, bf16& h, bf16& l){h=__float2bfloat16(v); l=__float2bfloat16(v-__bfloat162float(h));}
__device__ __forceinline__ uint32_t pk(bf16 a, bf16 b){return (uint32_t)__bfloat16_as_ushort(a)|((uint32_t)__bfloat16_as_ushort(b)<<16);}
__device__ __forceinline__ void mma16816(float* c, const uint32_t* a, const uint32_t* b){
    asm volatile("mma.sync.aligned.m16n8k16.row.col.f32.bf16.bf16.f32 "
        "{%0,%1,%2,%3},{%4,%5,%6,%7},{%8,%9},{%0,%1,%2,%3};"
        : "+f"(c[0]), "+f"(c[1]), "+f"(c[2]), "+f"(c[3])
        : "r"(a[0]), "r"(a[1]), "r"(a[2]), "r"(a[3]), "r"(b[0]), "r"(b[1]));
}
#define LDM4(r, a) asm volatile("ldmatrix.sync.aligned.m8n8.x4.shared.b16 {%0,%1,%2,%3}, [%4];" \
    : "=r"((r)[0]),"=r"((r)[1]),"=r"((r)[2]),"=r"((r)[3]) : "r"(a))

// ---------------- tensor-core GEMM: BM=BN=128, BK=32, all operands bf16 k-fast ----------------
// plane = 128 rows x 80B (32 bf16 + pad). planes: Ah,Al,Bh,Bl; 2 buffers.
#define PLANE 10240
#define BUFSZ 40960
#define SMEMSZ 81920

template<bool BIASROW, bool RELU, bool HAS2, bool OUTBF>
__global__ void __launch_bounds__(256) tc(
  const bf16* __restrict__ A1, long aso1, long asi1, int adiv1, int lda1, long alod1, int K1,
  const bf16* __restrict__ B1, long bso1, long bsi1, int bdiv1, int ldb1, long blod1,
  const bf16* __restrict__ A2, long aso2, long asi2, int adiv2, int lda2, long alod2, int K2,
  const bf16* __restrict__ B2, long bso2, long bsi2, int bdiv2, int ldb2, long blod2,
  void* __restrict__ C, long cso, long csi, int cdiv, int ldc, long clod,
  const float* __restrict__ bias)
{
    extern __shared__ char sm[];
    const uint32_t sbase = su32(sm);
    const int tid = threadIdx.x;
    const int z = blockIdx.z, m0 = blockIdx.y*128, n0 = blockIdx.x*128;
    const int lane = tid&31, w = tid>>5;
    const int wm = w>>1, wn = w&1;
    const int qr = lane>>2, qk = lane&3;

    // ldmatrix per-lane address offsets (bytes) within a plane
    const uint32_t a_off = (uint32_t)(wm*32 + (lane&15))*80 + (uint32_t)(lane>>4)*16;
    const uint32_t b_off = (uint32_t)(wn*64 + (lane&7) + (lane>>4)*8)*80 + (uint32_t)((lane>>3)&1)*16;

    const bf16* pA1 = A1 + (long)(z/adiv1)*aso1 + (long)(z%adiv1)*asi1;
    const bf16* pB1 = B1 + (long)(z/bdiv1)*bso1 + (long)(z%bdiv1)*bsi1;
    const bf16* pA2 = HAS2 ? A2 + (long)(z/adiv2)*aso2 + (long)(z%adiv2)*asi2 : nullptr;
    const bf16* pB2 = HAS2 ? B2 + (long)(z/bdiv2)*bso2 + (long)(z%bdiv2)*bsi2 : nullptr;
    const int nst1 = K1/32, nst = nst1 + (HAS2 ? K2/32 : 0);

    float acc[2][8][4];
#pragma unroll
    for(int i=0;i<2;++i)
#pragma unroll
        for(int j=0;j<8;++j)
#pragma unroll
            for(int q=0;q<4;++q) acc[i][j][q]=0.0f;

    auto ld=[&](int c){
        const bf16 *pa,*pb; int la,lb,k0; long al,bl;
        if(!HAS2 || c<nst1){ pa=pA1; pb=pB1; la=lda1; lb=ldb1; al=alod1; bl=blod1; k0=c*32; }
        else               { pa=pA2; pb=pB2; la=lda2; lb=ldb2; al=alod2; bl=blod2; k0=(c-nst1)*32; }
        uint32_t sb = sbase + (uint32_t)(c&1)*BUFSZ;
#pragma unroll
        for(int it=0;it<2;++it){
            int ch=tid+it*256, r=ch>>2, q=ch&3;
            const bf16* sa = pa + (long)(m0+r)*la + k0 + q*8;
            uint32_t da = sb + (uint32_t)r*80 + q*16;
            cp16(da, sa);            cp16(da+PLANE, sa+al);
            const bf16* sbp = pb + (long)(n0+r)*lb + k0 + q*8;
            cp16(da+2*PLANE, sbp);   cp16(da+3*PLANE, sbp+bl);
        }
        asm volatile("cp.async.commit_group;":::"memory");
    };

    auto compute=[&](int buf){
        const uint32_t base = sbase + (uint32_t)buf*BUFSZ;
#pragma unroll
        for(int s=0;s<2;++s){
            uint32_t ah[2][4], al[2][4];
#pragma unroll
            for(int mi=0;mi<2;++mi){
                LDM4(ah[mi], base + a_off + mi*1280 + s*32);
                LDM4(al[mi], base + PLANE + a_off + mi*1280 + s*32);
            }
#pragma unroll
            for(int nq=0;nq<4;++nq){
                uint32_t bh[4], bl[4];
                LDM4(bh, base + 2*PLANE + b_off + nq*1280 + s*32);
                LDM4(bl, base + 3*PLANE + b_off + nq*1280 + s*32);
#pragma unroll
                for(int half=0;half<2;++half){
                    int ni = nq*2 + half;
#pragma unroll
                    for(int mi=0;mi<2;++mi){
                        mma16816(acc[mi][ni], ah[mi], bh + half*2);
                        mma16816(acc[mi][ni], ah[mi], bl + half*2);
                        mma16816(acc[mi][ni], al[mi], bh + half*2);
                    }
                }
            }
        }
    };

    ld(0);
    if(nst>1) ld(1);
    for(int c=0;c<nst;++c){
        if(c+1<nst) asm volatile("cp.async.wait_group 1;":::"memory");
        else        asm volatile("cp.async.wait_group 0;":::"memory");
        __syncthreads();
        compute(c&1);
        __syncthreads();
        if(c+2<nst) ld(c+2);
    }

    // ---------------- epilogue ----------------
    long cz = (long)(z/cdiv)*cso + (long)(z%cdiv)*csi;
#pragma unroll
    for(int mi=0;mi<2;++mi){
#pragma unroll
        for(int half=0;half<2;++half){
            int row = m0 + wm*32 + mi*16 + qr + half*8;
            float tr = (BIASROW && bias) ? __ldg(bias+row) : 0.0f;
#pragma unroll
            for(int ni=0;ni<8;++ni){
                int col = n0 + wn*64 + ni*8 + qk*2;
                float v0 = acc[mi][ni][half*2], v1 = acc[mi][ni][half*2+1];
                if(BIASROW){ v0 += tr; v1 += tr; }
                else if(bias){ v0 += __ldg(bias+col); v1 += __ldg(bias+col+1); }
                if(RELU){ v0 = fmaxf(v0,0.0f); v1 = fmaxf(v1,0.0f); }
                if(OUTBF){
                    bf16 h0,l0,h1,l1; spl(v0,h0,l0); spl(v1,h1,l1);
                    bf16* Cb = (bf16*)C + cz + (long)row*ldc + col;
                    *(uint32_t*)Cb = pk(h0,h1);
                    *(uint32_t*)(Cb+clod) = pk(l0,l1);
                } else {
                    float2 f = {v0, v1};
                    *(float2*)((float*)C + cz + (long)row*ldc + col) = f;
                }
            }
        }
    }
}

// ---------------- prep kernels ----------------
__global__ void k_convw(const float* __restrict__ w, const float* __restrict__ g,
                        const float* __restrict__ vr, bf16* __restrict__ o, long lod, int K, int total){
    int i = blockIdx.x*256 + threadIdx.x; if(i>=total) return;
    float s = g ? g[i/K]*rsqrtf(vr[i/K]+EPSBN) : 1.0f;
    bf16 h,l; spl(w[i]*s,h,l);
    o[i]=h; o[i+lod]=l;
}
__global__ void k_xt(const float* __restrict__ x, bf16* __restrict__ o){
    __shared__ float t[32][33];
    int c0=blockIdx.x*32, nn0=blockIdx.y*32, b=blockIdx.z, tx=threadIdx.x, ty=threadIdx.y;
#pragma unroll
    for(int i=0;i<4;++i) t[ty+i*8][tx] = x[((long)b*1024 + c0+ty+i*8)*256 + nn0+tx];
    __syncthreads();
    bf16* ob = o + (long)b*262144;
#pragma unroll
    for(int i=0;i<4;++i){
        bf16 h,l; spl(t[tx][ty+i*8],h,l);
        long idx = (long)(nn0+ty+i*8)*1024 + c0+tx;
        ob[idx]=h; ob[idx+16777216]=l;
    }
}
__global__ void k_posT(const float* __restrict__ rh, const float* __restrict__ rw, bf16* __restrict__ o){
    int i = blockIdx.x*256 + threadIdx.x; if(i>=131072) return;
    int d = i&127, n = (i>>7)&255, h = i>>15;
    int hd = h*128+d;
    float v = rh[hd*16+(n&15)] + rw[hd*16+(n>>4)];
    bf16 hh,ll; spl(v,hh,ll);
    o[i]=hh; o[i+131072]=ll;
}
__global__ void k_prepvec(const float* g1,const float* b1,const float* m1,const float* v1,
                          const float* g2,const float* b2,const float* m2,const float* v2,const float* vbv,
                          const float* g3,const float* b3,const float* m3,const float* v3,const float* scb,
                          const float* gs,const float* bs,const float* ms,const float* vs){
    int i = blockIdx.x*256 + threadIdx.x;
    if(i<P_){
        float s1=g1[i]*rsqrtf(v1[i]+EPSBN); d_t1[i]=b1[i]-m1[i]*s1;
        float s2=g2[i]*rsqrtf(v2[i]+EPSBN);
        d_vshift[i]=fmaf(vbv[i],s2,b2[i]-m2[i]*s2);     // BN2 folded into V
    }
    if(i<COUT){
        float s3=g3[i]*rsqrtf(v3[i]+EPSBN);
        float ss=gs[i]*rsqrtf(vs[i]+EPSBN);
        d_tfin[i]=(b3[i]-m3[i]*s3) + fmaf(scb[i]-ms[i],ss,bs[i]);
    }
}
__global__ void k_softmax(const float* __restrict__ a, bf16* __restrict__ o){
    int row = blockIdx.x*8 + (threadIdx.x>>5), lane = threadIdx.x&31;
    const float* rp = a + (long)row*256;
    float4 f0 = ((const float4*)rp)[lane*2], f1 = ((const float4*)rp)[lane*2+1];
    float v[8] = {f0.x,f0.y,f0.z,f0.w,f1.x,f1.y,f1.z,f1.w};
    float mx = -1e30f;
#pragma unroll
    for(int j=0;j<8;++j) mx = fmaxf(mx,v[j]);
#pragma unroll
    for(int s=16;s;s>>=1) mx = fmaxf(mx,__shfl_xor_sync(~0u,mx,s));
    float sum = 0;
#pragma unroll
    for(int j=0;j<8;++j){ v[j]=__expf(v[j]-mx); sum+=v[j]; }
#pragma unroll
    for(int s=16;s;s>>=1) sum += __shfl_xor_sync(~0u,sum,s);
    float inv = 1.0f/sum;
    uint32_t hw[4], lw[4];
#pragma unroll
    for(int p=0;p<4;++p){
        bf16 h0,l0,h1,l1;
        spl(v[2*p]*inv,h0,l0); spl(v[2*p+1]*inv,h1,l1);
        hw[p]=pk(h0,h1); lw[p]=pk(l0,l1);
    }
    bf16* ob = o + (long)row*256 + lane*8;
    uint4 hq={hw[0],hw[1],hw[2],hw[3]}, lq={lw[0],lw[1],lw[2],lw[3]};
    *(uint4*)ob = hq;
    *(uint4*)(ob+16777216) = lq;
}

// ---------------- launch ----------------
extern "C" void kernel_launch(void* const* d_in, const int* in_sizes, int n_in,
                              void* d_out, int out_size) {
    const float *x=(const float*)d_in[0], *c1w=(const float*)d_in[1];
    const float *b1g=(const float*)d_in[2],*b1b=(const float*)d_in[3],*b1m=(const float*)d_in[4],*b1v=(const float*)d_in[5];
    const float *qw=(const float*)d_in[6],*qbv=(const float*)d_in[7],*kw=(const float*)d_in[8],*kbv=(const float*)d_in[9];
    const float *vw=(const float*)d_in[10],*vbv=(const float*)d_in[11],*rh=(const float*)d_in[12],*rwv=(const float*)d_in[13];
    const float *b2g=(const float*)d_in[14],*b2b=(const float*)d_in[15],*b2m=(const float*)d_in[16],*b2v=(const float*)d_in[17];
    const float *c3w=(const float*)d_in[18];
    const float *b3g=(const float*)d_in[19],*b3b=(const float*)d_in[20],*b3m=(const float*)d_in[21],*b3v=(const float*)d_in[22];
    const float *scw=(const float*)d_in[23],*scb=(const float*)d_in[24];
    const float *sg=(const float*)d_in[25],*sb=(const float*)d_in[26],*smn=(const float*)d_in[27],*sv=(const float*)d_in[28];

    bf16 *xt,*w1,*wq,*wk,*wv,*w3,*wsc,*o1,*q,*k,*v,*ao,*at,*pos;
    float *attnf,*t1,*vsh,*tf;
    cudaGetSymbolAddress((void**)&xt, g_xt);   cudaGetSymbolAddress((void**)&w1, g_w1);
    cudaGetSymbolAddress((void**)&wq, g_wq);   cudaGetSymbolAddress((void**)&wk, g_wk);
    cudaGetSymbolAddress((void**)&wv, g_wv);   cudaGetSymbolAddress((void**)&w3, g_w3);
    cudaGetSymbolAddress((void**)&wsc,g_wsc);  cudaGetSymbolAddress((void**)&o1, g_o1);
    cudaGetSymbolAddress((void**)&q,  g_q);    cudaGetSymbolAddress((void**)&k,  g_k);
    cudaGetSymbolAddress((void**)&v,  g_v);    cudaGetSymbolAddress((void**)&ao, g_ao);
    cudaGetSymbolAddress((void**)&at, g_at);   cudaGetSymbolAddress((void**)&pos,g_pos);
    cudaGetSymbolAddress((void**)&attnf, g_attnf);
    cudaGetSymbolAddress((void**)&t1, d_t1);   cudaGetSymbolAddress((void**)&vsh, d_vshift);
    cudaGetSymbolAddress((void**)&tf, d_tfin);

    cudaFuncSetAttribute(tc<false,true ,false,true >, cudaFuncAttributeMaxDynamicSharedMemorySize, SMEMSZ);
    cudaFuncSetAttribute(tc<false,false,false,true >, cudaFuncAttributeMaxDynamicSharedMemorySize, SMEMSZ);
    cudaFuncSetAttribute(tc<true ,false,false,true >, cudaFuncAttributeMaxDynamicSharedMemorySize, SMEMSZ);
    cudaFuncSetAttribute(tc<false,false,true ,false>, cudaFuncAttributeMaxDynamicSharedMemorySize, SMEMSZ);
    cudaFuncSetAttribute(tc<true ,true ,true ,false>, cudaFuncAttributeMaxDynamicSharedMemorySize, SMEMSZ);

    // prep: convert weights/x once (bf16 hi/lo), fold BN
    k_convw<<<2048,256>>>(c1w, b1g, b1v, w1, 524288, 1024, 524288);
    k_convw<<<1024,256>>>(qw, nullptr, nullptr, wq, 262144, 512, 262144);
    k_convw<<<1024,256>>>(kw, nullptr, nullptr, wk, 262144, 512, 262144);
    k_convw<<<1024,256>>>(vw, b2g, b2v, wv, 262144, 512, 262144);     // BN2 scale folded
    k_convw<<<4096,256>>>(c3w, b3g, b3v, w3, 1048576, 512, 1048576);
    k_convw<<<8192,256>>>(scw, sg, sv, wsc, 2097152, 1024, 2097152);
    k_xt<<<dim3(32,8,64),dim3(32,8)>>>(x, xt);
    k_posT<<<512,256>>>(rh, rwv, pos);
    k_prepvec<<<8,256>>>(b1g,b1b,b1m,b1v, b2g,b2b,b2m,b2v,vbv, b3g,b3b,b3m,b3v,scb, sg,sb,smn,sv);

    // 1) out1[b][n][p] = xT·w1 + t1[col], ReLU
    tc<false,true,false,true><<<dim3(4,2,64),256,SMEMSZ>>>(
        xt,262144,0,1,1024,16777216,1024,  w1,0,0,1,1024,524288,
        nullptr,0,0,1,0,0,0, nullptr,0,0,1,0,0,
        o1,131072,0,1,512,8388608, t1);
    // 2) q[b][n][p]
    tc<false,false,false,true><<<dim3(4,2,64),256,SMEMSZ>>>(
        o1,131072,0,1,512,8388608,512,  wq,0,0,1,512,262144,
        nullptr,0,0,1,0,0,0, nullptr,0,0,1,0,0,
        q,131072,0,1,512,8388608, qbv);
    // 3) k[b][n][p]
    tc<false,false,false,true><<<dim3(4,2,64),256,SMEMSZ>>>(
        o1,131072,0,1,512,8388608,512,  wk,0,0,1,512,262144,
        nullptr,0,0,1,0,0,0, nullptr,0,0,1,0,0,
        k,131072,0,1,512,8388608, kbv);
    // 4) v'[b][p][m] = (s2·wv)·out1 + vshift[row]
    tc<true,false,false,true><<<dim3(2,4,64),256,SMEMSZ>>>(
        wv,0,0,1,512,262144,512,  o1,131072,0,1,512,8388608,
        nullptr,0,0,1,0,0,0, nullptr,0,0,1,0,0,
        v,131072,0,1,256,8388608, vsh);
    // 5) logits[bh][n][m] = q·k + posT·q (two-phase)
    tc<false,false,true,false><<<dim3(2,2,256),256,SMEMSZ>>>(
        q,131072,128,4,512,8388608,128,  k,131072,128,4,512,8388608,
        pos,0,32768,4,128,131072,128,    q,131072,128,4,512,8388608,
        attnf,65536,0,1,256,0, nullptr);
    // 6) softmax -> attn bf16
    k_softmax<<<8192,256>>>(attnf, at);
    // 7) attout[b][n][h*128+d] = attn·v', ReLU
    tc<false,true,false,true><<<dim3(1,2,256),256,SMEMSZ>>>(
        at,65536,0,1,256,16777216,256,  v,131072,32768,4,256,8388608,
        nullptr,0,0,1,0,0,0, nullptr,0,0,1,0,0,
        ao,131072,128,4,512,8388608, nullptr);
    // 8) out[b][cout][n] = w3·attout + wsc·xT + tfin[row], ReLU
    tc<true,true,true,false><<<dim3(2,16,64),256,SMEMSZ>>>(
        w3,0,0,1,512,1048576,512,  ao,131072,0,1,512,8388608,
        wsc,0,0,1,1024,2097152,1024,  xt,262144,0,1,1024,16777216,
        d_out,524288,0,1,256,0, tf);
}

// round 8
// speedup vs baseline: 3.2481x; 1.3904x over previous
#include <cuda_runtime.h>
#include <cuda_fp16.h>
#include <math.h>
#include <stdint.h>
typedef __half hlf;

#define EPSBN 1e-5f
#define B_    64
#define CIN   1024
#define P_    512
#define COUT  2048
#define NSP   256
#define HEADS 4
#define DH    128

// ---------------- scratch: fp16 hi plane + lo plane (lo at +count) ----------------
__device__ __align__(16) hlf g_xt [2*16777216];  // xT[b][n][cin]
__device__ __align__(16) hlf g_w1 [2*524288];
__device__ __align__(16) hlf g_wq [2*262144];
__device__ __align__(16) hlf g_wk [2*262144];
__device__ __align__(16) hlf g_wv [2*262144];    // pre-scaled by BN2
__device__ __align__(16) hlf g_w3 [2*1048576];
__device__ __align__(16) hlf g_wsc[2*2097152];
__device__ __align__(16) hlf g_o1 [2*8388608];   // out1[b][n][p]
__device__ __align__(16) hlf g_q  [2*8388608];
__device__ __align__(16) hlf g_k  [2*8388608];
__device__ __align__(16) hlf g_v  [2*8388608];   // v'[b][p][m]
__device__ __align__(16) hlf g_ao [2*8388608];   // attout[b][n][p]
__device__ __align__(16) hlf g_at [2*16777216];  // attn fp16 [bh][n][m]
__device__ __align__(16) hlf g_pos[2*131072];    // posT[h][n][d]
__device__ __align__(16) float g_attnf[16777216];
__device__ __align__(16) float d_t1[P_], d_vshift[P_], d_tfin[COUT];

// ---------------- helpers ----------------
__device__ __forceinline__ uint32_t su32(const void* p){uint32_t a;asm("{ .reg .u64 t; cvta.to.shared.u64 t, %1; cvt.u32.u64 %0, t; }":"=r"(a):"l"(p));return a;}
__device__ __forceinline__ void cp16(uint32_t d, const void* s){asm volatile("cp.async.cg.shared.global [%0], [%1], 16;"::"r"(d),"l"(s));}
__device__ __forceinline__ void spl(float v, hlf& h, hlf& l){h=__float2half(v); l=__float2half(v-__half2float(h));}
__device__ __forceinline__ uint32_t pk(hlf a, hlf b){return (uint32_t)__half_as_ushort(a)|((uint32_t)__half_as_ushort(b)<<16);}
__device__ __forceinline__ void mma16816(float* c, const uint32_t* a, const uint32_t* b){
    asm volatile("mma.sync.aligned.m16n8k16.row.col.f32.f16.f16.f32 "
        "{%0,%1,%2,%3},{%4,%5,%6,%7},{%8,%9},{%0,%1,%2,%3};"
        : "+f"(c[0]), "+f"(c[1]), "+f"(c[2]), "+f"(c[3])
        : "r"(a[0]), "r"(a[1]), "r"(a[2]), "r"(a[3]), "r"(b[0]), "r"(b[1]));
}
#define LDM4(r, a) asm volatile("ldmatrix.sync.aligned.m8n8.x4.shared.b16 {%0,%1,%2,%3}, [%4];" \
    : "=r"((r)[0]),"=r"((r)[1]),"=r"((r)[2]),"=r"((r)[3]) : "r"(a))

// ---------------- tensor-core GEMM: BM=BN=128, BK=32 ----------------
// planes: Ah, Al, Bh (B rounded once). plane = 128 rows x 80B. 2 buffers.
#define PLANE 10240
#define BUFSZ 30720
#define SMEMSZ 61440

template<bool BIASROW, bool RELU, bool HAS2, bool OUTHF>
__global__ void __launch_bounds__(256) tc(
  const hlf* __restrict__ A1, long aso1, long asi1, int adiv1, int lda1, long alod1, int K1,
  const hlf* __restrict__ B1, long bso1, long bsi1, int bdiv1, int ldb1,
  const hlf* __restrict__ A2, long aso2, long asi2, int adiv2, int lda2, long alod2, int K2,
  const hlf* __restrict__ B2, long bso2, long bsi2, int bdiv2, int ldb2,
  void* __restrict__ C, long cso, long csi, int cdiv, int ldc, long clod,
  const float* __restrict__ bias)
{
    extern __shared__ char sm[];
    const uint32_t sbase = su32(sm);
    const int tid = threadIdx.x;
    const int z = blockIdx.z, m0 = blockIdx.y*128, n0 = blockIdx.x*128;
    const int lane = tid&31, w = tid>>5;
    const int wm = w>>1, wn = w&1;
    const int qr = lane>>2, qk = lane&3;

    const uint32_t a_off = (uint32_t)(wm*32 + (lane&15))*80 + (uint32_t)(lane>>4)*16;
    const uint32_t b_off = (uint32_t)(wn*64 + (lane&7) + (lane>>4)*8)*80 + (uint32_t)((lane>>3)&1)*16;

    const hlf* pA1 = A1 + (long)(z/adiv1)*aso1 + (long)(z%adiv1)*asi1;
    const hlf* pB1 = B1 + (long)(z/bdiv1)*bso1 + (long)(z%bdiv1)*bsi1;
    const hlf* pA2 = HAS2 ? A2 + (long)(z/adiv2)*aso2 + (long)(z%adiv2)*asi2 : nullptr;
    const hlf* pB2 = HAS2 ? B2 + (long)(z/bdiv2)*bso2 + (long)(z%bdiv2)*bsi2 : nullptr;
    const int nst1 = K1/32, nst = nst1 + (HAS2 ? K2/32 : 0);

    float acc[2][8][4];
#pragma unroll
    for(int i=0;i<2;++i)
#pragma unroll
        for(int j=0;j<8;++j)
#pragma unroll
            for(int q=0;q<4;++q) acc[i][j][q]=0.0f;

    auto ld=[&](int c){
        const hlf *pa,*pb; int la,lb,k0; long al;
        if(!HAS2 || c<nst1){ pa=pA1; pb=pB1; la=lda1; lb=ldb1; al=alod1; k0=c*32; }
        else               { pa=pA2; pb=pB2; la=lda2; lb=ldb2; al=alod2; k0=(c-nst1)*32; }
        uint32_t sb = sbase + (uint32_t)(c&1)*BUFSZ;
#pragma unroll
        for(int it=0;it<2;++it){
            int ch=tid+it*256, r=ch>>2, q=ch&3;
            const hlf* sa = pa + (long)(m0+r)*la + k0 + q*8;
            uint32_t da = sb + (uint32_t)r*80 + q*16;
            cp16(da, sa);            cp16(da+PLANE, sa+al);
            const hlf* sbp = pb + (long)(n0+r)*lb + k0 + q*8;
            cp16(da+2*PLANE, sbp);
        }
        asm volatile("cp.async.commit_group;":::"memory");
    };

    auto compute=[&](int buf){
        const uint32_t base = sbase + (uint32_t)buf*BUFSZ;
#pragma unroll
        for(int s=0;s<2;++s){
            uint32_t ah[2][4], al[2][4];
#pragma unroll
            for(int mi=0;mi<2;++mi){
                LDM4(ah[mi], base + a_off + mi*1280 + s*32);
                LDM4(al[mi], base + PLANE + a_off + mi*1280 + s*32);
            }
#pragma unroll
            for(int nq=0;nq<4;++nq){
                uint32_t bh[4];
                LDM4(bh, base + 2*PLANE + b_off + nq*1280 + s*32);
#pragma unroll
                for(int hf=0;hf<2;++hf){
                    int ni = nq*2 + hf;
#pragma unroll
                    for(int mi=0;mi<2;++mi){
                        mma16816(acc[mi][ni], ah[mi], bh + hf*2);
                        mma16816(acc[mi][ni], al[mi], bh + hf*2);
                    }
                }
            }
        }
    };

    ld(0);
    if(nst>1) ld(1);
    for(int c=0;c<nst;++c){
        if(c+1<nst) asm volatile("cp.async.wait_group 1;":::"memory");
        else        asm volatile("cp.async.wait_group 0;":::"memory");
        __syncthreads();
        compute(c&1);
        __syncthreads();
        if(c+2<nst) ld(c+2);
    }

    // ---------------- epilogue ----------------
    long cz = (long)(z/cdiv)*cso + (long)(z%cdiv)*csi;
#pragma unroll
    for(int mi=0;mi<2;++mi){
#pragma unroll
        for(int hf=0;hf<2;++hf){
            int row = m0 + wm*32 + mi*16 + qr + hf*8;
            float tr = (BIASROW && bias) ? __ldg(bias+row) : 0.0f;
#pragma unroll
            for(int ni=0;ni<8;++ni){
                int col = n0 + wn*64 + ni*8 + qk*2;
                float v0 = acc[mi][ni][hf*2], v1 = acc[mi][ni][hf*2+1];
                if(BIASROW){ v0 += tr; v1 += tr; }
                else if(bias){ v0 += __ldg(bias+col); v1 += __ldg(bias+col+1); }
                if(RELU){ v0 = fmaxf(v0,0.0f); v1 = fmaxf(v1,0.0f); }
                if(OUTHF){
                    hlf h0,l0,h1,l1; spl(v0,h0,l0); spl(v1,h1,l1);
                    hlf* Cb = (hlf*)C + cz + (long)row*ldc + col;
                    *(uint32_t*)Cb = pk(h0,h1);
                    *(uint32_t*)(Cb+clod) = pk(l0,l1);
                } else {
                    float2 f = {v0, v1};
                    *(float2*)((float*)C + cz + (long)row*ldc + col) = f;
                }
            }
        }
    }
}

// ---------------- prep kernels ----------------
__global__ void k_convw(const float* __restrict__ w, const float* __restrict__ g,
                        const float* __restrict__ vr, hlf* __restrict__ o, long lod, int K, int total){
    int i = blockIdx.x*256 + threadIdx.x; if(i>=total) return;
    float s = g ? g[i/K]*rsqrtf(vr[i/K]+EPSBN) : 1.0f;
    hlf h,l; spl(w[i]*s,h,l);
    o[i]=h; o[i+lod]=l;
}
__global__ void k_xt(const float* __restrict__ x, hlf* __restrict__ o){
    __shared__ float t[32][33];
    int c0=blockIdx.x*32, nn0=blockIdx.y*32, b=blockIdx.z, tx=threadIdx.x, ty=threadIdx.y;
#pragma unroll
    for(int i=0;i<4;++i) t[ty+i*8][tx] = x[((long)b*1024 + c0+ty+i*8)*256 + nn0+tx];
    __syncthreads();
    hlf* ob = o + (long)b*262144;
#pragma unroll
    for(int i=0;i<4;++i){
        hlf h,l; spl(t[tx][ty+i*8],h,l);
        long idx = (long)(nn0+ty+i*8)*1024 + c0+tx;
        ob[idx]=h; ob[idx+16777216]=l;
    }
}
__global__ void k_posT(const float* __restrict__ rh, const float* __restrict__ rw, hlf* __restrict__ o){
    int i = blockIdx.x*256 + threadIdx.x; if(i>=131072) return;
    int d = i&127, n = (i>>7)&255, h = i>>15;
    int hd = h*128+d;
    float v = rh[hd*16+(n&15)] + rw[hd*16+(n>>4)];
    hlf hh,ll; spl(v,hh,ll);
    o[i]=hh; o[i+131072]=ll;
}
__global__ void k_prepvec(const float* g1,const float* b1,const float* m1,const float* v1,
                          const float* g2,const float* b2,const float* m2,const float* v2,const float* vbv,
                          const float* g3,const float* b3,const float* m3,const float* v3,const float* scb,
                          const float* gs,const float* bs,const float* ms,const float* vs){
    int i = blockIdx.x*256 + threadIdx.x;
    if(i<P_){
        float s1=g1[i]*rsqrtf(v1[i]+EPSBN); d_t1[i]=b1[i]-m1[i]*s1;
        float s2=g2[i]*rsqrtf(v2[i]+EPSBN);
        d_vshift[i]=fmaf(vbv[i],s2,b2[i]-m2[i]*s2);     // BN2 folded into V
    }
    if(i<COUT){
        float s3=g3[i]*rsqrtf(v3[i]+EPSBN);
        float ss=gs[i]*rsqrtf(vs[i]+EPSBN);
        d_tfin[i]=(b3[i]-m3[i]*s3) + fmaf(scb[i]-ms[i],ss,bs[i]);
    }
}
__global__ void k_softmax(const float* __restrict__ a, hlf* __restrict__ o){
    int row = blockIdx.x*8 + (threadIdx.x>>5), lane = threadIdx.x&31;
    const float* rp = a + (long)row*256;
    float4 f0 = ((const float4*)rp)[lane*2], f1 = ((const float4*)rp)[lane*2+1];
    float v[8] = {f0.x,f0.y,f0.z,f0.w,f1.x,f1.y,f1.z,f1.w};
    float mx = -1e30f;
#pragma unroll
    for(int j=0;j<8;++j) mx = fmaxf(mx,v[j]);
#pragma unroll
    for(int s=16;s;s>>=1) mx = fmaxf(mx,__shfl_xor_sync(~0u,mx,s));
    float sum = 0;
#pragma unroll
    for(int j=0;j<8;++j){ v[j]=__expf(v[j]-mx); sum+=v[j]; }
#pragma unroll
    for(int s=16;s;s>>=1) sum += __shfl_xor_sync(~0u,sum,s);
    float inv = 1.0f/sum;
    uint32_t hw[4], lw[4];
#pragma unroll
    for(int p=0;p<4;++p){
        hlf h0,l0,h1,l1;
        spl(v[2*p]*inv,h0,l0); spl(v[2*p+1]*inv,h1,l1);
        hw[p]=pk(h0,h1); lw[p]=pk(l0,l1);
    }
    hlf* ob = o + (long)row*256 + lane*8;
    uint4 hq={hw[0],hw[1],hw[2],hw[3]}, lq={lw[0],lw[1],lw[2],lw[3]};
    *(uint4*)ob = hq;
    *(uint4*)(ob+16777216) = lq;
}

// ---------------- launch ----------------
extern "C" void kernel_launch(void* const* d_in, const int* in_sizes, int n_in,
                              void* d_out, int out_size) {
    const float *x=(const float*)d_in[0], *c1w=(const float*)d_in[1];
    const float *b1g=(const float*)d_in[2],*b1b=(const float*)d_in[3],*b1m=(const float*)d_in[4],*b1v=(const float*)d_in[5];
    const float *qw=(const float*)d_in[6],*qbv=(const float*)d_in[7],*kw=(const float*)d_in[8],*kbv=(const float*)d_in[9];
    const float *vw=(const float*)d_in[10],*vbv=(const float*)d_in[11],*rh=(const float*)d_in[12],*rwv=(const float*)d_in[13];
    const float *b2g=(const float*)d_in[14],*b2b=(const float*)d_in[15],*b2m=(const float*)d_in[16],*b2v=(const float*)d_in[17];
    const float *c3w=(const float*)d_in[18];
    const float *b3g=(const float*)d_in[19],*b3b=(const float*)d_in[20],*b3m=(const float*)d_in[21],*b3v=(const float*)d_in[22];
    const float *scw=(const float*)d_in[23],*scb=(const float*)d_in[24];
    const float *sg=(const float*)d_in[25],*sb=(const float*)d_in[26],*smn=(const float*)d_in[27],*sv=(const float*)d_in[28];

    hlf *xt,*w1,*wq,*wk,*wv,*w3,*wsc,*o1,*q,*k,*v,*ao,*at,*pos;
    float *attnf,*t1,*vsh,*tf;
    cudaGetSymbolAddress((void**)&xt, g_xt);   cudaGetSymbolAddress((void**)&w1, g_w1);
    cudaGetSymbolAddress((void**)&wq, g_wq);   cudaGetSymbolAddress((void**)&wk, g_wk);
    cudaGetSymbolAddress((void**)&wv, g_wv);   cudaGetSymbolAddress((void**)&w3, g_w3);
    cudaGetSymbolAddress((void**)&wsc,g_wsc);  cudaGetSymbolAddress((void**)&o1, g_o1);
    cudaGetSymbolAddress((void**)&q,  g_q);    cudaGetSymbolAddress((void**)&k,  g_k);
    cudaGetSymbolAddress((void**)&v,  g_v);    cudaGetSymbolAddress((void**)&ao, g_ao);
    cudaGetSymbolAddress((void**)&at, g_at);   cudaGetSymbolAddress((void**)&pos,g_pos);
    cudaGetSymbolAddress((void**)&attnf, g_attnf);
    cudaGetSymbolAddress((void**)&t1, d_t1);   cudaGetSymbolAddress((void**)&vsh, d_vshift);
    cudaGetSymbolAddress((void**)&tf, d_tfin);

    cudaFuncSetAttribute(tc<false,true ,false,true >, cudaFuncAttributeMaxDynamicSharedMemorySize, SMEMSZ);
    cudaFuncSetAttribute(tc<false,false,false,true >, cudaFuncAttributeMaxDynamicSharedMemorySize, SMEMSZ);
    cudaFuncSetAttribute(tc<true ,false,false,true >, cudaFuncAttributeMaxDynamicSharedMemorySize, SMEMSZ);
    cudaFuncSetAttribute(tc<false,false,true ,false>, cudaFuncAttributeMaxDynamicSharedMemorySize, SMEMSZ);
    cudaFuncSetAttribute(tc<true ,true ,true ,false>, cudaFuncAttributeMaxDynamicSharedMemorySize, SMEMSZ);

    // prep: convert weights/x once (fp16 hi/lo), fold BN
    k_convw<<<2048,256>>>(c1w, b1g, b1v, w1, 524288, 1024, 524288);
    k_convw<<<1024,256>>>(qw, nullptr, nullptr, wq, 262144, 512, 262144);
    k_convw<<<1024,256>>>(kw, nullptr, nullptr, wk, 262144, 512, 262144);
    k_convw<<<1024,256>>>(vw, b2g, b2v, wv, 262144, 512, 262144);     // BN2 scale folded
    k_convw<<<4096,256>>>(c3w, b3g, b3v, w3, 1048576, 512, 1048576);
    k_convw<<<8192,256>>>(scw, sg, sv, wsc, 2097152, 1024, 2097152);
    k_xt<<<dim3(32,8,64),dim3(32,8)>>>(x, xt);
    k_posT<<<512,256>>>(rh, rwv, pos);
    k_prepvec<<<8,256>>>(b1g,b1b,b1m,b1v, b2g,b2b,b2m,b2v,vbv, b3g,b3b,b3m,b3v,scb, sg,sb,smn,sv);

    // 1) out1[b][n][p] = xT·w1 + t1[col], ReLU
    tc<false,true,false,true><<<dim3(4,2,64),256,SMEMSZ>>>(
        xt,262144,0,1,1024,16777216,1024,  w1,0,0,1,1024,
        nullptr,0,0,1,0,0,0, nullptr,0,0,1,0,
        o1,131072,0,1,512,8388608, t1);
    // 2) q[b][n][p]
    tc<false,false,false,true><<<dim3(4,2,64),256,SMEMSZ>>>(
        o1,131072,0,1,512,8388608,512,  wq,0,0,1,512,
        nullptr,0,0,1,0,0,0, nullptr,0,0,1,0,
        q,131072,0,1,512,8388608, qbv);
    // 3) k[b][n][p]
    tc<false,false,false,true><<<dim3(4,2,64),256,SMEMSZ>>>(
        o1,131072,0,1,512,8388608,512,  wk,0,0,1,512,
        nullptr,0,0,1,0,0,0, nullptr,0,0,1,0,
        k,131072,0,1,512,8388608, kbv);
    // 4) v'[b][p][m] = (s2·wv)·out1 + vshift[row]
    tc<true,false,false,true><<<dim3(2,4,64),256,SMEMSZ>>>(
        wv,0,0,1,512,262144,512,  o1,131072,0,1,512,
        nullptr,0,0,1,0,0,0, nullptr,0,0,1,0,
        v,131072,0,1,256,8388608, vsh);
    // 5) logits[bh][n][m] = q·k + posT·q (two-phase)
    tc<false,false,true,false><<<dim3(2,2,256),256,SMEMSZ>>>(
        q,131072,128,4,512,8388608,128,  k,131072,128,4,512,
        pos,0,32768,4,128,131072,128,    q,131072,128,4,512,
        attnf,65536,0,1,256,0, nullptr);
    // 6) softmax -> attn fp16
    k_softmax<<<8192,256>>>(attnf, at);
    // 7) attout[b][n][h*128+d] = attn·v', ReLU
    tc<false,true,false,true><<<dim3(1,2,256),256,SMEMSZ>>>(
        at,65536,0,1,256,16777216,256,  v,131072,32768,4,256,
        nullptr,0,0,1,0,0,0, nullptr,0,0,1,0,
        ao,131072,128,4,512,8388608, nullptr);
    // 8) out[b][cout][n] = w3·attout + wsc·xT + tfin[row], ReLU
    tc<true,true,true,false><<<dim3(2,16,64),256,SMEMSZ>>>(
        w3,0,0,1,512,1048576,512,  ao,131072,0,1,512,
        wsc,0,0,1,1024,2097152,1024,  xt,262144,0,1,1024,
        d_out,524288,0,1,256,0, tf);
}

// round 9
// speedup vs baseline: 4.2521x; 1.3091x over previous
#include <cuda_runtime.h>
#include <cuda_fp16.h>
#include <math.h>
#include <stdint.h>
typedef __half hlf;

#define EPSBN 1e-5f
#define B_    64
#define CIN   1024
#define P_    512
#define COUT  2048
#define NSP   256
#define HEADS 4
#define DH    128

// ---------------- scratch: fp16 hi plane + lo plane (lo at +count) ----------------
__device__ __align__(16) hlf g_xt [2*16777216];  // xT[b][n][cin]
__device__ __align__(16) hlf g_w1 [2*524288];
__device__ __align__(16) hlf g_wq [2*262144];
__device__ __align__(16) hlf g_wk [2*262144];
__device__ __align__(16) hlf g_wv [2*262144];    // pre-scaled by BN2
__device__ __align__(16) hlf g_w3 [2*1048576];
__device__ __align__(16) hlf g_wsc[2*2097152];
__device__ __align__(16) hlf g_o1 [2*8388608];   // out1[b][n][p]
__device__ __align__(16) hlf g_q  [2*8388608];
__device__ __align__(16) hlf g_k  [2*8388608];
__device__ __align__(16) hlf g_v  [2*8388608];   // v'[b][p][m]
__device__ __align__(16) hlf g_ao [2*8388608];   // attout[b][n][p]
__device__ __align__(16) hlf g_at [16777216];    // attn fp16 [bh][n][m] (hi only)
__device__ __align__(16) hlf g_pos[2*131072];    // posT[h][n][d]
__device__ __align__(16) float g_attnf[16777216];
__device__ __align__(16) float d_t1[P_], d_vshift[P_], d_tfin[COUT];

// ---------------- helpers ----------------
__device__ __forceinline__ uint32_t su32(const void* p){uint32_t a;asm("{ .reg .u64 t; cvta.to.shared.u64 t, %1; cvt.u32.u64 %0, t; }":"=r"(a):"l"(p));return a;}
__device__ __forceinline__ void cp16(uint32_t d, const void* s){asm volatile("cp.async.cg.shared.global [%0], [%1], 16;"::"r"(d),"l"(s));}
__device__ __forceinline__ void spl(float v, hlf& h, hlf& l){h=__float2half(v); l=__float2half(v-__half2float(h));}
__device__ __forceinline__ uint32_t pk(hlf a, hlf b){return (uint32_t)__half_as_ushort(a)|((uint32_t)__half_as_ushort(b)<<16);}
__device__ __forceinline__ void mma16816(float* c, const uint32_t* a, const uint32_t* b){
    asm volatile("mma.sync.aligned.m16n8k16.row.col.f32.f16.f16.f32 "
        "{%0,%1,%2,%3},{%4,%5,%6,%7},{%8,%9},{%0,%1,%2,%3};"
        : "+f"(c[0]), "+f"(c[1]), "+f"(c[2]), "+f"(c[3])
        : "r"(a[0]), "r"(a[1]), "r"(a[2]), "r"(a[3]), "r"(b[0]), "r"(b[1]));
}
#define LDM4(r, a) asm volatile("ldmatrix.sync.aligned.m8n8.x4.shared.b16 {%0,%1,%2,%3}, [%4];" \
    : "=r"((r)[0]),"=r"((r)[1]),"=r"((r)[2]),"=r"((r)[3]) : "r"(a))
template<int N> __device__ __forceinline__ void cpwait(){
    asm volatile("cp.async.wait_group %0;"::"n"(N):"memory");
}

// ---------------- tensor-core GEMM: BM=BN=128, BK=32 ----------------
// planes per buffer: ASPLIT ? {Ah,Al,Bh} : {Ah,Bh}. plane = 128 rows x 80B.
#define PLANE 10240
#define SMEMSZ 61440

template<bool BIASROW, bool RELU, bool HAS2, bool OUTHF, bool ASPLIT>
__global__ void __launch_bounds__(256) tc(
  const hlf* __restrict__ A1, long aso1, long asi1, int adiv1, int lda1, long alod1, int K1,
  const hlf* __restrict__ B1, long bso1, long bsi1, int bdiv1, int ldb1,
  const hlf* __restrict__ A2, long aso2, long asi2, int adiv2, int lda2, long alod2, int K2,
  const hlf* __restrict__ B2, long bso2, long bsi2, int bdiv2, int ldb2,
  void* __restrict__ C, long cso, long csi, int cdiv, int ldc, long clod,
  const float* __restrict__ bias)
{
    constexpr int NPL = ASPLIT ? 3 : 2;
    constexpr uint32_t BUFSZ = NPL * PLANE;
    constexpr int NB = ASPLIT ? 2 : 3;     // pipeline depth
    extern __shared__ char sm[];
    const uint32_t sbase = su32(sm);
    const int tid = threadIdx.x;
    const int z = blockIdx.z, m0 = blockIdx.y*128, n0 = blockIdx.x*128;
    const int lane = tid&31, w = tid>>5;
    const int wm = w>>1, wn = w&1;
    const int qr = lane>>2, qk = lane&3;

    const uint32_t a_off = (uint32_t)(wm*32 + (lane&15))*80 + (uint32_t)(lane>>4)*16;
    const uint32_t b_off = (uint32_t)(wn*64 + (lane&7) + (lane>>4)*8)*80 + (uint32_t)((lane>>3)&1)*16;

    const hlf* pA1 = A1 + (long)(z/adiv1)*aso1 + (long)(z%adiv1)*asi1;
    const hlf* pB1 = B1 + (long)(z/bdiv1)*bso1 + (long)(z%bdiv1)*bsi1;
    const hlf* pA2 = HAS2 ? A2 + (long)(z/adiv2)*aso2 + (long)(z%adiv2)*asi2 : nullptr;
    const hlf* pB2 = HAS2 ? B2 + (long)(z/bdiv2)*bso2 + (long)(z%bdiv2)*bsi2 : nullptr;
    const int nst1 = K1/32, nst = nst1 + (HAS2 ? K2/32 : 0);

    float acc[2][8][4];
#pragma unroll
    for(int i=0;i<2;++i)
#pragma unroll
        for(int j=0;j<8;++j)
#pragma unroll
            for(int q=0;q<4;++q) acc[i][j][q]=0.0f;

    auto ld=[&](int c){
        const hlf *pa,*pb; int la,lb,k0; long al;
        if(!HAS2 || c<nst1){ pa=pA1; pb=pB1; la=lda1; lb=ldb1; al=alod1; k0=c*32; }
        else               { pa=pA2; pb=pB2; la=lda2; lb=ldb2; al=alod2; k0=(c-nst1)*32; }
        uint32_t sb = sbase + (uint32_t)(c%NB)*BUFSZ;
#pragma unroll
        for(int it=0;it<2;++it){
            int ch=tid+it*256, r=ch>>2, q=ch&3;
            const hlf* sa = pa + (long)(m0+r)*la + k0 + q*8;
            uint32_t da = sb + (uint32_t)r*80 + q*16;
            cp16(da, sa);
            if(ASPLIT) cp16(da+PLANE, sa+al);
            const hlf* sbp = pb + (long)(n0+r)*lb + k0 + q*8;
            cp16(da+(NPL-1)*PLANE, sbp);
        }
        asm volatile("cp.async.commit_group;":::"memory");
    };

    auto compute=[&](int buf){
        const uint32_t base = sbase + (uint32_t)buf*BUFSZ;
#pragma unroll
        for(int s=0;s<2;++s){
            uint32_t ah[2][4], al[2][4];
#pragma unroll
            for(int mi=0;mi<2;++mi){
                LDM4(ah[mi], base + a_off + mi*1280 + s*32);
                if(ASPLIT) LDM4(al[mi], base + PLANE + a_off + mi*1280 + s*32);
            }
#pragma unroll
            for(int nq=0;nq<4;++nq){
                uint32_t bh[4];
                LDM4(bh, base + (NPL-1)*PLANE + b_off + nq*1280 + s*32);
#pragma unroll
                for(int hf=0;hf<2;++hf){
                    int ni = nq*2 + hf;
#pragma unroll
                    for(int mi=0;mi<2;++mi){
                        mma16816(acc[mi][ni], ah[mi], bh + hf*2);
                        if(ASPLIT) mma16816(acc[mi][ni], al[mi], bh + hf*2);
                    }
                }
            }
        }
    };

    ld(0);
    if(nst>1) ld(1);
    if(NB>2 && nst>2) ld(2);
    for(int c=0;c<nst;++c){
        int rem = nst-c-1;
        if(rem >= NB-1) cpwait<NB-1>();
        else if(rem==1) cpwait<1>();
        else            cpwait<0>();
        __syncthreads();
        compute(c%NB);
        __syncthreads();
        if(c+NB<nst) ld(c+NB);
    }

    // ---------------- epilogue ----------------
    long cz = (long)(z/cdiv)*cso + (long)(z%cdiv)*csi;
#pragma unroll
    for(int mi=0;mi<2;++mi){
#pragma unroll
        for(int hf=0;hf<2;++hf){
            int row = m0 + wm*32 + mi*16 + qr + hf*8;
            float tr = (BIASROW && bias) ? __ldg(bias+row) : 0.0f;
#pragma unroll
            for(int ni=0;ni<8;++ni){
                int col = n0 + wn*64 + ni*8 + qk*2;
                float v0 = acc[mi][ni][hf*2], v1 = acc[mi][ni][hf*2+1];
                if(BIASROW){ v0 += tr; v1 += tr; }
                else if(bias){ v0 += __ldg(bias+col); v1 += __ldg(bias+col+1); }
                if(RELU){ v0 = fmaxf(v0,0.0f); v1 = fmaxf(v1,0.0f); }
                if(OUTHF){
                    hlf h0,l0,h1,l1; spl(v0,h0,l0); spl(v1,h1,l1);
                    hlf* Cb = (hlf*)C + cz + (long)row*ldc + col;
                    *(uint32_t*)Cb = pk(h0,h1);
                    *(uint32_t*)(Cb+clod) = pk(l0,l1);
                } else {
                    float2 f = {v0, v1};
                    *(float2*)((float*)C + cz + (long)row*ldc + col) = f;
                }
            }
        }
    }
}

// ---------------- prep kernels ----------------
__global__ void k_convw(const float* __restrict__ w, const float* __restrict__ g,
                        const float* __restrict__ vr, hlf* __restrict__ o, long lod, int K, int total){
    int i = blockIdx.x*256 + threadIdx.x; if(i>=total) return;
    float s = g ? g[i/K]*rsqrtf(vr[i/K]+EPSBN) : 1.0f;
    hlf h,l; spl(w[i]*s,h,l);
    o[i]=h; o[i+lod]=l;
}
__global__ void k_xt(const float* __restrict__ x, hlf* __restrict__ o){
    __shared__ float t[32][33];
    int c0=blockIdx.x*32, nn0=blockIdx.y*32, b=blockIdx.z, tx=threadIdx.x, ty=threadIdx.y;
#pragma unroll
    for(int i=0;i<4;++i) t[ty+i*8][tx] = x[((long)b*1024 + c0+ty+i*8)*256 + nn0+tx];
    __syncthreads();
    hlf* ob = o + (long)b*262144;
#pragma unroll
    for(int i=0;i<4;++i){
        hlf h,l; spl(t[tx][ty+i*8],h,l);
        long idx = (long)(nn0+ty+i*8)*1024 + c0+tx;
        ob[idx]=h; ob[idx+16777216]=l;
    }
}
__global__ void k_posT(const float* __restrict__ rh, const float* __restrict__ rw, hlf* __restrict__ o){
    int i = blockIdx.x*256 + threadIdx.x; if(i>=131072) return;
    int d = i&127, n = (i>>7)&255, h = i>>15;
    int hd = h*128+d;
    float v = rh[hd*16+(n&15)] + rw[hd*16+(n>>4)];
    hlf hh,ll; spl(v,hh,ll);
    o[i]=hh; o[i+131072]=ll;
}
__global__ void k_prepvec(const float* g1,const float* b1,const float* m1,const float* v1,
                          const float* g2,const float* b2,const float* m2,const float* v2,const float* vbv,
                          const float* g3,const float* b3,const float* m3,const float* v3,const float* scb,
                          const float* gs,const float* bs,const float* ms,const float* vs){
    int i = blockIdx.x*256 + threadIdx.x;
    if(i<P_){
        float s1=g1[i]*rsqrtf(v1[i]+EPSBN); d_t1[i]=b1[i]-m1[i]*s1;
        float s2=g2[i]*rsqrtf(v2[i]+EPSBN);
        d_vshift[i]=fmaf(vbv[i],s2,b2[i]-m2[i]*s2);     // BN2 folded into V
    }
    if(i<COUT){
        float s3=g3[i]*rsqrtf(v3[i]+EPSBN);
        float ss=gs[i]*rsqrtf(vs[i]+EPSBN);
        d_tfin[i]=(b3[i]-m3[i]*s3) + fmaf(scb[i]-ms[i],ss,bs[i]);
    }
}
__global__ void k_softmax(const float* __restrict__ a, hlf* __restrict__ o){
    int row = blockIdx.x*8 + (threadIdx.x>>5), lane = threadIdx.x&31;
    const float* rp = a + (long)row*256;
    float4 f0 = ((const float4*)rp)[lane*2], f1 = ((const float4*)rp)[lane*2+1];
    float v[8] = {f0.x,f0.y,f0.z,f0.w,f1.x,f1.y,f1.z,f1.w};
    float mx = -1e30f;
#pragma unroll
    for(int j=0;j<8;++j) mx = fmaxf(mx,v[j]);
#pragma unroll
    for(int s=16;s;s>>=1) mx = fmaxf(mx,__shfl_xor_sync(~0u,mx,s));
    float sum = 0;
#pragma unroll
    for(int j=0;j<8;++j){ v[j]=__expf(v[j]-mx); sum+=v[j]; }
#pragma unroll
    for(int s=16;s;s>>=1) sum += __shfl_xor_sync(~0u,sum,s);
    float inv = 1.0f/sum;
    uint32_t hw[4];
#pragma unroll
    for(int p=0;p<4;++p)
        hw[p] = pk(__float2half(v[2*p]*inv), __float2half(v[2*p+1]*inv));
    hlf* ob = o + (long)row*256 + lane*8;
    uint4 hq={hw[0],hw[1],hw[2],hw[3]};
    *(uint4*)ob = hq;
}

// ---------------- launch ----------------
extern "C" void kernel_launch(void* const* d_in, const int* in_sizes, int n_in,
                              void* d_out, int out_size) {
    const float *x=(const float*)d_in[0], *c1w=(const float*)d_in[1];
    const float *b1g=(const float*)d_in[2],*b1b=(const float*)d_in[3],*b1m=(const float*)d_in[4],*b1v=(const float*)d_in[5];
    const float *qw=(const float*)d_in[6],*qbv=(const float*)d_in[7],*kw=(const float*)d_in[8],*kbv=(const float*)d_in[9];
    const float *vw=(const float*)d_in[10],*vbv=(const float*)d_in[11],*rh=(const float*)d_in[12],*rwv=(const float*)d_in[13];
    const float *b2g=(const float*)d_in[14],*b2b=(const float*)d_in[15],*b2m=(const float*)d_in[16],*b2v=(const float*)d_in[17];
    const float *c3w=(const float*)d_in[18];
    const float *b3g=(const float*)d_in[19],*b3b=(const float*)d_in[20],*b3m=(const float*)d_in[21],*b3v=(const float*)d_in[22];
    const float *scw=(const float*)d_in[23],*scb=(const float*)d_in[24];
    const float *sg=(const float*)d_in[25],*sb=(const float*)d_in[26],*smn=(const float*)d_in[27],*sv=(const float*)d_in[28];

    hlf *xt,*w1,*wq,*wk,*wv,*w3,*wsc,*o1,*q,*k,*v,*ao,*at,*pos;
    float *attnf,*t1,*vsh,*tf;
    cudaGetSymbolAddress((void**)&xt, g_xt);   cudaGetSymbolAddress((void**)&w1, g_w1);
    cudaGetSymbolAddress((void**)&wq, g_wq);   cudaGetSymbolAddress((void**)&wk, g_wk);
    cudaGetSymbolAddress((void**)&wv, g_wv);   cudaGetSymbolAddress((void**)&w3, g_w3);
    cudaGetSymbolAddress((void**)&wsc,g_wsc);  cudaGetSymbolAddress((void**)&o1, g_o1);
    cudaGetSymbolAddress((void**)&q,  g_q);    cudaGetSymbolAddress((void**)&k,  g_k);
    cudaGetSymbolAddress((void**)&v,  g_v);    cudaGetSymbolAddress((void**)&ao, g_ao);
    cudaGetSymbolAddress((void**)&at, g_at);   cudaGetSymbolAddress((void**)&pos,g_pos);
    cudaGetSymbolAddress((void**)&attnf, g_attnf);
    cudaGetSymbolAddress((void**)&t1, d_t1);   cudaGetSymbolAddress((void**)&vsh, d_vshift);
    cudaGetSymbolAddress((void**)&tf, d_tfin);

    cudaFuncSetAttribute(tc<false,true ,false,true ,true >, cudaFuncAttributeMaxDynamicSharedMemorySize, SMEMSZ);
    cudaFuncSetAttribute(tc<false,false,false,true ,true >, cudaFuncAttributeMaxDynamicSharedMemorySize, SMEMSZ);
    cudaFuncSetAttribute(tc<true ,false,false,true ,true >, cudaFuncAttributeMaxDynamicSharedMemorySize, SMEMSZ);
    cudaFuncSetAttribute(tc<false,false,true ,false,true >, cudaFuncAttributeMaxDynamicSharedMemorySize, SMEMSZ);
    cudaFuncSetAttribute(tc<false,true ,false,true ,false>, cudaFuncAttributeMaxDynamicSharedMemorySize, SMEMSZ);
    cudaFuncSetAttribute(tc<true ,true ,true ,false,false>, cudaFuncAttributeMaxDynamicSharedMemorySize, SMEMSZ);

    // prep: convert weights/x once (fp16 hi/lo), fold BN
    k_convw<<<2048,256>>>(c1w, b1g, b1v, w1, 524288, 1024, 524288);
    k_convw<<<1024,256>>>(qw, nullptr, nullptr, wq, 262144, 512, 262144);
    k_convw<<<1024,256>>>(kw, nullptr, nullptr, wk, 262144, 512, 262144);
    k_convw<<<1024,256>>>(vw, b2g, b2v, wv, 262144, 512, 262144);     // BN2 scale folded
    k_convw<<<4096,256>>>(c3w, b3g, b3v, w3, 1048576, 512, 1048576);
    k_convw<<<8192,256>>>(scw, sg, sv, wsc, 2097152, 1024, 2097152);
    k_xt<<<dim3(32,8,64),dim3(32,8)>>>(x, xt);
    k_posT<<<512,256>>>(rh, rwv, pos);
    k_prepvec<<<8,256>>>(b1g,b1b,b1m,b1v, b2g,b2b,b2m,b2v,vbv, b3g,b3b,b3m,b3v,scb, sg,sb,smn,sv);

    // 1) out1[b][n][p] = xT·w1 + t1[col], ReLU   (A split)
    tc<false,true,false,true,true><<<dim3(4,2,64),256,SMEMSZ>>>(
        xt,262144,0,1,1024,16777216,1024,  w1,0,0,1,1024,
        nullptr,0,0,1,0,0,0, nullptr,0,0,1,0,
        o1,131072,0,1,512,8388608, t1);
    // 2) q[b][n][p]   (A split)
    tc<false,false,false,true,true><<<dim3(4,2,64),256,SMEMSZ>>>(
        o1,131072,0,1,512,8388608,512,  wq,0,0,1,512,
        nullptr,0,0,1,0,0,0, nullptr,0,0,1,0,
        q,131072,0,1,512,8388608, qbv);
    // 3) k[b][n][p]   (A split)
    tc<false,false,false,true,true><<<dim3(4,2,64),256,SMEMSZ>>>(
        o1,131072,0,1,512,8388608,512,  wk,0,0,1,512,
        nullptr,0,0,1,0,0,0, nullptr,0,0,1,0,
        k,131072,0,1,512,8388608, kbv);
    // 4) v'[b][p][m] = (s2·wv)·out1 + vshift[row]   (A split)
    tc<true,false,false,true,true><<<dim3(2,4,64),256,SMEMSZ>>>(
        wv,0,0,1,512,262144,512,  o1,131072,0,1,512,
        nullptr,0,0,1,0,0,0, nullptr,0,0,1,0,
        v,131072,0,1,256,8388608, vsh);
    // 5) logits[bh][n][m] = q·k + posT·q   (A split, two-phase)
    tc<false,false,true,false,true><<<dim3(2,2,256),256,SMEMSZ>>>(
        q,131072,128,4,512,8388608,128,  k,131072,128,4,512,
        pos,0,32768,4,128,131072,128,    q,131072,128,4,512,
        attnf,65536,0,1,256,0, nullptr);
    // 6) softmax -> attn fp16 (hi only)
    k_softmax<<<8192,256>>>(attnf, at);
    // 7) attout[b][n][h*128+d] = attn·v', ReLU   (A single)
    tc<false,true,false,true,false><<<dim3(1,2,256),256,SMEMSZ>>>(
        at,65536,0,1,256,0,256,  v,131072,32768,4,256,
        nullptr,0,0,1,0,0,0, nullptr,0,0,1,0,
        ao,131072,128,4,512,8388608, nullptr);
    // 8) out[b][cout][n] = w3·attout + wsc·xT + tfin[row], ReLU   (A single, two-phase)
    tc<true,true,true,false,false><<<dim3(2,16,64),256,SMEMSZ>>>(
        w3,0,0,1,512,0,512,  ao,131072,0,1,512,
        wsc,0,0,1,1024,0,1024,  xt,262144,0,1,1024,
        d_out,524288,0,1,256,0, tf);
}

// round 10
// speedup vs baseline: 4.7155x; 1.1090x over previous
#include <cuda_runtime.h>
#include <cuda_fp16.h>
#include <math.h>
#include <stdint.h>
typedef __half hlf;

#define EPSBN 1e-5f
#define B_    64
#define CIN   1024
#define P_    512
#define COUT  2048
#define NSP   256
#define HEADS 4
#define DH    128

// ---------------- scratch: fp16 hi plane + lo plane (lo at +count) ----------------
__device__ __align__(16) hlf g_xt [2*16777216];  // xT[b][n][cin]
__device__ __align__(16) hlf g_w1 [2*524288];
__device__ __align__(16) hlf g_wq [2*262144];
__device__ __align__(16) hlf g_wk [2*262144];
__device__ __align__(16) hlf g_wv [2*262144];    // pre-scaled by BN2
__device__ __align__(16) hlf g_w3 [2*1048576];
__device__ __align__(16) hlf g_wsc[2*2097152];
__device__ __align__(16) hlf g_o1 [2*8388608];   // out1[b][n][p]
__device__ __align__(16) hlf g_q  [2*8388608];   // q[b][n][p]
__device__ __align__(16) hlf g_k  [2*8388608];
__device__ __align__(16) hlf g_v  [2*8388608];   // v'[b][p][m]
__device__ __align__(16) hlf g_ao [2*8388608];   // attout[b][n][p]
__device__ __align__(16) hlf g_pos[2*131072];    // posT[h][n][d]
__device__ __align__(16) float d_t1[P_], d_vshift[P_], d_tfin[COUT];

// ---------------- helpers ----------------
__device__ __forceinline__ uint32_t su32(const void* p){uint32_t a;asm("{ .reg .u64 t; cvta.to.shared.u64 t, %1; cvt.u32.u64 %0, t; }":"=r"(a):"l"(p));return a;}
__device__ __forceinline__ void cp16(uint32_t d, const void* s){asm volatile("cp.async.cg.shared.global [%0], [%1], 16;"::"r"(d),"l"(s));}
__device__ __forceinline__ void spl(float v, hlf& h, hlf& l){h=__float2half(v); l=__float2half(v-__half2float(h));}
__device__ __forceinline__ uint32_t pk(hlf a, hlf b){return (uint32_t)__half_as_ushort(a)|((uint32_t)__half_as_ushort(b)<<16);}
__device__ __forceinline__ void mma16816(float* c, const uint32_t* a, const uint32_t* b){
    asm volatile("mma.sync.aligned.m16n8k16.row.col.f32.f16.f16.f32 "
        "{%0,%1,%2,%3},{%4,%5,%6,%7},{%8,%9},{%0,%1,%2,%3};"
        : "+f"(c[0]), "+f"(c[1]), "+f"(c[2]), "+f"(c[3])
        : "r"(a[0]), "r"(a[1]), "r"(a[2]), "r"(a[3]), "r"(b[0]), "r"(b[1]));
}
#define LDM4(r, a) asm volatile("ldmatrix.sync.aligned.m8n8.x4.shared.b16 {%0,%1,%2,%3}, [%4];" \
    : "=r"((r)[0]),"=r"((r)[1]),"=r"((r)[2]),"=r"((r)[3]) : "r"(a))
template<int N> __device__ __forceinline__ void cpwait(){
    asm volatile("cp.async.wait_group %0;"::"n"(N):"memory");
}

// ---------------- tensor-core GEMM: BM=BN=128, BK=32 ----------------
// planes per buffer: ASPLIT ? {Ah,Al,Bh} : {Ah,Bh}. plane = 128 rows x 80B.
#define PLANE 10240
#define SMEMSZ 61440

template<bool BIASROW, bool RELU, bool HAS2, bool OUTHF, bool ASPLIT>
__global__ void __launch_bounds__(256) tc(
  const hlf* __restrict__ A1, long aso1, long asi1, int adiv1, int lda1, long alod1, int K1,
  const hlf* __restrict__ B1, long bso1, long bsi1, int bdiv1, int ldb1,
  const hlf* __restrict__ A2, long aso2, long asi2, int adiv2, int lda2, long alod2, int K2,
  const hlf* __restrict__ B2, long bso2, long bsi2, int bdiv2, int ldb2,
  void* __restrict__ C, long cso, long csi, int cdiv, int ldc, long clod,
  const float* __restrict__ bias)
{
    constexpr int NPL = ASPLIT ? 3 : 2;
    constexpr uint32_t BUFSZ = NPL * PLANE;
    constexpr int NB = ASPLIT ? 2 : 3;
    extern __shared__ char sm[];
    const uint32_t sbase = su32(sm);
    const int tid = threadIdx.x;
    const int z = blockIdx.z, m0 = blockIdx.y*128, n0 = blockIdx.x*128;
    const int lane = tid&31, w = tid>>5;
    const int wm = w>>1, wn = w&1;
    const int qr = lane>>2, qk = lane&3;

    const uint32_t a_off = (uint32_t)(wm*32 + (lane&15))*80 + (uint32_t)(lane>>4)*16;
    const uint32_t b_off = (uint32_t)(wn*64 + (lane&7) + (lane>>4)*8)*80 + (uint32_t)((lane>>3)&1)*16;

    const hlf* pA1 = A1 + (long)(z/adiv1)*aso1 + (long)(z%adiv1)*asi1;
    const hlf* pB1 = B1 + (long)(z/bdiv1)*bso1 + (long)(z%bdiv1)*bsi1;
    const hlf* pA2 = HAS2 ? A2 + (long)(z/adiv2)*aso2 + (long)(z%adiv2)*asi2 : nullptr;
    const hlf* pB2 = HAS2 ? B2 + (long)(z/bdiv2)*bso2 + (long)(z%bdiv2)*bsi2 : nullptr;
    const int nst1 = K1/32, nst = nst1 + (HAS2 ? K2/32 : 0);

    float acc[2][8][4];
#pragma unroll
    for(int i=0;i<2;++i)
#pragma unroll
        for(int j=0;j<8;++j)
#pragma unroll
            for(int q=0;q<4;++q) acc[i][j][q]=0.0f;

    auto ld=[&](int c){
        const hlf *pa,*pb; int la,lb,k0; long al;
        if(!HAS2 || c<nst1){ pa=pA1; pb=pB1; la=lda1; lb=ldb1; al=alod1; k0=c*32; }
        else               { pa=pA2; pb=pB2; la=lda2; lb=ldb2; al=alod2; k0=(c-nst1)*32; }
        uint32_t sb = sbase + (uint32_t)(c%NB)*BUFSZ;
#pragma unroll
        for(int it=0;it<2;++it){
            int ch=tid+it*256, r=ch>>2, q=ch&3;
            const hlf* sa = pa + (long)(m0+r)*la + k0 + q*8;
            uint32_t da = sb + (uint32_t)r*80 + q*16;
            cp16(da, sa);
            if(ASPLIT) cp16(da+PLANE, sa+al);
            const hlf* sbp = pb + (long)(n0+r)*lb + k0 + q*8;
            cp16(da+(NPL-1)*PLANE, sbp);
        }
        asm volatile("cp.async.commit_group;":::"memory");
    };

    auto compute=[&](int buf){
        const uint32_t base = sbase + (uint32_t)buf*BUFSZ;
#pragma unroll
        for(int s=0;s<2;++s){
            uint32_t ah[2][4], al[2][4];
#pragma unroll
            for(int mi=0;mi<2;++mi){
                LDM4(ah[mi], base + a_off + mi*1280 + s*32);
                if(ASPLIT) LDM4(al[mi], base + PLANE + a_off + mi*1280 + s*32);
            }
#pragma unroll
            for(int nq=0;nq<4;++nq){
                uint32_t bh[4];
                LDM4(bh, base + (NPL-1)*PLANE + b_off + nq*1280 + s*32);
#pragma unroll
                for(int hf=0;hf<2;++hf){
                    int ni = nq*2 + hf;
#pragma unroll
                    for(int mi=0;mi<2;++mi){
                        mma16816(acc[mi][ni], ah[mi], bh + hf*2);
                        if(ASPLIT) mma16816(acc[mi][ni], al[mi], bh + hf*2);
                    }
                }
            }
        }
    };

    ld(0);
    if(nst>1) ld(1);
    if(NB>2 && nst>2) ld(2);
    for(int c=0;c<nst;++c){
        int rem = nst-c-1;
        if(rem >= NB-1) cpwait<NB-1>();
        else if(rem==1) cpwait<1>();
        else            cpwait<0>();
        __syncthreads();
        compute(c%NB);
        __syncthreads();
        if(c+NB<nst) ld(c+NB);
    }

    long cz = (long)(z/cdiv)*cso + (long)(z%cdiv)*csi;
#pragma unroll
    for(int mi=0;mi<2;++mi){
#pragma unroll
        for(int hf=0;hf<2;++hf){
            int row = m0 + wm*32 + mi*16 + qr + hf*8;
            float tr = (BIASROW && bias) ? __ldg(bias+row) : 0.0f;
#pragma unroll
            for(int ni=0;ni<8;++ni){
                int col = n0 + wn*64 + ni*8 + qk*2;
                float v0 = acc[mi][ni][hf*2], v1 = acc[mi][ni][hf*2+1];
                if(BIASROW){ v0 += tr; v1 += tr; }
                else if(bias){ v0 += __ldg(bias+col); v1 += __ldg(bias+col+1); }
                if(RELU){ v0 = fmaxf(v0,0.0f); v1 = fmaxf(v1,0.0f); }
                if(OUTHF){
                    hlf h0,l0,h1,l1; spl(v0,h0,l0); spl(v1,h1,l1);
                    hlf* Cb = (hlf*)C + cz + (long)row*ldc + col;
                    *(uint32_t*)Cb = pk(h0,h1);
                    *(uint32_t*)(Cb+clod) = pk(l0,l1);
                } else {
                    float2 f = {v0, v1};
                    *(float2*)((float*)C + cz + (long)row*ldc + col) = f;
                }
            }
        }
    }
}

// ---------------- fused attention: logits + softmax + attn·V ----------------
// grid (2, 256): blockIdx.x -> row half m0, blockIdx.y -> z = b*4+h.
// smem: [0,61440) A/B pipeline (2 bufs x {A 10240, B 20480});
//       [61440,129024) V 128x528B; [129024,196608) P 128x528B; [196608,+1024) red.
#define FA_OV 61440
#define FA_OP 129024
#define FA_OR 196608
#define FA_SMEM 197632

__global__ void __launch_bounds__(256) fattn(
  const hlf* __restrict__ Q, const hlf* __restrict__ K,
  const hlf* __restrict__ POS, const hlf* __restrict__ V,
  hlf* __restrict__ AO)
{
    extern __shared__ char sm[];
    const uint32_t sbase = su32(sm);
    const int tid=threadIdx.x, lane=tid&31, w=tid>>5, wm=w>>1, wn=w&1;
    const int qr=lane>>2, qk=lane&3;
    const int m0 = blockIdx.x*128;
    const int z = blockIdx.y, b = z>>2, h = z&3;

    const hlf* pq = Q + (long)b*131072;
    const hlf* pkk = K + (long)b*131072;
    const hlf* pp = POS + (long)h*32768;
    const hlf* pv = V + (long)b*131072 + (long)h*128*256;

    const uint32_t a_off = (uint32_t)(wm*32+(lane&15))*80 + (uint32_t)(lane>>4)*16;
    const uint32_t b_off = (uint32_t)((lane&7)+((lane>>4)<<3))*80 + (uint32_t)((lane>>3)&1)*16;

    auto ldA=[&](int c){
        uint32_t sb = sbase + (uint32_t)(c&1)*30720;
        const hlf *pa, *pb; int la;
        if(c<4){ pa = pq + (long)m0*512 + h*128 + c*32; la=512; pb = pkk + h*128 + c*32; }
        else   { pa = pp + (long)m0*128 + (c-4)*32;     la=128; pb = pq  + h*128 + (c-4)*32; }
#pragma unroll
        for(int it=0;it<2;++it){
            int ch=tid+it*256, r=ch>>2, q2=ch&3;
            cp16(sb + (uint32_t)r*80 + q2*16, pa + (long)r*la + q2*8);
        }
#pragma unroll
        for(int it=0;it<4;++it){
            int ch=tid+it*256, r=ch>>2, q2=ch&3;
            cp16(sb + 10240 + (uint32_t)r*80 + q2*16, pb + (long)r*512 + q2*8);
        }
        asm volatile("cp.async.commit_group;":::"memory");
    };

    // V load joins group 0
#pragma unroll
    for(int it=0;it<16;++it){
        int ch = tid + it*256;
        int r = ch>>5, cq = ch&31;
        cp16(sbase + FA_OV + (uint32_t)r*528 + cq*16, pv + (long)r*256 + cq*8);
    }
    ldA(0); ldA(1);

    float acc[2][16][4];
#pragma unroll
    for(int i=0;i<2;++i)
#pragma unroll
        for(int j=0;j<16;++j)
#pragma unroll
            for(int q=0;q<4;++q) acc[i][j][q]=0.0f;

    for(int c=0;c<8;++c){
        if(c<7) cpwait<1>(); else cpwait<0>();
        __syncthreads();
        const uint32_t base = sbase + (uint32_t)(c&1)*30720;
#pragma unroll
        for(int s=0;s<2;++s){
            uint32_t ah[2][4];
#pragma unroll
            for(int mi=0;mi<2;++mi) LDM4(ah[mi], base + a_off + mi*1280 + s*32);
#pragma unroll
            for(int nq=0;nq<8;++nq){
                uint32_t bh[4];
                LDM4(bh, base + 10240 + (uint32_t)wn*10240 + nq*1280 + b_off + s*32);
#pragma unroll
                for(int hf=0;hf<2;++hf){
                    int ni = nq*2+hf;
#pragma unroll
                    for(int mi=0;mi<2;++mi) mma16816(acc[mi][ni], ah[mi], bh+hf*2);
                }
            }
        }
        __syncthreads();
        if(c+2<8) ldA(c+2);
    }

    // ---- softmax over rows (256 cols split across wn pairs) ----
    float* red = (float*)(sm + FA_OR);
    float mxv[2][2], inv[2][2];
#pragma unroll
    for(int mi=0;mi<2;++mi)
#pragma unroll
    for(int hf=0;hf<2;++hf){
        float m = -1e30f;
#pragma unroll
        for(int ni=0;ni<16;++ni){ m=fmaxf(m,acc[mi][ni][hf*2]); m=fmaxf(m,acc[mi][ni][hf*2+1]); }
        m = fmaxf(m, __shfl_xor_sync(~0u,m,1));
        m = fmaxf(m, __shfl_xor_sync(~0u,m,2));
        if(qk==0) red[(wm*32+mi*16+hf*8+qr)*2+wn] = m;
    }
    __syncthreads();
#pragma unroll
    for(int mi=0;mi<2;++mi)
#pragma unroll
    for(int hf=0;hf<2;++hf){
        int r = wm*32+mi*16+hf*8+qr;
        mxv[mi][hf] = fmaxf(red[r*2], red[r*2+1]);
    }
    __syncthreads();
#pragma unroll
    for(int mi=0;mi<2;++mi)
#pragma unroll
    for(int hf=0;hf<2;++hf){
        float s = 0.0f;
#pragma unroll
        for(int ni=0;ni<16;++ni){
            float e0=__expf(acc[mi][ni][hf*2]  -mxv[mi][hf]);
            float e1=__expf(acc[mi][ni][hf*2+1]-mxv[mi][hf]);
            acc[mi][ni][hf*2]=e0; acc[mi][ni][hf*2+1]=e1; s+=e0+e1;
        }
        s += __shfl_xor_sync(~0u,s,1);
        s += __shfl_xor_sync(~0u,s,2);
        if(qk==0) red[(wm*32+mi*16+hf*8+qr)*2+wn] = s;
    }
    __syncthreads();
#pragma unroll
    for(int mi=0;mi<2;++mi)
#pragma unroll
    for(int hf=0;hf<2;++hf){
        int r = wm*32+mi*16+hf*8+qr;
        inv[mi][hf] = 1.0f/(red[r*2]+red[r*2+1]);
    }
    // write P (fp16) to smem
#pragma unroll
    for(int mi=0;mi<2;++mi)
#pragma unroll
    for(int hf=0;hf<2;++hf){
        int r = wm*32+mi*16+hf*8+qr;
#pragma unroll
        for(int ni=0;ni<16;++ni){
            int col = wn*128+ni*8+qk*2;
            uint32_t p2 = pk(__float2half(acc[mi][ni][hf*2]  *inv[mi][hf]),
                             __float2half(acc[mi][ni][hf*2+1]*inv[mi][hf]));
            *(uint32_t*)(sm + FA_OP + (uint32_t)r*528 + col*2) = p2;
        }
    }
    __syncthreads();

    // ---- phase B: out[n][d] = P·V^T (k = m, 256) ----
    float ao_acc[2][8][4];
#pragma unroll
    for(int i=0;i<2;++i)
#pragma unroll
        for(int j=0;j<8;++j)
#pragma unroll
            for(int q=0;q<4;++q) ao_acc[i][j][q]=0.0f;

    const uint32_t pa2 = (uint32_t)(wm*32+(lane&15))*528 + (uint32_t)(lane>>4)*16;
    const uint32_t vb2 = (uint32_t)(wn*64+(lane&7)+((lane>>4)<<3))*528 + (uint32_t)((lane>>3)&1)*16;
#pragma unroll 2
    for(int ks=0;ks<16;++ks){
        uint32_t ap[2][4];
#pragma unroll
        for(int mi=0;mi<2;++mi) LDM4(ap[mi], sbase + FA_OP + pa2 + mi*(16*528) + ks*32);
#pragma unroll
        for(int dq=0;dq<4;++dq){
            uint32_t bv[4];
            LDM4(bv, sbase + FA_OV + vb2 + dq*(16*528) + ks*32);
#pragma unroll
            for(int hf=0;hf<2;++hf){
                int ni = dq*2+hf;
#pragma unroll
                for(int mi=0;mi<2;++mi) mma16816(ao_acc[mi][ni], ap[mi], bv+hf*2);
            }
        }
    }

    hlf* po = AO + (long)b*131072 + h*128;
#pragma unroll
    for(int mi=0;mi<2;++mi)
#pragma unroll
    for(int hf=0;hf<2;++hf){
        int row = m0 + wm*32+mi*16+hf*8+qr;
#pragma unroll
        for(int ni=0;ni<8;++ni){
            int d = wn*64+ni*8+qk*2;
            float v0=fmaxf(ao_acc[mi][ni][hf*2],0.f), v1=fmaxf(ao_acc[mi][ni][hf*2+1],0.f);
            *(uint32_t*)(po + (long)row*512 + d) = pk(__float2half(v0), __float2half(v1));
        }
    }
}

// ---------------- prep kernels ----------------
__global__ void k_convw(const float* __restrict__ w, const float* __restrict__ g,
                        const float* __restrict__ vr, hlf* __restrict__ o, long lod, int K, int total){
    int i = blockIdx.x*256 + threadIdx.x; if(i>=total) return;
    float s = g ? g[i/K]*rsqrtf(vr[i/K]+EPSBN) : 1.0f;
    hlf h,l; spl(w[i]*s,h,l);
    o[i]=h; o[i+lod]=l;
}
__global__ void k_xt(const float* __restrict__ x, hlf* __restrict__ o){
    __shared__ float t[32][33];
    int c0=blockIdx.x*32, nn0=blockIdx.y*32, b=blockIdx.z, tx=threadIdx.x, ty=threadIdx.y;
#pragma unroll
    for(int i=0;i<4;++i) t[ty+i*8][tx] = x[((long)b*1024 + c0+ty+i*8)*256 + nn0+tx];
    __syncthreads();
    hlf* ob = o + (long)b*262144;
#pragma unroll
    for(int i=0;i<4;++i){
        hlf h,l; spl(t[tx][ty+i*8],h,l);
        long idx = (long)(nn0+ty+i*8)*1024 + c0+tx;
        ob[idx]=h; ob[idx+16777216]=l;
    }
}
__global__ void k_posT(const float* __restrict__ rh, const float* __restrict__ rw, hlf* __restrict__ o){
    int i = blockIdx.x*256 + threadIdx.x; if(i>=131072) return;
    int d = i&127, n = (i>>7)&255, h = i>>15;
    int hd = h*128+d;
    float v = rh[hd*16+(n&15)] + rw[hd*16+(n>>4)];
    hlf hh,ll; spl(v,hh,ll);
    o[i]=hh; o[i+131072]=ll;
}
__global__ void k_prepvec(const float* g1,const float* b1,const float* m1,const float* v1,
                          const float* g2,const float* b2,const float* m2,const float* v2,const float* vbv,
                          const float* g3,const float* b3,const float* m3,const float* v3,const float* scb,
                          const float* gs,const float* bs,const float* ms,const float* vs){
    int i = blockIdx.x*256 + threadIdx.x;
    if(i<P_){
        float s1=g1[i]*rsqrtf(v1[i]+EPSBN); d_t1[i]=b1[i]-m1[i]*s1;
        float s2=g2[i]*rsqrtf(v2[i]+EPSBN);
        d_vshift[i]=fmaf(vbv[i],s2,b2[i]-m2[i]*s2);
    }
    if(i<COUT){
        float s3=g3[i]*rsqrtf(v3[i]+EPSBN);
        float ss=gs[i]*rsqrtf(vs[i]+EPSBN);
        d_tfin[i]=(b3[i]-m3[i]*s3) + fmaf(scb[i]-ms[i],ss,bs[i]);
    }
}

// ---------------- launch ----------------
extern "C" void kernel_launch(void* const* d_in, const int* in_sizes, int n_in,
                              void* d_out, int out_size) {
    const float *x=(const float*)d_in[0], *c1w=(const float*)d_in[1];
    const float *b1g=(const float*)d_in[2],*b1b=(const float*)d_in[3],*b1m=(const float*)d_in[4],*b1v=(const float*)d_in[5];
    const float *qw=(const float*)d_in[6],*qbv=(const float*)d_in[7],*kw=(const float*)d_in[8],*kbv=(const float*)d_in[9];
    const float *vw=(const float*)d_in[10],*vbv=(const float*)d_in[11],*rh=(const float*)d_in[12],*rwv=(const float*)d_in[13];
    const float *b2g=(const float*)d_in[14],*b2b=(const float*)d_in[15],*b2m=(const float*)d_in[16],*b2v=(const float*)d_in[17];
    const float *c3w=(const float*)d_in[18];
    const float *b3g=(const float*)d_in[19],*b3b=(const float*)d_in[20],*b3m=(const float*)d_in[21],*b3v=(const float*)d_in[22];
    const float *scw=(const float*)d_in[23],*scb=(const float*)d_in[24];
    const float *sg=(const float*)d_in[25],*sb=(const float*)d_in[26],*smn=(const float*)d_in[27],*sv=(const float*)d_in[28];

    hlf *xt,*w1,*wq,*wk,*wv,*w3,*wsc,*o1,*q,*k,*v,*ao,*pos;
    float *t1,*vsh,*tf;
    cudaGetSymbolAddress((void**)&xt, g_xt);   cudaGetSymbolAddress((void**)&w1, g_w1);
    cudaGetSymbolAddress((void**)&wq, g_wq);   cudaGetSymbolAddress((void**)&wk, g_wk);
    cudaGetSymbolAddress((void**)&wv, g_wv);   cudaGetSymbolAddress((void**)&w3, g_w3);
    cudaGetSymbolAddress((void**)&wsc,g_wsc);  cudaGetSymbolAddress((void**)&o1, g_o1);
    cudaGetSymbolAddress((void**)&q,  g_q);    cudaGetSymbolAddress((void**)&k,  g_k);
    cudaGetSymbolAddress((void**)&v,  g_v);    cudaGetSymbolAddress((void**)&ao, g_ao);
    cudaGetSymbolAddress((void**)&pos,g_pos);
    cudaGetSymbolAddress((void**)&t1, d_t1);   cudaGetSymbolAddress((void**)&vsh, d_vshift);
    cudaGetSymbolAddress((void**)&tf, d_tfin);

    cudaFuncSetAttribute(tc<false,true ,false,true ,true >, cudaFuncAttributeMaxDynamicSharedMemorySize, SMEMSZ);
    cudaFuncSetAttribute(tc<false,false,false,true ,false>, cudaFuncAttributeMaxDynamicSharedMemorySize, SMEMSZ);
    cudaFuncSetAttribute(tc<true ,false,false,true ,true >, cudaFuncAttributeMaxDynamicSharedMemorySize, SMEMSZ);
    cudaFuncSetAttribute(tc<true ,true ,true ,false,false>, cudaFuncAttributeMaxDynamicSharedMemorySize, SMEMSZ);
    cudaFuncSetAttribute(fattn, cudaFuncAttributeMaxDynamicSharedMemorySize, FA_SMEM);

    // prep: convert weights/x once (fp16 hi/lo), fold BN
    k_convw<<<2048,256>>>(c1w, b1g, b1v, w1, 524288, 1024, 524288);
    k_convw<<<1024,256>>>(qw, nullptr, nullptr, wq, 262144, 512, 262144);
    k_convw<<<1024,256>>>(kw, nullptr, nullptr, wk, 262144, 512, 262144);
    k_convw<<<1024,256>>>(vw, b2g, b2v, wv, 262144, 512, 262144);
    k_convw<<<4096,256>>>(c3w, b3g, b3v, w3, 1048576, 512, 1048576);
    k_convw<<<8192,256>>>(scw, sg, sv, wsc, 2097152, 1024, 2097152);
    k_xt<<<dim3(32,8,64),dim3(32,8)>>>(x, xt);
    k_posT<<<512,256>>>(rh, rwv, pos);
    k_prepvec<<<8,256>>>(b1g,b1b,b1m,b1v, b2g,b2b,b2m,b2v,vbv, b3g,b3b,b3m,b3v,scb, sg,sb,smn,sv);

    // 1) out1[b][n][p] = xT·w1 + t1[col], ReLU   (A split)
    tc<false,true,false,true,true><<<dim3(4,2,64),256,SMEMSZ>>>(
        xt,262144,0,1,1024,16777216,1024,  w1,0,0,1,1024,
        nullptr,0,0,1,0,0,0, nullptr,0,0,1,0,
        o1,131072,0,1,512,8388608, t1);
    // 2) q[b][n][p]   (single)
    tc<false,false,false,true,false><<<dim3(4,2,64),256,SMEMSZ>>>(
        o1,131072,0,1,512,0,512,  wq,0,0,1,512,
        nullptr,0,0,1,0,0,0, nullptr,0,0,1,0,
        q,131072,0,1,512,8388608, qbv);
    // 3) k[b][n][p]   (single)
    tc<false,false,false,true,false><<<dim3(4,2,64),256,SMEMSZ>>>(
        o1,131072,0,1,512,0,512,  wk,0,0,1,512,
        nullptr,0,0,1,0,0,0, nullptr,0,0,1,0,
        k,131072,0,1,512,8388608, kbv);
    // 4) v'[b][p][m] = (s2·wv)·out1 + vshift[row]   (A split)
    tc<true,false,false,true,true><<<dim3(2,4,64),256,SMEMSZ>>>(
        wv,0,0,1,512,262144,512,  o1,131072,0,1,512,
        nullptr,0,0,1,0,0,0, nullptr,0,0,1,0,
        v,131072,0,1,256,8388608, vsh);
    // 5-7) fused attention: logits (q·k + pos·q) -> softmax -> P·V^T, ReLU
    fattn<<<dim3(2,256),256,FA_SMEM>>>(q, k, pos, v, ao);
    // 8) out[b][cout][n] = w3·attout + wsc·xT + tfin[row], ReLU   (single, two-phase)
    tc<true,true,true,false,false><<<dim3(2,16,64),256,SMEMSZ>>>(
        w3,0,0,1,512,0,512,  ao,131072,0,1,512,
        wsc,0,0,1,1024,0,1024,  xt,262144,0,1,1024,
        d_out,524288,0,1,256,0, tf);
}

// round 11
// speedup vs baseline: 5.4425x; 1.1542x over previous
#include <cuda_runtime.h>
#include <cuda_fp16.h>
#include <math.h>
#include <stdint.h>
typedef __half hlf;

#define EPSBN 1e-5f
#define B_    64
#define CIN   1024
#define P_    512
#define COUT  2048
#define NSP   256
#define HEADS 4
#define DH    128

// ---------------- scratch (fp16, single plane) ----------------
__device__ __align__(16) hlf g_xt [16777216];  // xT[b][n][cin]
__device__ __align__(16) hlf g_w1 [524288];
__device__ __align__(16) hlf g_wq [262144];
__device__ __align__(16) hlf g_wk [262144];
__device__ __align__(16) hlf g_wv [262144];    // pre-scaled by BN2
__device__ __align__(16) hlf g_w3 [1048576];
__device__ __align__(16) hlf g_wsc[2097152];
__device__ __align__(16) hlf g_o1 [8388608];   // out1[b][n][p]
__device__ __align__(16) hlf g_q  [8388608];   // q[b][n][p]
__device__ __align__(16) hlf g_k  [8388608];
__device__ __align__(16) hlf g_v  [8388608];   // v'[b][p][m]
__device__ __align__(16) hlf g_ao [8388608];   // attout[b][n][p]
__device__ __align__(16) hlf g_pos[131072];    // posT[h][n][d]
__device__ __align__(16) float d_t1[P_], d_vshift[P_], d_tfin[COUT];

// ---------------- helpers ----------------
__device__ __forceinline__ uint32_t su32(const void* p){uint32_t a;asm("{ .reg .u64 t; cvta.to.shared.u64 t, %1; cvt.u32.u64 %0, t; }":"=r"(a):"l"(p));return a;}
__device__ __forceinline__ void cp16(uint32_t d, const void* s){asm volatile("cp.async.cg.shared.global [%0], [%1], 16;"::"r"(d),"l"(s));}
__device__ __forceinline__ uint32_t pk(hlf a, hlf b){return (uint32_t)__half_as_ushort(a)|((uint32_t)__half_as_ushort(b)<<16);}
__device__ __forceinline__ void mma16816(float* c, const uint32_t* a, const uint32_t* b){
    asm volatile("mma.sync.aligned.m16n8k16.row.col.f32.f16.f16.f32 "
        "{%0,%1,%2,%3},{%4,%5,%6,%7},{%8,%9},{%0,%1,%2,%3};"
        : "+f"(c[0]), "+f"(c[1]), "+f"(c[2]), "+f"(c[3])
        : "r"(a[0]), "r"(a[1]), "r"(a[2]), "r"(a[3]), "r"(b[0]), "r"(b[1]));
}
#define LDM4(r, a) asm volatile("ldmatrix.sync.aligned.m8n8.x4.shared.b16 {%0,%1,%2,%3}, [%4];" \
    : "=r"((r)[0]),"=r"((r)[1]),"=r"((r)[2]),"=r"((r)[3]) : "r"(a))
template<int N> __device__ __forceinline__ void cpwait(){
    asm volatile("cp.async.wait_group %0;"::"n"(N):"memory");
}

// ---------------- tensor-core GEMM: BM=BN=128, BK=32, 3-stage pipeline ----------------
// planes per buffer: {A, B}. plane = 128 rows x 80B.
#define PLANE 10240
#define BUFSZ 20480
#define SMEMSZ 61440

template<bool BIASROW, bool RELU, bool HAS2, bool OUTHF>
__global__ void __launch_bounds__(256) tc(
  const hlf* __restrict__ A1, long aso1, long asi1, int adiv1, int lda1, int K1,
  const hlf* __restrict__ B1, long bso1, long bsi1, int bdiv1, int ldb1,
  const hlf* __restrict__ A2, long aso2, long asi2, int adiv2, int lda2, int K2,
  const hlf* __restrict__ B2, long bso2, long bsi2, int bdiv2, int ldb2,
  void* __restrict__ C, long cso, long csi, int cdiv, int ldc,
  const float* __restrict__ bias)
{
    extern __shared__ char sm[];
    const uint32_t sbase = su32(sm);
    const int tid = threadIdx.x;
    const int z = blockIdx.z, m0 = blockIdx.y*128, n0 = blockIdx.x*128;
    const int lane = tid&31, w = tid>>5;
    const int wm = w>>1, wn = w&1;
    const int qr = lane>>2, qk = lane&3;

    const uint32_t a_off = (uint32_t)(wm*32 + (lane&15))*80 + (uint32_t)(lane>>4)*16;
    const uint32_t b_off = (uint32_t)(wn*64 + (lane&7) + (lane>>4)*8)*80 + (uint32_t)((lane>>3)&1)*16;

    const hlf* pA1 = A1 + (long)(z/adiv1)*aso1 + (long)(z%adiv1)*asi1;
    const hlf* pB1 = B1 + (long)(z/bdiv1)*bso1 + (long)(z%bdiv1)*bsi1;
    const hlf* pA2 = HAS2 ? A2 + (long)(z/adiv2)*aso2 + (long)(z%adiv2)*asi2 : nullptr;
    const hlf* pB2 = HAS2 ? B2 + (long)(z/bdiv2)*bso2 + (long)(z%bdiv2)*bsi2 : nullptr;
    const int nst1 = K1/32, nst = nst1 + (HAS2 ? K2/32 : 0);

    float acc[2][8][4];
#pragma unroll
    for(int i=0;i<2;++i)
#pragma unroll
        for(int j=0;j<8;++j)
#pragma unroll
            for(int q=0;q<4;++q) acc[i][j][q]=0.0f;

    auto ld=[&](int c){
        const hlf *pa,*pb; int la,lb,k0;
        if(!HAS2 || c<nst1){ pa=pA1; pb=pB1; la=lda1; lb=ldb1; k0=c*32; }
        else               { pa=pA2; pb=pB2; la=lda2; lb=ldb2; k0=(c-nst1)*32; }
        uint32_t sb = sbase + (uint32_t)(c%3)*BUFSZ;
#pragma unroll
        for(int it=0;it<2;++it){
            int ch=tid+it*256, r=ch>>2, q=ch&3;
            uint32_t da = sb + (uint32_t)r*80 + q*16;
            cp16(da, pa + (long)(m0+r)*la + k0 + q*8);
            cp16(da+PLANE, pb + (long)(n0+r)*lb + k0 + q*8);
        }
        asm volatile("cp.async.commit_group;":::"memory");
    };

    auto compute=[&](int buf){
        const uint32_t base = sbase + (uint32_t)buf*BUFSZ;
#pragma unroll
        for(int s=0;s<2;++s){
            uint32_t ah[2][4];
#pragma unroll
            for(int mi=0;mi<2;++mi) LDM4(ah[mi], base + a_off + mi*1280 + s*32);
#pragma unroll
            for(int nq=0;nq<4;++nq){
                uint32_t bh[4];
                LDM4(bh, base + PLANE + b_off + nq*1280 + s*32);
#pragma unroll
                for(int hf=0;hf<2;++hf){
                    int ni = nq*2 + hf;
#pragma unroll
                    for(int mi=0;mi<2;++mi) mma16816(acc[mi][ni], ah[mi], bh + hf*2);
                }
            }
        }
    };

    ld(0);
    if(nst>1) ld(1);
    if(nst>2) ld(2);
    for(int c=0;c<nst;++c){
        int rem = nst-c-1;
        if(rem >= 2)    cpwait<2>();
        else if(rem==1) cpwait<1>();
        else            cpwait<0>();
        __syncthreads();
        compute(c%3);
        __syncthreads();
        if(c+3<nst) ld(c+3);
    }

    long cz = (long)(z/cdiv)*cso + (long)(z%cdiv)*csi;
#pragma unroll
    for(int mi=0;mi<2;++mi){
#pragma unroll
        for(int hf=0;hf<2;++hf){
            int row = m0 + wm*32 + mi*16 + qr + hf*8;
            float tr = (BIASROW && bias) ? __ldg(bias+row) : 0.0f;
#pragma unroll
            for(int ni=0;ni<8;++ni){
                int col = n0 + wn*64 + ni*8 + qk*2;
                float v0 = acc[mi][ni][hf*2], v1 = acc[mi][ni][hf*2+1];
                if(BIASROW){ v0 += tr; v1 += tr; }
                else if(bias){ v0 += __ldg(bias+col); v1 += __ldg(bias+col+1); }
                if(RELU){ v0 = fmaxf(v0,0.0f); v1 = fmaxf(v1,0.0f); }
                if(OUTHF){
                    hlf* Cb = (hlf*)C + cz + (long)row*ldc + col;
                    *(uint32_t*)Cb = pk(__float2half(v0), __float2half(v1));
                } else {
                    float2 f = {v0, v1};
                    *(float2*)((float*)C + cz + (long)row*ldc + col) = f;
                }
            }
        }
    }
}

// ---------------- fused attention: logits + softmax + attn·V ----------------
#define FA_OV 61440
#define FA_OP 129024
#define FA_OR 196608
#define FA_SMEM 197632

__global__ void __launch_bounds__(256) fattn(
  const hlf* __restrict__ Q, const hlf* __restrict__ K,
  const hlf* __restrict__ POS, const hlf* __restrict__ V,
  hlf* __restrict__ AO)
{
    extern __shared__ char sm[];
    const uint32_t sbase = su32(sm);
    const int tid=threadIdx.x, lane=tid&31, w=tid>>5, wm=w>>1, wn=w&1;
    const int qr=lane>>2, qk=lane&3;
    const int m0 = blockIdx.x*128;
    const int z = blockIdx.y, b = z>>2, h = z&3;

    const hlf* pq = Q + (long)b*131072;
    const hlf* pkk = K + (long)b*131072;
    const hlf* pp = POS + (long)h*32768;
    const hlf* pv = V + (long)b*131072 + (long)h*128*256;

    const uint32_t a_off = (uint32_t)(wm*32+(lane&15))*80 + (uint32_t)(lane>>4)*16;
    const uint32_t b_off = (uint32_t)((lane&7)+((lane>>4)<<3))*80 + (uint32_t)((lane>>3)&1)*16;

    auto ldA=[&](int c){
        uint32_t sb = sbase + (uint32_t)(c&1)*30720;
        const hlf *pa, *pb; int la;
        if(c<4){ pa = pq + (long)m0*512 + h*128 + c*32; la=512; pb = pkk + h*128 + c*32; }
        else   { pa = pp + (long)m0*128 + (c-4)*32;     la=128; pb = pq  + h*128 + (c-4)*32; }
#pragma unroll
        for(int it=0;it<2;++it){
            int ch=tid+it*256, r=ch>>2, q2=ch&3;
            cp16(sb + (uint32_t)r*80 + q2*16, pa + (long)r*la + q2*8);
        }
#pragma unroll
        for(int it=0;it<4;++it){
            int ch=tid+it*256, r=ch>>2, q2=ch&3;
            cp16(sb + 10240 + (uint32_t)r*80 + q2*16, pb + (long)r*512 + q2*8);
        }
        asm volatile("cp.async.commit_group;":::"memory");
    };

#pragma unroll
    for(int it=0;it<16;++it){
        int ch = tid + it*256;
        int r = ch>>5, cq = ch&31;
        cp16(sbase + FA_OV + (uint32_t)r*528 + cq*16, pv + (long)r*256 + cq*8);
    }
    ldA(0); ldA(1);

    float acc[2][16][4];
#pragma unroll
    for(int i=0;i<2;++i)
#pragma unroll
        for(int j=0;j<16;++j)
#pragma unroll
            for(int q=0;q<4;++q) acc[i][j][q]=0.0f;

    for(int c=0;c<8;++c){
        if(c<7) cpwait<1>(); else cpwait<0>();
        __syncthreads();
        const uint32_t base = sbase + (uint32_t)(c&1)*30720;
#pragma unroll
        for(int s=0;s<2;++s){
            uint32_t ah[2][4];
#pragma unroll
            for(int mi=0;mi<2;++mi) LDM4(ah[mi], base + a_off + mi*1280 + s*32);
#pragma unroll
            for(int nq=0;nq<8;++nq){
                uint32_t bh[4];
                LDM4(bh, base + 10240 + (uint32_t)wn*10240 + nq*1280 + b_off + s*32);
#pragma unroll
                for(int hf=0;hf<2;++hf){
                    int ni = nq*2+hf;
#pragma unroll
                    for(int mi=0;mi<2;++mi) mma16816(acc[mi][ni], ah[mi], bh+hf*2);
                }
            }
        }
        __syncthreads();
        if(c+2<8) ldA(c+2);
    }

    float* red = (float*)(sm + FA_OR);
    float mxv[2][2], inv[2][2];
#pragma unroll
    for(int mi=0;mi<2;++mi)
#pragma unroll
    for(int hf=0;hf<2;++hf){
        float m = -1e30f;
#pragma unroll
        for(int ni=0;ni<16;++ni){ m=fmaxf(m,acc[mi][ni][hf*2]); m=fmaxf(m,acc[mi][ni][hf*2+1]); }
        m = fmaxf(m, __shfl_xor_sync(~0u,m,1));
        m = fmaxf(m, __shfl_xor_sync(~0u,m,2));
        if(qk==0) red[(wm*32+mi*16+hf*8+qr)*2+wn] = m;
    }
    __syncthreads();
#pragma unroll
    for(int mi=0;mi<2;++mi)
#pragma unroll
    for(int hf=0;hf<2;++hf){
        int r = wm*32+mi*16+hf*8+qr;
        mxv[mi][hf] = fmaxf(red[r*2], red[r*2+1]);
    }
    __syncthreads();
#pragma unroll
    for(int mi=0;mi<2;++mi)
#pragma unroll
    for(int hf=0;hf<2;++hf){
        float s = 0.0f;
#pragma unroll
        for(int ni=0;ni<16;++ni){
            float e0=__expf(acc[mi][ni][hf*2]  -mxv[mi][hf]);
            float e1=__expf(acc[mi][ni][hf*2+1]-mxv[mi][hf]);
            acc[mi][ni][hf*2]=e0; acc[mi][ni][hf*2+1]=e1; s+=e0+e1;
        }
        s += __shfl_xor_sync(~0u,s,1);
        s += __shfl_xor_sync(~0u,s,2);
        if(qk==0) red[(wm*32+mi*16+hf*8+qr)*2+wn] = s;
    }
    __syncthreads();
#pragma unroll
    for(int mi=0;mi<2;++mi)
#pragma unroll
    for(int hf=0;hf<2;++hf){
        int r = wm*32+mi*16+hf*8+qr;
        inv[mi][hf] = 1.0f/(red[r*2]+red[r*2+1]);
    }
#pragma unroll
    for(int mi=0;mi<2;++mi)
#pragma unroll
    for(int hf=0;hf<2;++hf){
        int r = wm*32+mi*16+hf*8+qr;
#pragma unroll
        for(int ni=0;ni<16;++ni){
            int col = wn*128+ni*8+qk*2;
            uint32_t p2 = pk(__float2half(acc[mi][ni][hf*2]  *inv[mi][hf]),
                             __float2half(acc[mi][ni][hf*2+1]*inv[mi][hf]));
            *(uint32_t*)(sm + FA_OP + (uint32_t)r*528 + col*2) = p2;
        }
    }
    __syncthreads();

    float ao_acc[2][8][4];
#pragma unroll
    for(int i=0;i<2;++i)
#pragma unroll
        for(int j=0;j<8;++j)
#pragma unroll
            for(int q=0;q<4;++q) ao_acc[i][j][q]=0.0f;

    const uint32_t pa2 = (uint32_t)(wm*32+(lane&15))*528 + (uint32_t)(lane>>4)*16;
    const uint32_t vb2 = (uint32_t)(wn*64+(lane&7)+((lane>>4)<<3))*528 + (uint32_t)((lane>>3)&1)*16;
#pragma unroll 2
    for(int ks=0;ks<16;++ks){
        uint32_t ap[2][4];
#pragma unroll
        for(int mi=0;mi<2;++mi) LDM4(ap[mi], sbase + FA_OP + pa2 + mi*(16*528) + ks*32);
#pragma unroll
        for(int dq=0;dq<4;++dq){
            uint32_t bv[4];
            LDM4(bv, sbase + FA_OV + vb2 + dq*(16*528) + ks*32);
#pragma unroll
            for(int hf=0;hf<2;++hf){
                int ni = dq*2+hf;
#pragma unroll
                for(int mi=0;mi<2;++mi) mma16816(ao_acc[mi][ni], ap[mi], bv+hf*2);
            }
        }
    }

    hlf* po = AO + (long)b*131072 + h*128;
#pragma unroll
    for(int mi=0;mi<2;++mi)
#pragma unroll
    for(int hf=0;hf<2;++hf){
        int row = m0 + wm*32+mi*16+hf*8+qr;
#pragma unroll
        for(int ni=0;ni<8;++ni){
            int d = wn*64+ni*8+qk*2;
            float v0=fmaxf(ao_acc[mi][ni][hf*2],0.f), v1=fmaxf(ao_acc[mi][ni][hf*2+1],0.f);
            *(uint32_t*)(po + (long)row*512 + d) = pk(__float2half(v0), __float2half(v1));
        }
    }
}

// ---------------- prep kernels ----------------
__global__ void k_convw(const float* __restrict__ w, const float* __restrict__ g,
                        const float* __restrict__ vr, hlf* __restrict__ o, int K, int total){
    int i = blockIdx.x*256 + threadIdx.x; if(i>=total) return;
    float s = g ? g[i/K]*rsqrtf(vr[i/K]+EPSBN) : 1.0f;
    o[i] = __float2half(w[i]*s);
}
__global__ void k_xt(const float* __restrict__ x, hlf* __restrict__ o){
    __shared__ float t[32][33];
    int c0=blockIdx.x*32, nn0=blockIdx.y*32, b=blockIdx.z, tx=threadIdx.x, ty=threadIdx.y;
#pragma unroll
    for(int i=0;i<4;++i) t[ty+i*8][tx] = x[((long)b*1024 + c0+ty+i*8)*256 + nn0+tx];
    __syncthreads();
    hlf* ob = o + (long)b*262144;
#pragma unroll
    for(int i=0;i<4;++i)
        ob[(long)(nn0+ty+i*8)*1024 + c0+tx] = __float2half(t[tx][ty+i*8]);
}
__global__ void k_posT(const float* __restrict__ rh, const float* __restrict__ rw, hlf* __restrict__ o){
    int i = blockIdx.x*256 + threadIdx.x; if(i>=131072) return;
    int d = i&127, n = (i>>7)&255, h = i>>15;
    int hd = h*128+d;
    o[i] = __float2half(rh[hd*16+(n&15)] + rw[hd*16+(n>>4)]);
}
__global__ void k_prepvec(const float* g1,const float* b1,const float* m1,const float* v1,
                          const float* g2,const float* b2,const float* m2,const float* v2,const float* vbv,
                          const float* g3,const float* b3,const float* m3,const float* v3,const float* scb,
                          const float* gs,const float* bs,const float* ms,const float* vs){
    int i = blockIdx.x*256 + threadIdx.x;
    if(i<P_){
        float s1=g1[i]*rsqrtf(v1[i]+EPSBN); d_t1[i]=b1[i]-m1[i]*s1;
        float s2=g2[i]*rsqrtf(v2[i]+EPSBN);
        d_vshift[i]=fmaf(vbv[i],s2,b2[i]-m2[i]*s2);
    }
    if(i<COUT){
        float s3=g3[i]*rsqrtf(v3[i]+EPSBN);
        float ss=gs[i]*rsqrtf(vs[i]+EPSBN);
        d_tfin[i]=(b3[i]-m3[i]*s3) + fmaf(scb[i]-ms[i],ss,bs[i]);
    }
}

// ---------------- launch ----------------
extern "C" void kernel_launch(void* const* d_in, const int* in_sizes, int n_in,
                              void* d_out, int out_size) {
    const float *x=(const float*)d_in[0], *c1w=(const float*)d_in[1];
    const float *b1g=(const float*)d_in[2],*b1b=(const float*)d_in[3],*b1m=(const float*)d_in[4],*b1v=(const float*)d_in[5];
    const float *qw=(const float*)d_in[6],*qbv=(const float*)d_in[7],*kw=(const float*)d_in[8],*kbv=(const float*)d_in[9];
    const float *vw=(const float*)d_in[10],*vbv=(const float*)d_in[11],*rh=(const float*)d_in[12],*rwv=(const float*)d_in[13];
    const float *b2g=(const float*)d_in[14],*b2b=(const float*)d_in[15],*b2m=(const float*)d_in[16],*b2v=(const float*)d_in[17];
    const float *c3w=(const float*)d_in[18];
    const float *b3g=(const float*)d_in[19],*b3b=(const float*)d_in[20],*b3m=(const float*)d_in[21],*b3v=(const float*)d_in[22];
    const float *scw=(const float*)d_in[23],*scb=(const float*)d_in[24];
    const float *sg=(const float*)d_in[25],*sb=(const float*)d_in[26],*smn=(const float*)d_in[27],*sv=(const float*)d_in[28];

    hlf *xt,*w1,*wq,*wk,*wv,*w3,*wsc,*o1,*q,*k,*v,*ao,*pos;
    float *t1,*vsh,*tf;
    cudaGetSymbolAddress((void**)&xt, g_xt);   cudaGetSymbolAddress((void**)&w1, g_w1);
    cudaGetSymbolAddress((void**)&wq, g_wq);   cudaGetSymbolAddress((void**)&wk, g_wk);
    cudaGetSymbolAddress((void**)&wv, g_wv);   cudaGetSymbolAddress((void**)&w3, g_w3);
    cudaGetSymbolAddress((void**)&wsc,g_wsc);  cudaGetSymbolAddress((void**)&o1, g_o1);
    cudaGetSymbolAddress((void**)&q,  g_q);    cudaGetSymbolAddress((void**)&k,  g_k);
    cudaGetSymbolAddress((void**)&v,  g_v);    cudaGetSymbolAddress((void**)&ao, g_ao);
    cudaGetSymbolAddress((void**)&pos,g_pos);
    cudaGetSymbolAddress((void**)&t1, d_t1);   cudaGetSymbolAddress((void**)&vsh, d_vshift);
    cudaGetSymbolAddress((void**)&tf, d_tfin);

    cudaFuncSetAttribute(tc<false,true ,false,true >, cudaFuncAttributeMaxDynamicSharedMemorySize, SMEMSZ);
    cudaFuncSetAttribute(tc<false,false,false,true >, cudaFuncAttributeMaxDynamicSharedMemorySize, SMEMSZ);
    cudaFuncSetAttribute(tc<true ,false,false,true >, cudaFuncAttributeMaxDynamicSharedMemorySize, SMEMSZ);
    cudaFuncSetAttribute(tc<true ,true ,true ,false>, cudaFuncAttributeMaxDynamicSharedMemorySize, SMEMSZ);
    cudaFuncSetAttribute(fattn, cudaFuncAttributeMaxDynamicSharedMemorySize, FA_SMEM);

    // prep: convert weights/x once (fp16), fold BN
    k_convw<<<2048,256>>>(c1w, b1g, b1v, w1, 1024, 524288);
    k_convw<<<1024,256>>>(qw, nullptr, nullptr, wq, 512, 262144);
    k_convw<<<1024,256>>>(kw, nullptr, nullptr, wk, 512, 262144);
    k_convw<<<1024,256>>>(vw, b2g, b2v, wv, 512, 262144);
    k_convw<<<4096,256>>>(c3w, b3g, b3v, w3, 512, 1048576);
    k_convw<<<8192,256>>>(scw, sg, sv, wsc, 1024, 2097152);
    k_xt<<<dim3(32,8,64),dim3(32,8)>>>(x, xt);
    k_posT<<<512,256>>>(rh, rwv, pos);
    k_prepvec<<<8,256>>>(b1g,b1b,b1m,b1v, b2g,b2b,b2m,b2v,vbv, b3g,b3b,b3m,b3v,scb, sg,sb,smn,sv);

    // 1) out1[b][n][p] = xT·w1 + t1[col], ReLU
    tc<false,true,false,true><<<dim3(4,2,64),256,SMEMSZ>>>(
        xt,262144,0,1,1024,1024,  w1,0,0,1,1024,
        nullptr,0,0,1,0,0, nullptr,0,0,1,0,
        o1,131072,0,1,512, t1);
    // 2) q[b][n][p]
    tc<false,false,false,true><<<dim3(4,2,64),256,SMEMSZ>>>(
        o1,131072,0,1,512,512,  wq,0,0,1,512,
        nullptr,0,0,1,0,0, nullptr,0,0,1,0,
        q,131072,0,1,512, qbv);
    // 3) k[b][n][p]
    tc<false,false,false,true><<<dim3(4,2,64),256,SMEMSZ>>>(
        o1,131072,0,1,512,512,  wk,0,0,1,512,
        nullptr,0,0,1,0,0, nullptr,0,0,1,0,
        k,131072,0,1,512, kbv);
    // 4) v'[b][p][m] = (s2·wv)·out1 + vshift[row]
    tc<true,false,false,true><<<dim3(2,4,64),256,SMEMSZ>>>(
        wv,0,0,1,512,512,  o1,131072,0,1,512,
        nullptr,0,0,1,0,0, nullptr,0,0,1,0,
        v,131072,0,1,256, vsh);
    // 5-7) fused attention: logits (q·k + pos·q) -> softmax -> P·V^T, ReLU
    fattn<<<dim3(2,256),256,FA_SMEM>>>(q, k, pos, v, ao);
    // 8) out[b][cout][n] = w3·attout + wsc·xT + tfin[row], ReLU (two-phase)
    tc<true,true,true,false><<<dim3(2,16,64),256,SMEMSZ>>>(
        w3,0,0,1,512,512,  ao,131072,0,1,512,
        wsc,0,0,1,1024,1024,  xt,262144,0,1,1024,
        d_out,524288,0,1,256, tf);
}

// round 12
// speedup vs baseline: 5.6014x; 1.0292x over previous
#include <cuda_runtime.h>
#include <cuda_fp16.h>
#include <math.h>
#include <stdint.h>
typedef __half hlf;

#define EPSBN 1e-5f
#define B_    64
#define CIN   1024
#define P_    512
#define COUT  2048
#define NSP   256
#define HEADS 4
#define DH    128

// ---------------- scratch (fp16, single plane) ----------------
__device__ __align__(16) hlf g_xt [16777216];  // xT[b][n][cin]
__device__ __align__(16) hlf g_w1 [524288];
__device__ __align__(16) hlf g_wqk[524288];    // [wq;wk] rows 0..511 q, 512..1023 k
__device__ __align__(16) hlf g_wv [262144];    // pre-scaled by BN2
__device__ __align__(16) hlf g_w3 [1048576];
__device__ __align__(16) hlf g_wsc[2097152];
__device__ __align__(16) hlf g_o1 [8388608];   // out1[b][n][p]
__device__ __align__(16) hlf g_qk [16777216];  // qk[b][n][1024]
__device__ __align__(16) hlf g_v  [8388608];   // v'[b][p][m]
__device__ __align__(16) hlf g_ao [8388608];   // attout[b][n][p]
__device__ __align__(16) hlf g_pos[131072];    // posT[h][n][d]
__device__ __align__(16) float d_t1[P_], d_vshift[P_], d_tfin[COUT], d_qkb[1024];

// ---------------- helpers ----------------
__device__ __forceinline__ uint32_t su32(const void* p){uint32_t a;asm("{ .reg .u64 t; cvta.to.shared.u64 t, %1; cvt.u32.u64 %0, t; }":"=r"(a):"l"(p));return a;}
__device__ __forceinline__ void cp16(uint32_t d, const void* s){asm volatile("cp.async.cg.shared.global [%0], [%1], 16;"::"r"(d),"l"(s));}
__device__ __forceinline__ uint32_t pk(hlf a, hlf b){return (uint32_t)__half_as_ushort(a)|((uint32_t)__half_as_ushort(b)<<16);}
__device__ __forceinline__ void mma16816(float* c, const uint32_t* a, const uint32_t* b){
    asm volatile("mma.sync.aligned.m16n8k16.row.col.f32.f16.f16.f32 "
        "{%0,%1,%2,%3},{%4,%5,%6,%7},{%8,%9},{%0,%1,%2,%3};"
        : "+f"(c[0]), "+f"(c[1]), "+f"(c[2]), "+f"(c[3])
        : "r"(a[0]), "r"(a[1]), "r"(a[2]), "r"(a[3]), "r"(b[0]), "r"(b[1]));
}
#define LDM4(r, a) asm volatile("ldmatrix.sync.aligned.m8n8.x4.shared.b16 {%0,%1,%2,%3}, [%4];" \
    : "=r"((r)[0]),"=r"((r)[1]),"=r"((r)[2]),"=r"((r)[3]) : "r"(a))
template<int N> __device__ __forceinline__ void cpwait(){
    asm volatile("cp.async.wait_group %0;"::"n"(N):"memory");
}

// ---------------- tensor-core GEMM: BM=BN=128, BK=32, 4-buf single-sync pipeline ----------------
#define PLANE 10240
#define BUFSZ 20480
#define SMEMSZ 81920

template<bool BIASROW, bool RELU, bool HAS2, bool OUTHF>
__global__ void __launch_bounds__(256,2) tc(
  const hlf* __restrict__ A1, long aso1, long asi1, int adiv1, int lda1, int K1,
  const hlf* __restrict__ B1, long bso1, long bsi1, int bdiv1, int ldb1,
  const hlf* __restrict__ A2, long aso2, long asi2, int adiv2, int lda2, int K2,
  const hlf* __restrict__ B2, long bso2, long bsi2, int bdiv2, int ldb2,
  void* __restrict__ C, long cso, long csi, int cdiv, int ldc,
  const float* __restrict__ bias)
{
    extern __shared__ char sm[];
    const uint32_t sbase = su32(sm);
    const int tid = threadIdx.x;
    const int z = blockIdx.z, m0 = blockIdx.y*128, n0 = blockIdx.x*128;
    const int lane = tid&31, w = tid>>5;
    const int wm = w>>1, wn = w&1;
    const int qr = lane>>2, qk = lane&3;

    const uint32_t a_off = (uint32_t)(wm*32 + (lane&15))*80 + (uint32_t)(lane>>4)*16;
    const uint32_t b_off = (uint32_t)(wn*64 + (lane&7) + (lane>>4)*8)*80 + (uint32_t)((lane>>3)&1)*16;

    const hlf* pA1 = A1 + (long)(z/adiv1)*aso1 + (long)(z%adiv1)*asi1;
    const hlf* pB1 = B1 + (long)(z/bdiv1)*bso1 + (long)(z%bdiv1)*bsi1;
    const hlf* pA2 = HAS2 ? A2 + (long)(z/adiv2)*aso2 + (long)(z%adiv2)*asi2 : nullptr;
    const hlf* pB2 = HAS2 ? B2 + (long)(z/bdiv2)*bso2 + (long)(z%bdiv2)*bsi2 : nullptr;
    const int nst1 = K1/32, nst = nst1 + (HAS2 ? K2/32 : 0);

    float acc[2][8][4];
#pragma unroll
    for(int i=0;i<2;++i)
#pragma unroll
        for(int j=0;j<8;++j)
#pragma unroll
            for(int q=0;q<4;++q) acc[i][j][q]=0.0f;

    auto ld=[&](int c){
        const hlf *pa,*pb; int la,lb,k0;
        if(!HAS2 || c<nst1){ pa=pA1; pb=pB1; la=lda1; lb=ldb1; k0=c*32; }
        else               { pa=pA2; pb=pB2; la=lda2; lb=ldb2; k0=(c-nst1)*32; }
        uint32_t sb = sbase + (uint32_t)(c&3)*BUFSZ;
#pragma unroll
        for(int it=0;it<2;++it){
            int ch=tid+it*256, r=ch>>2, q=ch&3;
            uint32_t da = sb + (uint32_t)r*80 + q*16;
            cp16(da, pa + (long)(m0+r)*la + k0 + q*8);
            cp16(da+PLANE, pb + (long)(n0+r)*lb + k0 + q*8);
        }
        asm volatile("cp.async.commit_group;":::"memory");
    };

    auto compute=[&](int buf){
        const uint32_t base = sbase + (uint32_t)buf*BUFSZ;
#pragma unroll
        for(int s=0;s<2;++s){
            uint32_t ah[2][4];
#pragma unroll
            for(int mi=0;mi<2;++mi) LDM4(ah[mi], base + a_off + mi*1280 + s*32);
#pragma unroll
            for(int nq=0;nq<4;++nq){
                uint32_t bh[4];
                LDM4(bh, base + PLANE + b_off + nq*1280 + s*32);
#pragma unroll
                for(int hf=0;hf<2;++hf){
                    int ni = nq*2 + hf;
#pragma unroll
                    for(int mi=0;mi<2;++mi) mma16816(acc[mi][ni], ah[mi], bh + hf*2);
                }
            }
        }
    };

    ld(0);
    if(nst>1) ld(1);
    if(nst>2) ld(2);
    for(int c=0;c<nst;++c){
        int out = nst - c;
        if(out >= 3)    cpwait<2>();
        else if(out==2) cpwait<1>();
        else            cpwait<0>();
        __syncthreads();
        if(c+3<nst) ld(c+3);          // overwrites buffer (c-1)%4: safe post-barrier
        compute(c&3);
    }

    long cz = (long)(z/cdiv)*cso + (long)(z%cdiv)*csi;
#pragma unroll
    for(int mi=0;mi<2;++mi){
#pragma unroll
        for(int hf=0;hf<2;++hf){
            int row = m0 + wm*32 + mi*16 + qr + hf*8;
            float tr = (BIASROW && bias) ? __ldg(bias+row) : 0.0f;
#pragma unroll
            for(int ni=0;ni<8;++ni){
                int col = n0 + wn*64 + ni*8 + qk*2;
                float v0 = acc[mi][ni][hf*2], v1 = acc[mi][ni][hf*2+1];
                if(BIASROW){ v0 += tr; v1 += tr; }
                else if(bias){ v0 += __ldg(bias+col); v1 += __ldg(bias+col+1); }
                if(RELU){ v0 = fmaxf(v0,0.0f); v1 = fmaxf(v1,0.0f); }
                if(OUTHF){
                    hlf* Cb = (hlf*)C + cz + (long)row*ldc + col;
                    *(uint32_t*)Cb = pk(__float2half(v0), __float2half(v1));
                } else {
                    float2 f = {v0, v1};
                    *(float2*)((float*)C + cz + (long)row*ldc + col) = f;
                }
            }
        }
    }
}

// ---------------- fused attention: logits + softmax + attn·V ----------------
#define FA_OV 61440
#define FA_OP 129024
#define FA_OR 196608
#define FA_SMEM 197632

__global__ void __launch_bounds__(256) fattn(
  const hlf* __restrict__ QK, const hlf* __restrict__ POS,
  const hlf* __restrict__ V, hlf* __restrict__ AO)
{
    extern __shared__ char sm[];
    const uint32_t sbase = su32(sm);
    const int tid=threadIdx.x, lane=tid&31, w=tid>>5, wm=w>>1, wn=w&1;
    const int qr=lane>>2, qk=lane&3;
    const int m0 = blockIdx.x*128;
    const int z = blockIdx.y, b = z>>2, h = z&3;

    const hlf* pq = QK + (long)b*262144;          // q cols 0..511, stride 1024
    const hlf* pkk = pq + 512;                    // k cols 512..1023
    const hlf* pp = POS + (long)h*32768;
    const hlf* pv = V + (long)b*131072 + (long)h*128*256;

    const uint32_t a_off = (uint32_t)(wm*32+(lane&15))*80 + (uint32_t)(lane>>4)*16;
    const uint32_t b_off = (uint32_t)((lane&7)+((lane>>4)<<3))*80 + (uint32_t)((lane>>3)&1)*16;

    auto ldA=[&](int c){
        uint32_t sb = sbase + (uint32_t)(c&1)*30720;
        const hlf *pa, *pb; int la;
        if(c<4){ pa = pq + (long)m0*1024 + h*128 + c*32; la=1024; pb = pkk + h*128 + c*32; }
        else   { pa = pp + (long)m0*128 + (c-4)*32;      la=128;  pb = pq  + h*128 + (c-4)*32; }
#pragma unroll
        for(int it=0;it<2;++it){
            int ch=tid+it*256, r=ch>>2, q2=ch&3;
            cp16(sb + (uint32_t)r*80 + q2*16, pa + (long)r*la + q2*8);
        }
#pragma unroll
        for(int it=0;it<4;++it){
            int ch=tid+it*256, r=ch>>2, q2=ch&3;
            cp16(sb + 10240 + (uint32_t)r*80 + q2*16, pb + (long)r*1024 + q2*8);
        }
        asm volatile("cp.async.commit_group;":::"memory");
    };

#pragma unroll
    for(int it=0;it<16;++it){
        int ch = tid + it*256;
        int r = ch>>5, cq = ch&31;
        cp16(sbase + FA_OV + (uint32_t)r*528 + cq*16, pv + (long)r*256 + cq*8);
    }
    ldA(0); ldA(1);

    float acc[2][16][4];
#pragma unroll
    for(int i=0;i<2;++i)
#pragma unroll
        for(int j=0;j<16;++j)
#pragma unroll
            for(int q=0;q<4;++q) acc[i][j][q]=0.0f;

    for(int c=0;c<8;++c){
        if(c<7) cpwait<1>(); else cpwait<0>();
        __syncthreads();
        const uint32_t base = sbase + (uint32_t)(c&1)*30720;
#pragma unroll
        for(int s=0;s<2;++s){
            uint32_t ah[2][4];
#pragma unroll
            for(int mi=0;mi<2;++mi) LDM4(ah[mi], base + a_off + mi*1280 + s*32);
#pragma unroll
            for(int nq=0;nq<8;++nq){
                uint32_t bh[4];
                LDM4(bh, base + 10240 + (uint32_t)wn*10240 + nq*1280 + b_off + s*32);
#pragma unroll
                for(int hf=0;hf<2;++hf){
                    int ni = nq*2+hf;
#pragma unroll
                    for(int mi=0;mi<2;++mi) mma16816(acc[mi][ni], ah[mi], bh+hf*2);
                }
            }
        }
        __syncthreads();
        if(c+2<8) ldA(c+2);
    }

    float* red = (float*)(sm + FA_OR);
    float mxv[2][2], inv[2][2];
#pragma unroll
    for(int mi=0;mi<2;++mi)
#pragma unroll
    for(int hf=0;hf<2;++hf){
        float m = -1e30f;
#pragma unroll
        for(int ni=0;ni<16;++ni){ m=fmaxf(m,acc[mi][ni][hf*2]); m=fmaxf(m,acc[mi][ni][hf*2+1]); }
        m = fmaxf(m, __shfl_xor_sync(~0u,m,1));
        m = fmaxf(m, __shfl_xor_sync(~0u,m,2));
        if(qk==0) red[(wm*32+mi*16+hf*8+qr)*2+wn] = m;
    }
    __syncthreads();
#pragma unroll
    for(int mi=0;mi<2;++mi)
#pragma unroll
    for(int hf=0;hf<2;++hf){
        int r = wm*32+mi*16+hf*8+qr;
        mxv[mi][hf] = fmaxf(red[r*2], red[r*2+1]);
    }
    __syncthreads();
#pragma unroll
    for(int mi=0;mi<2;++mi)
#pragma unroll
    for(int hf=0;hf<2;++hf){
        float s = 0.0f;
#pragma unroll
        for(int ni=0;ni<16;++ni){
            float e0=__expf(acc[mi][ni][hf*2]  -mxv[mi][hf]);
            float e1=__expf(acc[mi][ni][hf*2+1]-mxv[mi][hf]);
            acc[mi][ni][hf*2]=e0; acc[mi][ni][hf*2+1]=e1; s+=e0+e1;
        }
        s += __shfl_xor_sync(~0u,s,1);
        s += __shfl_xor_sync(~0u,s,2);
        if(qk==0) red[(wm*32+mi*16+hf*8+qr)*2+wn] = s;
    }
    __syncthreads();
#pragma unroll
    for(int mi=0;mi<2;++mi)
#pragma unroll
    for(int hf=0;hf<2;++hf){
        int r = wm*32+mi*16+hf*8+qr;
        inv[mi][hf] = 1.0f/(red[r*2]+red[r*2+1]);
    }
#pragma unroll
    for(int mi=0;mi<2;++mi)
#pragma unroll
    for(int hf=0;hf<2;++hf){
        int r = wm*32+mi*16+hf*8+qr;
#pragma unroll
        for(int ni=0;ni<16;++ni){
            int col = wn*128+ni*8+qk*2;
            uint32_t p2 = pk(__float2half(acc[mi][ni][hf*2]  *inv[mi][hf]),
                             __float2half(acc[mi][ni][hf*2+1]*inv[mi][hf]));
            *(uint32_t*)(sm + FA_OP + (uint32_t)r*528 + col*2) = p2;
        }
    }
    __syncthreads();

    float ao_acc[2][8][4];
#pragma unroll
    for(int i=0;i<2;++i)
#pragma unroll
        for(int j=0;j<8;++j)
#pragma unroll
            for(int q=0;q<4;++q) ao_acc[i][j][q]=0.0f;

    const uint32_t pa2 = (uint32_t)(wm*32+(lane&15))*528 + (uint32_t)(lane>>4)*16;
    const uint32_t vb2 = (uint32_t)(wn*64+(lane&7)+((lane>>4)<<3))*528 + (uint32_t)((lane>>3)&1)*16;
#pragma unroll 2
    for(int ks=0;ks<16;++ks){
        uint32_t ap[2][4];
#pragma unroll
        for(int mi=0;mi<2;++mi) LDM4(ap[mi], sbase + FA_OP + pa2 + mi*(16*528) + ks*32);
#pragma unroll
        for(int dq=0;dq<4;++dq){
            uint32_t bv[4];
            LDM4(bv, sbase + FA_OV + vb2 + dq*(16*528) + ks*32);
#pragma unroll
            for(int hf=0;hf<2;++hf){
                int ni = dq*2+hf;
#pragma unroll
                for(int mi=0;mi<2;++mi) mma16816(ao_acc[mi][ni], ap[mi], bv+hf*2);
            }
        }
    }

    hlf* po = AO + (long)b*131072 + h*128;
#pragma unroll
    for(int mi=0;mi<2;++mi)
#pragma unroll
    for(int hf=0;hf<2;++hf){
        int row = m0 + wm*32+mi*16+hf*8+qr;
#pragma unroll
        for(int ni=0;ni<8;++ni){
            int d = wn*64+ni*8+qk*2;
            float v0=fmaxf(ao_acc[mi][ni][hf*2],0.f), v1=fmaxf(ao_acc[mi][ni][hf*2+1],0.f);
            *(uint32_t*)(po + (long)row*512 + d) = pk(__float2half(v0), __float2half(v1));
        }
    }
}

// ---------------- prep kernels ----------------
__global__ void k_convw(const float* __restrict__ w, const float* __restrict__ g,
                        const float* __restrict__ vr, hlf* __restrict__ o, int K, int total){
    int i = blockIdx.x*256 + threadIdx.x; if(i>=total) return;
    float s = g ? g[i/K]*rsqrtf(vr[i/K]+EPSBN) : 1.0f;
    o[i] = __float2half(w[i]*s);
}
__global__ void k_xt(const float* __restrict__ x, hlf* __restrict__ o){
    __shared__ float t[32][33];
    int c0=blockIdx.x*32, nn0=blockIdx.y*32, b=blockIdx.z, tx=threadIdx.x, ty=threadIdx.y;
#pragma unroll
    for(int i=0;i<4;++i) t[ty+i*8][tx] = x[((long)b*1024 + c0+ty+i*8)*256 + nn0+tx];
    __syncthreads();
    hlf* ob = o + (long)b*262144;
#pragma unroll
    for(int i=0;i<4;++i)
        ob[(long)(nn0+ty+i*8)*1024 + c0+tx] = __float2half(t[tx][ty+i*8]);
}
__global__ void k_posT(const float* __restrict__ rh, const float* __restrict__ rw, hlf* __restrict__ o){
    int i = blockIdx.x*256 + threadIdx.x; if(i>=131072) return;
    int d = i&127, n = (i>>7)&255, h = i>>15;
    int hd = h*128+d;
    o[i] = __float2half(rh[hd*16+(n&15)] + rw[hd*16+(n>>4)]);
}
__global__ void k_prepvec(const float* g1,const float* b1,const float* m1,const float* v1,
                          const float* g2,const float* b2,const float* m2,const float* v2,const float* vbv,
                          const float* g3,const float* b3,const float* m3,const float* v3,const float* scb,
                          const float* gs,const float* bs,const float* ms,const float* vs,
                          const float* qbv,const float* kbv){
    int i = blockIdx.x*256 + threadIdx.x;
    if(i<P_){
        float s1=g1[i]*rsqrtf(v1[i]+EPSBN); d_t1[i]=b1[i]-m1[i]*s1;
        float s2=g2[i]*rsqrtf(v2[i]+EPSBN);
        d_vshift[i]=fmaf(vbv[i],s2,b2[i]-m2[i]*s2);
        d_qkb[i]=qbv[i];
        d_qkb[i+512]=kbv[i];
    }
    if(i<COUT){
        float s3=g3[i]*rsqrtf(v3[i]+EPSBN);
        float ss=gs[i]*rsqrtf(vs[i]+EPSBN);
        d_tfin[i]=(b3[i]-m3[i]*s3) + fmaf(scb[i]-ms[i],ss,bs[i]);
    }
}

// ---------------- launch ----------------
extern "C" void kernel_launch(void* const* d_in, const int* in_sizes, int n_in,
                              void* d_out, int out_size) {
    const float *x=(const float*)d_in[0], *c1w=(const float*)d_in[1];
    const float *b1g=(const float*)d_in[2],*b1b=(const float*)d_in[3],*b1m=(const float*)d_in[4],*b1v=(const float*)d_in[5];
    const float *qw=(const float*)d_in[6],*qbv=(const float*)d_in[7],*kw=(const float*)d_in[8],*kbv=(const float*)d_in[9];
    const float *vw=(const float*)d_in[10],*vbv=(const float*)d_in[11],*rh=(const float*)d_in[12],*rwv=(const float*)d_in[13];
    const float *b2g=(const float*)d_in[14],*b2b=(const float*)d_in[15],*b2m=(const float*)d_in[16],*b2v=(const float*)d_in[17];
    const float *c3w=(const float*)d_in[18];
    const float *b3g=(const float*)d_in[19],*b3b=(const float*)d_in[20],*b3m=(const float*)d_in[21],*b3v=(const float*)d_in[22];
    const float *scw=(const float*)d_in[23],*scb=(const float*)d_in[24];
    const float *sg=(const float*)d_in[25],*sb=(const float*)d_in[26],*smn=(const float*)d_in[27],*sv=(const float*)d_in[28];

    hlf *xt,*w1,*wqk,*wv,*w3,*wsc,*o1,*qk,*v,*ao,*pos;
    float *t1,*vsh,*tf,*qkb;
    cudaGetSymbolAddress((void**)&xt, g_xt);   cudaGetSymbolAddress((void**)&w1, g_w1);
    cudaGetSymbolAddress((void**)&wqk,g_wqk);  cudaGetSymbolAddress((void**)&wv, g_wv);
    cudaGetSymbolAddress((void**)&w3, g_w3);   cudaGetSymbolAddress((void**)&wsc,g_wsc);
    cudaGetSymbolAddress((void**)&o1, g_o1);   cudaGetSymbolAddress((void**)&qk, g_qk);
    cudaGetSymbolAddress((void**)&v,  g_v);    cudaGetSymbolAddress((void**)&ao, g_ao);
    cudaGetSymbolAddress((void**)&pos,g_pos);
    cudaGetSymbolAddress((void**)&t1, d_t1);   cudaGetSymbolAddress((void**)&vsh, d_vshift);
    cudaGetSymbolAddress((void**)&tf, d_tfin); cudaGetSymbolAddress((void**)&qkb, d_qkb);

    cudaFuncSetAttribute(tc<false,true ,false,true >, cudaFuncAttributeMaxDynamicSharedMemorySize, SMEMSZ);
    cudaFuncSetAttribute(tc<false,false,false,true >, cudaFuncAttributeMaxDynamicSharedMemorySize, SMEMSZ);
    cudaFuncSetAttribute(tc<true ,false,false,true >, cudaFuncAttributeMaxDynamicSharedMemorySize, SMEMSZ);
    cudaFuncSetAttribute(tc<true ,true ,true ,false>, cudaFuncAttributeMaxDynamicSharedMemorySize, SMEMSZ);
    cudaFuncSetAttribute(fattn, cudaFuncAttributeMaxDynamicSharedMemorySize, FA_SMEM);

    // prep
    k_convw<<<2048,256>>>(c1w, b1g, b1v, w1, 1024, 524288);
    k_convw<<<1024,256>>>(qw, nullptr, nullptr, wqk, 512, 262144);
    k_convw<<<1024,256>>>(kw, nullptr, nullptr, wqk + 262144, 512, 262144);
    k_convw<<<1024,256>>>(vw, b2g, b2v, wv, 512, 262144);
    k_convw<<<4096,256>>>(c3w, b3g, b3v, w3, 512, 1048576);
    k_convw<<<8192,256>>>(scw, sg, sv, wsc, 1024, 2097152);
    k_xt<<<dim3(32,8,64),dim3(32,8)>>>(x, xt);
    k_posT<<<512,256>>>(rh, rwv, pos);
    k_prepvec<<<8,256>>>(b1g,b1b,b1m,b1v, b2g,b2b,b2m,b2v,vbv, b3g,b3b,b3m,b3v,scb,
                         sg,sb,smn,sv, qbv,kbv);

    // 1) out1[b][n][p] = xT·w1 + t1[col], ReLU
    tc<false,true,false,true><<<dim3(4,2,64),256,SMEMSZ>>>(
        xt,262144,0,1,1024,1024,  w1,0,0,1,1024,
        nullptr,0,0,1,0,0, nullptr,0,0,1,0,
        o1,131072,0,1,512, t1);
    // 2) qk[b][n][0..1023] = o1·[wq;wk] + qkb[col]  (fused q+k)
    tc<false,false,false,true><<<dim3(8,2,64),256,SMEMSZ>>>(
        o1,131072,0,1,512,512,  wqk,0,0,1,512,
        nullptr,0,0,1,0,0, nullptr,0,0,1,0,
        qk,262144,0,1,1024, qkb);
    // 3) v'[b][p][m] = (s2·wv)·out1 + vshift[row]
    tc<true,false,false,true><<<dim3(2,4,64),256,SMEMSZ>>>(
        wv,0,0,1,512,512,  o1,131072,0,1,512,
        nullptr,0,0,1,0,0, nullptr,0,0,1,0,
        v,131072,0,1,256, vsh);
    // 4-6) fused attention: logits (q·k + pos·q) -> softmax -> P·V^T, ReLU
    fattn<<<dim3(2,256),256,FA_SMEM>>>(qk, pos, v, ao);
    // 7) out[b][cout][n] = w3·attout + wsc·xT + tfin[row], ReLU (two-phase)
    tc<true,true,true,false><<<dim3(2,16,64),256,SMEMSZ>>>(
        w3,0,0,1,512,512,  ao,131072,0,1,512,
        wsc,0,0,1,1024,1024,  xt,262144,0,1,1024,
        d_out,524288,0,1,256, tf);
}

// round 13
// speedup vs baseline: 5.7567x; 1.0277x over previous
#include <cuda_runtime.h>
#include <cuda_fp16.h>
#include <math.h>
#include <stdint.h>
typedef __half hlf;

#define EPSBN 1e-5f
#define B_    64
#define CIN   1024
#define P_    512
#define COUT  2048
#define NSP   256
#define HEADS 4
#define DH    128

// ---------------- scratch ----------------
__device__ __align__(16) hlf g_xt  [16777216];  // xT[b][n][cin]
__device__ __align__(16) hlf g_w1  [524288];
__device__ __align__(16) hlf g_wqkv[786432];    // [wq;wk;wv(BN2-scaled)] [1536][512]
__device__ __align__(16) hlf g_w3  [1048576];
__device__ __align__(16) hlf g_wsc [2097152];
__device__ __align__(16) hlf g_o1  [8388608];   // out1[b][n][p]
__device__ __align__(16) hlf g_qkv [25165824];  // qkv[b][n][1536]
__device__ __align__(16) hlf g_ao  [8388608];   // attout[b][n][p]
__device__ __align__(16) hlf g_pos [131072];    // posT[h][n][d]
__device__ __align__(16) float d_t1[P_], d_tfin[COUT], d_qkvb[1536];

// ---------------- helpers ----------------
__device__ __forceinline__ uint32_t su32(const void* p){uint32_t a;asm("{ .reg .u64 t; cvta.to.shared.u64 t, %1; cvt.u32.u64 %0, t; }":"=r"(a):"l"(p));return a;}
__device__ __forceinline__ void cp16(uint32_t d, const void* s){asm volatile("cp.async.cg.shared.global [%0], [%1], 16;"::"r"(d),"l"(s));}
__device__ __forceinline__ uint32_t pk(hlf a, hlf b){return (uint32_t)__half_as_ushort(a)|((uint32_t)__half_as_ushort(b)<<16);}
__device__ __forceinline__ void mma16816(float* c, const uint32_t* a, const uint32_t* b){
    asm volatile("mma.sync.aligned.m16n8k16.row.col.f32.f16.f16.f32 "
        "{%0,%1,%2,%3},{%4,%5,%6,%7},{%8,%9},{%0,%1,%2,%3};"
        : "+f"(c[0]), "+f"(c[1]), "+f"(c[2]), "+f"(c[3])
        : "r"(a[0]), "r"(a[1]), "r"(a[2]), "r"(a[3]), "r"(b[0]), "r"(b[1]));
}
#define LDM4(r, a) asm volatile("ldmatrix.sync.aligned.m8n8.x4.shared.b16 {%0,%1,%2,%3}, [%4];" \
    : "=r"((r)[0]),"=r"((r)[1]),"=r"((r)[2]),"=r"((r)[3]) : "r"(a))
#define LDM4T(r, a) asm volatile("ldmatrix.sync.aligned.m8n8.x4.trans.shared.b16 {%0,%1,%2,%3}, [%4];" \
    : "=r"((r)[0]),"=r"((r)[1]),"=r"((r)[2]),"=r"((r)[3]) : "r"(a))
template<int N> __device__ __forceinline__ void cpwait(){
    asm volatile("cp.async.wait_group %0;"::"n"(N):"memory");
}

// ---------------- tensor-core GEMM: BM=BN=128, BK=32, 4-buf single-sync pipeline ----------------
#define PLANE 10240
#define BUFSZ 20480
#define SMEMSZ 81920

template<bool BIASROW, bool RELU, bool HAS2, bool OUTHF>
__global__ void __launch_bounds__(256,2) tc(
  const hlf* __restrict__ A1, long aso1, long asi1, int adiv1, int lda1, int K1,
  const hlf* __restrict__ B1, long bso1, long bsi1, int bdiv1, int ldb1,
  const hlf* __restrict__ A2, long aso2, long asi2, int adiv2, int lda2, int K2,
  const hlf* __restrict__ B2, long bso2, long bsi2, int bdiv2, int ldb2,
  void* __restrict__ C, long cso, long csi, int cdiv, int ldc,
  const float* __restrict__ bias)
{
    extern __shared__ char sm[];
    const uint32_t sbase = su32(sm);
    const int tid = threadIdx.x;
    const int z = blockIdx.z, m0 = blockIdx.y*128, n0 = blockIdx.x*128;
    const int lane = tid&31, w = tid>>5;
    const int wm = w>>1, wn = w&1;
    const int qr = lane>>2, qk = lane&3;

    const uint32_t a_off = (uint32_t)(wm*32 + (lane&15))*80 + (uint32_t)(lane>>4)*16;
    const uint32_t b_off = (uint32_t)(wn*64 + (lane&7) + (lane>>4)*8)*80 + (uint32_t)((lane>>3)&1)*16;

    const hlf* pA1 = A1 + (long)(z/adiv1)*aso1 + (long)(z%adiv1)*asi1;
    const hlf* pB1 = B1 + (long)(z/bdiv1)*bso1 + (long)(z%bdiv1)*bsi1;
    const hlf* pA2 = HAS2 ? A2 + (long)(z/adiv2)*aso2 + (long)(z%adiv2)*asi2 : nullptr;
    const hlf* pB2 = HAS2 ? B2 + (long)(z/bdiv2)*bso2 + (long)(z%bdiv2)*bsi2 : nullptr;
    const int nst1 = K1/32, nst = nst1 + (HAS2 ? K2/32 : 0);

    float acc[2][8][4];
#pragma unroll
    for(int i=0;i<2;++i)
#pragma unroll
        for(int j=0;j<8;++j)
#pragma unroll
            for(int q=0;q<4;++q) acc[i][j][q]=0.0f;

    auto ld=[&](int c){
        const hlf *pa,*pb; int la,lb,k0;
        if(!HAS2 || c<nst1){ pa=pA1; pb=pB1; la=lda1; lb=ldb1; k0=c*32; }
        else               { pa=pA2; pb=pB2; la=lda2; lb=ldb2; k0=(c-nst1)*32; }
        uint32_t sb = sbase + (uint32_t)(c&3)*BUFSZ;
#pragma unroll
        for(int it=0;it<2;++it){
            int ch=tid+it*256, r=ch>>2, q=ch&3;
            uint32_t da = sb + (uint32_t)r*80 + q*16;
            cp16(da, pa + (long)(m0+r)*la + k0 + q*8);
            cp16(da+PLANE, pb + (long)(n0+r)*lb + k0 + q*8);
        }
        asm volatile("cp.async.commit_group;":::"memory");
    };

    auto compute=[&](int buf){
        const uint32_t base = sbase + (uint32_t)buf*BUFSZ;
#pragma unroll
        for(int s=0;s<2;++s){
            uint32_t ah[2][4];
#pragma unroll
            for(int mi=0;mi<2;++mi) LDM4(ah[mi], base + a_off + mi*1280 + s*32);
#pragma unroll
            for(int nq=0;nq<4;++nq){
                uint32_t bh[4];
                LDM4(bh, base + PLANE + b_off + nq*1280 + s*32);
#pragma unroll
                for(int hf=0;hf<2;++hf){
                    int ni = nq*2 + hf;
#pragma unroll
                    for(int mi=0;mi<2;++mi) mma16816(acc[mi][ni], ah[mi], bh + hf*2);
                }
            }
        }
    };

    ld(0);
    if(nst>1) ld(1);
    if(nst>2) ld(2);
    for(int c=0;c<nst;++c){
        int out = nst - c;
        if(out >= 3)    cpwait<2>();
        else if(out==2) cpwait<1>();
        else            cpwait<0>();
        __syncthreads();
        if(c+3<nst) ld(c+3);
        compute(c&3);
    }

    long cz = (long)(z/cdiv)*cso + (long)(z%cdiv)*csi;
#pragma unroll
    for(int mi=0;mi<2;++mi){
#pragma unroll
        for(int hf=0;hf<2;++hf){
            int row = m0 + wm*32 + mi*16 + qr + hf*8;
            float tr = (BIASROW && bias) ? __ldg(bias+row) : 0.0f;
#pragma unroll
            for(int ni=0;ni<8;++ni){
                int col = n0 + wn*64 + ni*8 + qk*2;
                float v0 = acc[mi][ni][hf*2], v1 = acc[mi][ni][hf*2+1];
                if(BIASROW){ v0 += tr; v1 += tr; }
                else if(bias){ v0 += __ldg(bias+col); v1 += __ldg(bias+col+1); }
                if(RELU){ v0 = fmaxf(v0,0.0f); v1 = fmaxf(v1,0.0f); }
                if(OUTHF){
                    hlf* Cb = (hlf*)C + cz + (long)row*ldc + col;
                    *(uint32_t*)Cb = pk(__float2half(v0), __float2half(v1));
                } else {
                    float2 f = {v0, v1};
                    *(float2*)((float*)C + cz + (long)row*ldc + col) = f;
                }
            }
        }
    }
}

// ---------------- fused attention: logits + softmax + attn·V ----------------
// smem: [0,61440) qk pipeline; [61440,131072) V 256x272B; [131072,198656) P 128x528B; red.
#define FA_OV 61440
#define FA_OP 131072
#define FA_OR 198656
#define FA_SMEM 199680

__global__ void __launch_bounds__(256) fattn(
  const hlf* __restrict__ QKV, const hlf* __restrict__ POS,
  hlf* __restrict__ AO)
{
    extern __shared__ char sm[];
    const uint32_t sbase = su32(sm);
    const int tid=threadIdx.x, lane=tid&31, w=tid>>5, wm=w>>1, wn=w&1;
    const int qr=lane>>2, qk=lane&3;
    const int m0 = blockIdx.x*128;
    const int z = blockIdx.y, b = z>>2, h = z&3;

    const hlf* pq = QKV + (long)b*393216;          // q cols 0..511, stride 1536
    const hlf* pkk = pq + 512;                     // k cols
    const hlf* pv  = pq + 1024 + h*128;            // v[m][d] rows stride 1536
    const hlf* pp = POS + (long)h*32768;

    const uint32_t a_off = (uint32_t)(wm*32+(lane&15))*80 + (uint32_t)(lane>>4)*16;
    const uint32_t b_off = (uint32_t)((lane&7)+((lane>>4)<<3))*80 + (uint32_t)((lane>>3)&1)*16;

    auto ldA=[&](int c){
        uint32_t sb = sbase + (uint32_t)(c&1)*30720;
        const hlf *pa, *pb; int la;
        if(c<4){ pa = pq + (long)m0*1536 + h*128 + c*32; la=1536; pb = pkk + h*128 + c*32; }
        else   { pa = pp + (long)m0*128 + (c-4)*32;      la=128;  pb = pq  + h*128 + (c-4)*32; }
#pragma unroll
        for(int it=0;it<2;++it){
            int ch=tid+it*256, r=ch>>2, q2=ch&3;
            cp16(sb + (uint32_t)r*80 + q2*16, pa + (long)r*la + q2*8);
        }
#pragma unroll
        for(int it=0;it<4;++it){
            int ch=tid+it*256, r=ch>>2, q2=ch&3;
            cp16(sb + 10240 + (uint32_t)r*80 + q2*16, pb + (long)r*1536 + q2*8);
        }
        asm volatile("cp.async.commit_group;":::"memory");
    };

    // V: 256 rows x 128 d, stride 272B (joins group 0)
#pragma unroll
    for(int it=0;it<16;++it){
        int ch = tid + it*256;
        int r = ch>>4, cq = ch&15;
        cp16(sbase + FA_OV + (uint32_t)r*272 + cq*16, pv + (long)r*1536 + cq*8);
    }
    ldA(0); ldA(1);

    float acc[2][16][4];
#pragma unroll
    for(int i=0;i<2;++i)
#pragma unroll
        for(int j=0;j<16;++j)
#pragma unroll
            for(int q=0;q<4;++q) acc[i][j][q]=0.0f;

    for(int c=0;c<8;++c){
        if(c<7) cpwait<1>(); else cpwait<0>();
        __syncthreads();
        const uint32_t base = sbase + (uint32_t)(c&1)*30720;
#pragma unroll
        for(int s=0;s<2;++s){
            uint32_t ah[2][4];
#pragma unroll
            for(int mi=0;mi<2;++mi) LDM4(ah[mi], base + a_off + mi*1280 + s*32);
#pragma unroll
            for(int nq=0;nq<8;++nq){
                uint32_t bh[4];
                LDM4(bh, base + 10240 + (uint32_t)wn*10240 + nq*1280 + b_off + s*32);
#pragma unroll
                for(int hf=0;hf<2;++hf){
                    int ni = nq*2+hf;
#pragma unroll
                    for(int mi=0;mi<2;++mi) mma16816(acc[mi][ni], ah[mi], bh+hf*2);
                }
            }
        }
        __syncthreads();
        if(c+2<8) ldA(c+2);
    }

    float* red = (float*)(sm + FA_OR);
    float mxv[2][2], inv[2][2];
#pragma unroll
    for(int mi=0;mi<2;++mi)
#pragma unroll
    for(int hf=0;hf<2;++hf){
        float m = -1e30f;
#pragma unroll
        for(int ni=0;ni<16;++ni){ m=fmaxf(m,acc[mi][ni][hf*2]); m=fmaxf(m,acc[mi][ni][hf*2+1]); }
        m = fmaxf(m, __shfl_xor_sync(~0u,m,1));
        m = fmaxf(m, __shfl_xor_sync(~0u,m,2));
        if(qk==0) red[(wm*32+mi*16+hf*8+qr)*2+wn] = m;
    }
    __syncthreads();
#pragma unroll
    for(int mi=0;mi<2;++mi)
#pragma unroll
    for(int hf=0;hf<2;++hf){
        int r = wm*32+mi*16+hf*8+qr;
        mxv[mi][hf] = fmaxf(red[r*2], red[r*2+1]);
    }
    __syncthreads();
#pragma unroll
    for(int mi=0;mi<2;++mi)
#pragma unroll
    for(int hf=0;hf<2;++hf){
        float s = 0.0f;
#pragma unroll
        for(int ni=0;ni<16;++ni){
            float e0=__expf(acc[mi][ni][hf*2]  -mxv[mi][hf]);
            float e1=__expf(acc[mi][ni][hf*2+1]-mxv[mi][hf]);
            acc[mi][ni][hf*2]=e0; acc[mi][ni][hf*2+1]=e1; s+=e0+e1;
        }
        s += __shfl_xor_sync(~0u,s,1);
        s += __shfl_xor_sync(~0u,s,2);
        if(qk==0) red[(wm*32+mi*16+hf*8+qr)*2+wn] = s;
    }
    __syncthreads();
#pragma unroll
    for(int mi=0;mi<2;++mi)
#pragma unroll
    for(int hf=0;hf<2;++hf){
        int r = wm*32+mi*16+hf*8+qr;
        inv[mi][hf] = 1.0f/(red[r*2]+red[r*2+1]);
    }
#pragma unroll
    for(int mi=0;mi<2;++mi)
#pragma unroll
    for(int hf=0;hf<2;++hf){
        int r = wm*32+mi*16+hf*8+qr;
#pragma unroll
        for(int ni=0;ni<16;++ni){
            int col = wn*128+ni*8+qk*2;
            uint32_t p2 = pk(__float2half(acc[mi][ni][hf*2]  *inv[mi][hf]),
                             __float2half(acc[mi][ni][hf*2+1]*inv[mi][hf]));
            *(uint32_t*)(sm + FA_OP + (uint32_t)r*528 + col*2) = p2;
        }
    }
    __syncthreads();

    // ---- phase B: out[n][d] = P[n][m] · V[m][d], V via trans ldmatrix ----
    float ao_acc[2][8][4];
#pragma unroll
    for(int i=0;i<2;++i)
#pragma unroll
        for(int j=0;j<8;++j)
#pragma unroll
            for(int q=0;q<4;++q) ao_acc[i][j][q]=0.0f;

    const uint32_t pa2 = (uint32_t)(wm*32+(lane&15))*528 + (uint32_t)(lane>>4)*16;
    const uint32_t vb2 = (uint32_t)(lane&15)*272 + (uint32_t)(lane>>4)*16 + (uint32_t)wn*128;
#pragma unroll 2
    for(int ks=0;ks<16;++ks){
        uint32_t ap[2][4];
#pragma unroll
        for(int mi=0;mi<2;++mi) LDM4(ap[mi], sbase + FA_OP + pa2 + mi*(16*528) + ks*32);
#pragma unroll
        for(int dq=0;dq<4;++dq){
            uint32_t bv[4];
            LDM4T(bv, sbase + FA_OV + vb2 + ks*(16*272) + dq*32);
#pragma unroll
            for(int hf=0;hf<2;++hf){
                int ni = dq*2+hf;
#pragma unroll
                for(int mi=0;mi<2;++mi) mma16816(ao_acc[mi][ni], ap[mi], bv+hf*2);
            }
        }
    }

    hlf* po = AO + (long)b*131072 + h*128;
#pragma unroll
    for(int mi=0;mi<2;++mi)
#pragma unroll
    for(int hf=0;hf<2;++hf){
        int row = m0 + wm*32+mi*16+hf*8+qr;
#pragma unroll
        for(int ni=0;ni<8;++ni){
            int d = wn*64+ni*8+qk*2;
            float v0=fmaxf(ao_acc[mi][ni][hf*2],0.f), v1=fmaxf(ao_acc[mi][ni][hf*2+1],0.f);
            *(uint32_t*)(po + (long)row*512 + d) = pk(__float2half(v0), __float2half(v1));
        }
    }
}

// ---------------- fused prep kernel (all weight conversions + pos + vectors) ----------------
__global__ void k_prep(const float* c1w, const float* b1g, const float* b1b, const float* b1m, const float* b1v,
                       const float* qw, const float* qbv, const float* kw, const float* kbv,
                       const float* vw, const float* vbv,
                       const float* b2g, const float* b2b, const float* b2m, const float* b2v,
                       const float* c3w, const float* b3g, const float* b3b, const float* b3m, const float* b3v,
                       const float* scw, const float* scb,
                       const float* sg, const float* sb, const float* smn, const float* sv,
                       const float* rh, const float* rw,
                       hlf* w1, hlf* wqkv, hlf* w3, hlf* wsc, hlf* pos){
    int blk = blockIdx.x, t = threadIdx.x;
    if(blk < 2048){                       // w1: conv1 * BN1 scale
        int i = blk*256+t;
        int o = i>>10;
        w1[i] = __float2half(c1w[i] * (b1g[o]*rsqrtf(b1v[o]+EPSBN)));
    } else if(blk < 3072){                // wq
        int i = (blk-2048)*256+t;
        wqkv[i] = __float2half(qw[i]);
    } else if(blk < 4096){                // wk
        int i = (blk-3072)*256+t;
        wqkv[262144+i] = __float2half(kw[i]);
    } else if(blk < 5120){                // wv * BN2 scale
        int i = (blk-4096)*256+t;
        int o = i>>9;
        wqkv[524288+i] = __float2half(vw[i] * (b2g[o]*rsqrtf(b2v[o]+EPSBN)));
    } else if(blk < 9216){                // w3 * BN3 scale
        int i = (blk-5120)*256+t;
        int o = i>>9;
        w3[i] = __float2half(c3w[i] * (b3g[o]*rsqrtf(b3v[o]+EPSBN)));
    } else if(blk < 17408){               // wsc * scBN scale
        int i = (blk-9216)*256+t;
        int o = i>>10;
        wsc[i] = __float2half(scw[i] * (sg[o]*rsqrtf(sv[o]+EPSBN)));
    } else if(blk < 17920){               // posT
        int i = (blk-17408)*256+t;
        int hd = ((i>>15)<<7) + (i&127), n = (i>>7)&255;
        pos[i] = __float2half(rh[hd*16+(n&15)] + rw[hd*16+(n>>4)]);
    } else {                              // vectors
        int i = (blk-17920)*256+t;
        if(i<P_){
            float s1=b1g[i]*rsqrtf(b1v[i]+EPSBN); d_t1[i]=b1b[i]-b1m[i]*s1;
            float s2=b2g[i]*rsqrtf(b2v[i]+EPSBN);
            d_qkvb[i]=qbv[i];
            d_qkvb[i+512]=kbv[i];
            d_qkvb[i+1024]=fmaf(vbv[i],s2,b2b[i]-b2m[i]*s2);   // BN2 folded into V
        }
        if(i<COUT){
            float s3=b3g[i]*rsqrtf(b3v[i]+EPSBN);
            float ss=sg[i]*rsqrtf(sv[i]+EPSBN);
            d_tfin[i]=(b3b[i]-b3m[i]*s3) + fmaf(scb[i]-smn[i],ss,sb[i]);
        }
    }
}
__global__ void k_xt(const float* __restrict__ x, hlf* __restrict__ o){
    __shared__ float t[32][33];
    int c0=blockIdx.x*32, nn0=blockIdx.y*32, b=blockIdx.z, tx=threadIdx.x, ty=threadIdx.y;
#pragma unroll
    for(int i=0;i<4;++i) t[ty+i*8][tx] = x[((long)b*1024 + c0+ty+i*8)*256 + nn0+tx];
    __syncthreads();
    hlf* ob = o + (long)b*262144;
#pragma unroll
    for(int i=0;i<4;++i)
        ob[(long)(nn0+ty+i*8)*1024 + c0+tx] = __float2half(t[tx][ty+i*8]);
}

// ---------------- launch ----------------
extern "C" void kernel_launch(void* const* d_in, const int* in_sizes, int n_in,
                              void* d_out, int out_size) {
    const float *x=(const float*)d_in[0], *c1w=(const float*)d_in[1];
    const float *b1g=(const float*)d_in[2],*b1b=(const float*)d_in[3],*b1m=(const float*)d_in[4],*b1v=(const float*)d_in[5];
    const float *qw=(const float*)d_in[6],*qbv=(const float*)d_in[7],*kw=(const float*)d_in[8],*kbv=(const float*)d_in[9];
    const float *vw=(const float*)d_in[10],*vbv=(const float*)d_in[11],*rh=(const float*)d_in[12],*rwv=(const float*)d_in[13];
    const float *b2g=(const float*)d_in[14],*b2b=(const float*)d_in[15],*b2m=(const float*)d_in[16],*b2v=(const float*)d_in[17];
    const float *c3w=(const float*)d_in[18];
    const float *b3g=(const float*)d_in[19],*b3b=(const float*)d_in[20],*b3m=(const float*)d_in[21],*b3v=(const float*)d_in[22];
    const float *scw=(const float*)d_in[23],*scb=(const float*)d_in[24];
    const float *sg=(const float*)d_in[25],*sb=(const float*)d_in[26],*smn=(const float*)d_in[27],*sv=(const float*)d_in[28];

    hlf *xt,*w1,*wqkv,*w3,*wsc,*o1,*qkv,*ao,*pos;
    float *t1,*tf,*qkvb;
    cudaGetSymbolAddress((void**)&xt, g_xt);    cudaGetSymbolAddress((void**)&w1, g_w1);
    cudaGetSymbolAddress((void**)&wqkv,g_wqkv); cudaGetSymbolAddress((void**)&w3, g_w3);
    cudaGetSymbolAddress((void**)&wsc,g_wsc);   cudaGetSymbolAddress((void**)&o1, g_o1);
    cudaGetSymbolAddress((void**)&qkv,g_qkv);   cudaGetSymbolAddress((void**)&ao, g_ao);
    cudaGetSymbolAddress((void**)&pos,g_pos);
    cudaGetSymbolAddress((void**)&t1, d_t1);    cudaGetSymbolAddress((void**)&tf, d_tfin);
    cudaGetSymbolAddress((void**)&qkvb, d_qkvb);

    cudaFuncSetAttribute(tc<false,true ,false,true >, cudaFuncAttributeMaxDynamicSharedMemorySize, SMEMSZ);
    cudaFuncSetAttribute(tc<false,false,false,true >, cudaFuncAttributeMaxDynamicSharedMemorySize, SMEMSZ);
    cudaFuncSetAttribute(tc<true ,true ,true ,false>, cudaFuncAttributeMaxDynamicSharedMemorySize, SMEMSZ);
    cudaFuncSetAttribute(fattn, cudaFuncAttributeMaxDynamicSharedMemorySize, FA_SMEM);

    // prep (2 launches)
    k_prep<<<17928,256>>>(c1w,b1g,b1b,b1m,b1v, qw,qbv,kw,kbv, vw,vbv,
                          b2g,b2b,b2m,b2v, c3w,b3g,b3b,b3m,b3v, scw,scb,
                          sg,sb,smn,sv, rh,rwv, w1,wqkv,w3,wsc,pos);
    k_xt<<<dim3(32,8,64),dim3(32,8)>>>(x, xt);

    // 1) out1[b][n][p] = xT·w1 + t1[col], ReLU
    tc<false,true,false,true><<<dim3(4,2,64),256,SMEMSZ>>>(
        xt,262144,0,1,1024,1024,  w1,0,0,1,1024,
        nullptr,0,0,1,0,0, nullptr,0,0,1,0,
        o1,131072,0,1,512, t1);
    // 2) qkv[b][n][0..1535] = o1·[wq;wk;wv'] + qkvb[col]
    tc<false,false,false,true><<<dim3(12,2,64),256,SMEMSZ>>>(
        o1,131072,0,1,512,512,  wqkv,0,0,1,512,
        nullptr,0,0,1,0,0, nullptr,0,0,1,0,
        qkv,393216,0,1,1536, qkvb);
    // 3-5) fused attention
    fattn<<<dim3(2,256),256,FA_SMEM>>>(qkv, pos, ao);
    // 6) out[b][cout][n] = w3·attout + wsc·xT + tfin[row], ReLU (two-phase)
    tc<true,true,true,false><<<dim3(2,16,64),256,SMEMSZ>>>(
        w3,0,0,1,512,512,  ao,131072,0,1,512,
        wsc,0,0,1,1024,1024,  xt,262144,0,1,1024,
        d_out,524288,0,1,256, tf);
}